// round 10
// baseline (speedup 1.0000x reference)
#include <cuda_runtime.h>
#include <cuda_bf16.h>
#include <math.h>
#include <stdint.h>

#define BATCH 4096
#define NR 512
#define RI 4096
#define OUT_REC_OFF 262144
#define OUT_MASK_OFF 524288

// conv-kernel SMEM layout (bytes)
#define XROW 264
#define XT_HI 0
#define XT_LO 84480
#define BBUF  168960
#define BPLANE 9216
#define BBUFSZ 18432
#define CONV_SMEM 205824

// 32-row GEMM staging layout (bytes): A 32x32 bf16 pitch 80, B 32x64 bf16 pitch 144
#define RSA_H 0
#define RSA_L 2560
#define RSB_H 5120
#define RSB_L 9728
#define RSTAGE 14336

// 64-row GEMM staging (decoder dec1/dec2, proven R9 layout)
#define GAH 0
#define GAL 5120
#define GBH 10240
#define GBL 14848
#define GSMB 19456

__device__ __nv_bfloat16 g_wB_hi[2304 * 64];
__device__ __nv_bfloat16 g_wB_lo[2304 * 64];
__device__ float g_Wp[RI * 64];              // W permuted [ri][od], fp32
__device__ float g_u[(size_t)BATCH * RI];
__device__ float g_bij[NR * 2];
__device__ float g_v[BATCH * 64];
__device__ float g_h0[BATCH * 64];
__device__ float g_h1[BATCH * 512];
__device__ float g_h2[(size_t)BATCH * 1024];

// ---------------- helpers ----------------
__device__ __forceinline__ float warp_sum(float v) {
    #pragma unroll
    for (int s = 16; s > 0; s >>= 1) v += __shfl_xor_sync(0xFFFFFFFFu, v, s);
    return v;
}
__device__ __forceinline__ float sq8(float v) {
    float t = v * v;
    t += __shfl_xor_sync(0xFFFFFFFFu, t, 4);
    t += __shfl_xor_sync(0xFFFFFFFFu, t, 8);
    t += __shfl_xor_sync(0xFFFFFFFFu, t, 16);
    return t;
}
__device__ __forceinline__ uint32_t smem_u32(const void* p) {
    return (uint32_t)__cvta_generic_to_shared(p);
}
__device__ __forceinline__ void ldsm_x4(uint32_t& r0, uint32_t& r1, uint32_t& r2, uint32_t& r3,
                                        uint32_t addr) {
    asm volatile("ldmatrix.sync.aligned.m8n8.x4.shared.b16 {%0,%1,%2,%3}, [%4];"
                 : "=r"(r0), "=r"(r1), "=r"(r2), "=r"(r3) : "r"(addr));
}
__device__ __forceinline__ void ldsm_x4_t(uint32_t& r0, uint32_t& r1, uint32_t& r2, uint32_t& r3,
                                          uint32_t addr) {
    asm volatile("ldmatrix.sync.aligned.m8n8.x4.trans.shared.b16 {%0,%1,%2,%3}, [%4];"
                 : "=r"(r0), "=r"(r1), "=r"(r2), "=r"(r3) : "r"(addr));
}
__device__ __forceinline__ void mma_bf16(float d[4], const uint32_t a[4],
                                         uint32_t b0, uint32_t b1) {
    asm volatile(
        "mma.sync.aligned.m16n8k16.row.col.f32.bf16.bf16.f32 "
        "{%0,%1,%2,%3}, {%4,%5,%6,%7}, {%8,%9}, {%0,%1,%2,%3};"
        : "+f"(d[0]), "+f"(d[1]), "+f"(d[2]), "+f"(d[3])
        : "r"(a[0]), "r"(a[1]), "r"(a[2]), "r"(a[3]), "r"(b0), "r"(b1));
}
__device__ __forceinline__ void cp_async16(uint32_t dst, const void* src) {
    asm volatile("cp.async.cg.shared.global [%0], [%1], 16;" :: "r"(dst), "l"(src) : "memory");
}
__device__ __forceinline__ uint32_t pk_bf(float a0, float a1) {
    __nv_bfloat16 h0 = __float2bfloat16(a0), h1 = __float2bfloat16(a1);
    return (uint32_t)__bfloat16_as_ushort(h0) | ((uint32_t)__bfloat16_as_ushort(h1) << 16);
}
__device__ __forceinline__ void pack8(const float* fa, uint4& h, uint4& l) {
    uint32_t hp[4], lp[4];
    #pragma unroll
    for (int q = 0; q < 4; q++) {
        float a0 = fa[2 * q], a1 = fa[2 * q + 1];
        __nv_bfloat16 h0 = __float2bfloat16(a0), h1 = __float2bfloat16(a1);
        float r0 = a0 - __bfloat162float(h0), r1 = a1 - __bfloat162float(h1);
        hp[q] = pk_bf(a0, a1);
        lp[q] = pk_bf(r0, r1);
        // note: pk_bf rounds again; identical to direct packing of h0,h1 / l0,l1
    }
    h = make_uint4(hp[0], hp[1], hp[2], hp[3]);
    l = make_uint4(lp[0], lp[1], lp[2], lp[3]);
}

// ---------------- basic kernels ----------------
__global__ void zero_kernel(float* p, int n) {
    int i = blockIdx.x * blockDim.x + threadIdx.x;
    if (i < n) p[i] = 0.0f;
}

__global__ void wb_split_kernel(const float* __restrict__ pw) {
    int idx = blockIdx.x * blockDim.x + threadIdx.x;
    if (idx >= 147456) return;
    int k = idx >> 6, oc = idx & 63;
    int j = k >> 8, ic = k & 255;
    float v = pw[oc * 2304 + ic * 9 + j];
    __nv_bfloat16 hi = __float2bfloat16(v);
    __nv_bfloat16 lo = __float2bfloat16(v - __bfloat162float(hi));
    g_wB_hi[idx] = hi;
    g_wB_lo[idx] = lo;
}

__global__ void w_perm_kernel(const float* __restrict__ W) {
    int idx = blockIdx.x * blockDim.x + threadIdx.x;   // 262144
    if (idx >= RI * 64) return;
    int od = idx & 63, ri = idx >> 6;
    int r = ri >> 3, i = ri & 7, o = od >> 5, dd = od & 31;
    g_Wp[idx] = W[((r * 2 + o) * 32 + dd) * 8 + i];
}

// ---------------- fused conv1 + mma.sync primary conv + squash (proven R6) ----
__global__ void __launch_bounds__(512, 1) conv_tc_kernel(
    const float* __restrict__ data, const float* __restrict__ w1,
    const float* __restrict__ b1, const float* __restrict__ pb)
{
    extern __shared__ char smem[];
    __shared__ float s_img[64];
    __nv_bfloat16* xhi = (__nv_bfloat16*)(smem + XT_HI);
    __nv_bfloat16* xlo = (__nv_bfloat16*)(smem + XT_LO);

    int b = blockIdx.x;
    int tid = threadIdx.x;
    int w = tid >> 5, lane = tid & 31;
    uint32_t sm_base = smem_u32(smem);

    #pragma unroll
    for (int o = 0; o < 2; o++) {
        int idx = o * 512 + tid;
        int plane = idx >> 9, rem = idx & 511, r = rem >> 3, seg = rem & 7;
        const __nv_bfloat16* src = (plane ? g_wB_lo : g_wB_hi) + (size_t)r * 64 + seg * 8;
        cp_async16(sm_base + BBUF + plane * BPLANE + r * 144 + seg * 16, src);
    }
    asm volatile("cp.async.commit_group;");

    {
        uint4 z = make_uint4(0, 0, 0, 0);
        uint4* p = (uint4*)smem;
        for (int i = tid; i < (XT_LO * 2) / 16; i += 512) p[i] = z;
    }
    if (tid < 64) s_img[tid] = data[b * 64 + tid];
    __syncthreads();

    {
        int ic = tid & 255, half = tid >> 8;
        float wr[9];
        #pragma unroll
        for (int k = 0; k < 9; k++) wr[k] = w1[ic * 9 + k];
        float bias = b1[ic];
        #pragma unroll
        for (int yy = 0; yy < 4; yy++) {
            int y = half * 4 + yy;
            #pragma unroll
            for (int x = 0; x < 8; x++) {
                float acc = bias;
                #pragma unroll
                for (int ky = 0; ky < 3; ky++) {
                    int iy = y + ky - 1;
                    if (iy < 0 || iy > 7) continue;
                    #pragma unroll
                    for (int kx = 0; kx < 3; kx++) {
                        int ix = x + kx - 1;
                        if (ix < 0 || ix > 7) continue;
                        acc += wr[ky * 3 + kx] * s_img[iy * 8 + ix];
                    }
                }
                acc = fmaxf(acc, 0.0f);
                __nv_bfloat16 hi = __float2bfloat16(acc);
                __nv_bfloat16 lo = __float2bfloat16(acc - __bfloat162float(hi));
                int p = (y + 1) * 16 + (x + 1);
                xhi[p * XROW + ic] = hi;
                xlo[p * XROW + ic] = lo;
            }
        }
    }

    int mf = w & 3, ng = w >> 2;
    int mloc = lane & 15, chalf = lane >> 4;
    int m = mf * 16 + mloc;
    int pbase = (m >> 3) * 16 + (m & 7);

    float d0[4] = {0.f, 0.f, 0.f, 0.f};
    float d1[4] = {0.f, 0.f, 0.f, 0.f};
    uint32_t xhi_u = sm_base + XT_HI;
    const int lo_delta = XT_LO - XT_HI;

    for (int cid = 0; cid < 36; cid++) {
        int buf = cid & 1;
        int js = cid >> 2, kc = cid & 3;
        int ky = js / 3, kx = js - ky * 3;

        asm volatile("cp.async.wait_group 0;");
        __syncthreads();

        if (cid + 1 < 36) {
            int njs = (cid + 1) >> 2, nkc = (cid + 1) & 3;
            int krow0 = njs * 256 + nkc * 64;
            #pragma unroll
            for (int o = 0; o < 2; o++) {
                int idx = o * 512 + tid;
                int plane = idx >> 9, rem = idx & 511, r = rem >> 3, seg = rem & 7;
                const __nv_bfloat16* src =
                    (plane ? g_wB_lo : g_wB_hi) + (size_t)(krow0 + r) * 64 + seg * 8;
                cp_async16(sm_base + BBUF + (buf ^ 1) * BBUFSZ + plane * BPLANE
                           + r * 144 + seg * 16, src);
            }
            asm volatile("cp.async.commit_group;");
        }

        uint32_t bbase = sm_base + BBUF + buf * BBUFSZ;
        int ashift = (pbase + ky * 16 + kx) * XROW;

        #pragma unroll
        for (int k16 = 0; k16 < 4; k16++) {
            int ic0 = kc * 64 + k16 * 16;
            uint32_t ah[4], al[4];
            uint32_t aaddr = xhi_u + (uint32_t)(ashift + ic0 + chalf * 8) * 2u;
            ldsm_x4(ah[0], ah[1], ah[2], ah[3], aaddr);
            ldsm_x4(al[0], al[1], al[2], al[3], aaddr + lo_delta);
            uint32_t bh[4], bl[4];
            uint32_t baddr = bbase + (uint32_t)(k16 * 16 + mloc) * 144u
                           + (uint32_t)(ng * 16 + chalf * 8) * 2u;
            ldsm_x4_t(bh[0], bh[1], bh[2], bh[3], baddr);
            ldsm_x4_t(bl[0], bl[1], bl[2], bl[3], baddr + BPLANE);
            mma_bf16(d0, ah, bh[0], bh[1]);
            mma_bf16(d1, ah, bh[2], bh[3]);
            mma_bf16(d0, ah, bl[0], bl[1]);
            mma_bf16(d1, ah, bl[2], bl[3]);
            mma_bf16(d0, al, bh[0], bh[1]);
            mma_bf16(d1, al, bh[2], bh[3]);
        }
    }

    {
        int tig = lane & 3, gid = lane >> 2;
        float* dst = g_u + (size_t)b * RI;
        #pragma unroll
        for (int f = 0; f < 2; f++) {
            const float* d = f ? d1 : d0;
            int oc = ng * 16 + f * 8 + 2 * tig;
            float b0 = pb[oc], b1v = pb[oc + 1];
            float v00 = d[0] + b0, v01 = d[1] + b1v;
            float v10 = d[2] + b0, v11 = d[3] + b1v;
            float q00 = sq8(v00), q01 = sq8(v01), q10 = sq8(v10), q11 = sq8(v11);
            float s00 = q00 / ((1.0f + q00) * sqrtf(q00 + 1e-9f));
            float s01 = q01 / ((1.0f + q01) * sqrtf(q01 + 1e-9f));
            float s10 = q10 / ((1.0f + q10) * sqrtf(q10 + 1e-9f));
            float s11 = q11 / ((1.0f + q11) * sqrtf(q11 + 1e-9f));
            int y0 = 2 * mf;
            dst[(oc * 8 + y0) * 8 + gid]           = v00 * s00;
            dst[((oc + 1) * 8 + y0) * 8 + gid]     = v01 * s01;
            dst[(oc * 8 + y0 + 1) * 8 + gid]       = v10 * s10;
            dst[((oc + 1) * 8 + y0 + 1) * 8 + gid] = v11 * s11;
        }
    }
}

// ---------------- 32-row-block MMA helper (8 warps; mf=w&1, ng=w>>1) ----------
__device__ __forceinline__ void mma32(char* sm, int w, int lane,
                                      float d0[4], float d1[4]) {
    int mf = w & 1, ng = w >> 1;
    int mloc = lane & 15, chalf = lane >> 4;
    uint32_t smb = smem_u32(sm);
    #pragma unroll
    for (int ks = 0; ks < 2; ks++) {
        uint32_t ah[4], al[4];
        uint32_t aaddr = smb + RSA_H
            + (uint32_t)((mf * 16 + mloc) * 80 + (ks * 16 + chalf * 8) * 2);
        ldsm_x4(ah[0], ah[1], ah[2], ah[3], aaddr);
        ldsm_x4(al[0], al[1], al[2], al[3], aaddr + (RSA_L - RSA_H));
        uint32_t bh[4], bl[4];
        uint32_t baddr = smb + RSB_H
            + (uint32_t)((ks * 16 + mloc) * 144 + (ng * 16 + chalf * 8) * 2);
        ldsm_x4_t(bh[0], bh[1], bh[2], bh[3], baddr);
        ldsm_x4_t(bl[0], bl[1], bl[2], bl[3], baddr + (RSB_L - RSB_H));
        mma_bf16(d0, ah, bh[0], bh[1]);
        mma_bf16(d1, ah, bh[2], bh[3]);
        mma_bf16(d0, ah, bl[0], bl[1]);
        mma_bf16(d1, ah, bl[2], bl[3]);
        mma_bf16(d0, al, bh[0], bh[1]);
        mma_bf16(d1, al, bh[2], bh[3]);
    }
}
// store warp fragments into fp32 tile [32][pitch 68]
__device__ __forceinline__ void frag_to_tile(float* tile, int w, int lane,
                                             const float d0[4], const float d1[4],
                                             float scale) {
    int mf = w & 1, ng = w >> 1;
    int tig = lane & 3, gid = lane >> 2;
    int r0 = mf * 16 + gid;
    #pragma unroll
    for (int f = 0; f < 2; f++) {
        const float* d = f ? d1 : d0;
        int col = ng * 16 + f * 8 + 2 * tig;
        tile[r0 * 68 + col]           = d[0] * scale;
        tile[r0 * 68 + col + 1]       = d[1] * scale;
        tile[(r0 + 8) * 68 + col]     = d[2] * scale;
        tile[(r0 + 8) * 68 + col + 1] = d[3] * scale;
    }
}

// ---------------- routing s-kernel: softmax + (u @ cW) + squash [+ mask] ------
__global__ void __launch_bounds__(256) routing_s_kernel(float* __restrict__ out, int last) {
    __shared__ char sm[RSTAGE];
    __shared__ float c_s[NR * 2];
    __shared__ float tile[32 * 68];
    __shared__ float red[256];
    int tid = threadIdx.x, w = tid >> 5, lane = tid & 31;
    int m0 = blockIdx.x * 32;

    // inline softmax over routes (axis 0) for o = 0,1
    #pragma unroll
    for (int o = 0; o < 2; o++) {
        float mx = -1e30f;
        for (int r = tid; r < NR; r += 256) mx = fmaxf(mx, g_bij[r * 2 + o]);
        red[tid] = mx; __syncthreads();
        for (int s = 128; s > 0; s >>= 1) {
            if (tid < s) red[tid] = fmaxf(red[tid], red[tid + s]);
            __syncthreads();
        }
        mx = red[0]; __syncthreads();
        float sum = 0.0f;
        for (int r = tid; r < NR; r += 256) sum += expf(g_bij[r * 2 + o] - mx);
        red[tid] = sum; __syncthreads();
        for (int s = 128; s > 0; s >>= 1) {
            if (tid < s) red[tid] += red[tid + s];
            __syncthreads();
        }
        sum = red[0]; __syncthreads();
        for (int r = tid; r < NR; r += 256)
            c_s[r * 2 + o] = expf(g_bij[r * 2 + o] - mx) / sum;
    }
    __syncthreads();

    float d0[4] = {0.f, 0.f, 0.f, 0.f}, d1[4] = {0.f, 0.f, 0.f, 0.f};
    for (int k0 = 0; k0 < RI; k0 += 32) {
        __syncthreads();
        {   // stage A: u[m0+m][k0..+32]
            int m = tid >> 3, kq = (tid & 7) * 4;
            const float* p = g_u + (size_t)(m0 + m) * RI + k0 + kq;
            float4 f = *(const float4*)p;
            uint2 h = make_uint2(pk_bf(f.x, f.y), pk_bf(f.z, f.w));
            __nv_bfloat16 hx = __float2bfloat16(f.x), hy = __float2bfloat16(f.y);
            __nv_bfloat16 hz = __float2bfloat16(f.z), hw = __float2bfloat16(f.w);
            uint2 l = make_uint2(pk_bf(f.x - __bfloat162float(hx), f.y - __bfloat162float(hy)),
                                 pk_bf(f.z - __bfloat162float(hz), f.w - __bfloat162float(hw)));
            *(uint2*)(sm + RSA_H + m * 80 + kq * 2) = h;
            *(uint2*)(sm + RSA_L + m * 80 + kq * 2) = l;
        }
        {   // stage B: Wp[k0+k][nq..+8] * c[(k0+k)>>3][nq>>5]
            int k = tid >> 3, nq = (tid & 7) * 8;
            float c = c_s[((k0 + k) >> 3) * 2 + (nq >> 5)];
            const float* p = g_Wp + (size_t)(k0 + k) * 64 + nq;
            float4 f0 = *(const float4*)p, f1 = *(const float4*)(p + 4);
            float fa[8] = {f0.x * c, f0.y * c, f0.z * c, f0.w * c,
                           f1.x * c, f1.y * c, f1.z * c, f1.w * c};
            uint4 h, l; pack8(fa, h, l);
            *(uint4*)(sm + RSB_H + k * 144 + nq * 2) = h;
            *(uint4*)(sm + RSB_L + k * 144 + nq * 2) = l;
        }
        __syncthreads();
        mma32(sm, w, lane, d0, d1);
    }
    __syncthreads();
    frag_to_tile(tile, w, lane, d0, d1, 1.0f);
    __syncthreads();

    // epilogue: warp per 4 rows; squash over od groups of 32
    #pragma unroll
    for (int rr = 0; rr < 4; rr++) {
        int row = w * 4 + rr;
        int b = m0 + row;
        float s0 = tile[row * 68 + lane];
        float s1 = tile[row * 68 + 32 + lane];
        float q0 = warp_sum(s0 * s0);
        float q1 = warp_sum(s1 * s1);
        float sc0 = q0 / ((1.0f + q0) * sqrtf(q0 + 1e-9f));
        float sc1 = q1 / ((1.0f + q1) * sqrtf(q1 + 1e-9f));
        float v0 = s0 * sc0, v1 = s1 * sc1;
        if (!last) {
            g_v[b * 64 + lane] = v0;
            g_v[b * 64 + 32 + lane] = v1;
        } else {
            float n0 = q0 * sc0 * sc0, n1 = q1 * sc1 * sc1;
            float m0v = (n1 > n0) ? 0.0f : 1.0f;
            float m1v = 1.0f - m0v;
            out[b * 64 + lane] = v0;
            out[b * 64 + 32 + lane] = v1;
            if (lane == 0) {
                out[OUT_MASK_OFF + b * 2 + 0] = m0v;
                out[OUT_MASK_OFF + b * 2 + 1] = m1v;
            }
            g_h0[b * 64 + lane] = v0 * m0v;
            g_h0[b * 64 + 32 + lane] = v1 * m1v;
        }
    }
}

// ---------------- routing G-kernel: (u^T @ v)/B + fused b_ij update -----------
__global__ void __launch_bounds__(256) routing_g_kernel(const float* __restrict__ W) {
    __shared__ char sm[RSTAGE];
    __shared__ float tile[32 * 68];
    int tid = threadIdx.x, w = tid >> 5, lane = tid & 31;
    int m0 = blockIdx.x * 32;   // ri block

    float d0[4] = {0.f, 0.f, 0.f, 0.f}, d1[4] = {0.f, 0.f, 0.f, 0.f};
    for (int k0 = 0; k0 < BATCH; k0 += 32) {
        __syncthreads();
        {   // stage A^T: u[k0+k][m0+mq..+4] scattered to A[m][k]
            int k = tid >> 3, mq = (tid & 7) * 4;
            const float* p = g_u + (size_t)(k0 + k) * RI + m0 + mq;
            float4 f = *(const float4*)p;
            float fa[4] = {f.x, f.y, f.z, f.w};
            #pragma unroll
            for (int i = 0; i < 4; i++) {
                __nv_bfloat16 h = __float2bfloat16(fa[i]);
                __nv_bfloat16 l = __float2bfloat16(fa[i] - __bfloat162float(h));
                *(__nv_bfloat16*)(sm + RSA_H + (mq + i) * 80 + k * 2) = h;
                *(__nv_bfloat16*)(sm + RSA_L + (mq + i) * 80 + k * 2) = l;
            }
        }
        {   // stage B: v[k0+k][nq..+8]
            int k = tid >> 3, nq = (tid & 7) * 8;
            const float* p = g_v + (size_t)(k0 + k) * 64 + nq;
            float4 f0 = *(const float4*)p, f1 = *(const float4*)(p + 4);
            float fa[8] = {f0.x, f0.y, f0.z, f0.w, f1.x, f1.y, f1.z, f1.w};
            uint4 h, l; pack8(fa, h, l);
            *(uint4*)(sm + RSB_H + k * 144 + nq * 2) = h;
            *(uint4*)(sm + RSB_L + k * 144 + nq * 2) = l;
        }
        __syncthreads();
        mma32(sm, w, lane, d0, d1);
    }
    __syncthreads();
    frag_to_tile(tile, w, lane, d0, d1, 1.0f / (float)BATCH);
    __syncthreads();

    // epilogue: warp per (r_loc, o); b[r][o] += sum_{d,i} W[r,o,d,i] * G[ri][od]
    int r_loc = w >> 1, o = w & 1;
    int r = (m0 >> 3) + r_loc;
    float sum = 0.0f;
    #pragma unroll
    for (int j = 0; j < 8; j++) {
        int t = lane + 32 * j;          // t = d*8 + i
        int dd = t >> 3, i = t & 7;
        sum += W[(r * 2 + o) * 256 + t] * tile[(r_loc * 8 + i) * 68 + o * 32 + dd];
    }
    sum = warp_sum(sum);
    if (lane == 0) g_bij[r * 2 + o] += sum;
}

// ---------------- dec3: (h2 @ W3 + b) -> sigmoid -> out ----------------------
__global__ void __launch_bounds__(256) dec3_kernel(
    const float* __restrict__ B, const float* __restrict__ bias, float* __restrict__ out)
{
    __shared__ char sm[RSTAGE];
    int tid = threadIdx.x, w = tid >> 5, lane = tid & 31;
    int m0 = blockIdx.x * 32;

    float d0[4] = {0.f, 0.f, 0.f, 0.f}, d1[4] = {0.f, 0.f, 0.f, 0.f};
    for (int k0 = 0; k0 < 1024; k0 += 32) {
        __syncthreads();
        {
            int m = tid >> 3, kq = (tid & 7) * 4;
            const float* p = g_h2 + (size_t)(m0 + m) * 1024 + k0 + kq;
            float4 f = *(const float4*)p;
            __nv_bfloat16 hx = __float2bfloat16(f.x), hy = __float2bfloat16(f.y);
            __nv_bfloat16 hz = __float2bfloat16(f.z), hw = __float2bfloat16(f.w);
            uint2 h = make_uint2(pk_bf(f.x, f.y), pk_bf(f.z, f.w));
            uint2 l = make_uint2(pk_bf(f.x - __bfloat162float(hx), f.y - __bfloat162float(hy)),
                                 pk_bf(f.z - __bfloat162float(hz), f.w - __bfloat162float(hw)));
            *(uint2*)(sm + RSA_H + m * 80 + kq * 2) = h;
            *(uint2*)(sm + RSA_L + m * 80 + kq * 2) = l;
        }
        {
            int k = tid >> 3, nq = (tid & 7) * 8;
            const float* p = B + (size_t)(k0 + k) * 64 + nq;
            float4 f0 = *(const float4*)p, f1 = *(const float4*)(p + 4);
            float fa[8] = {f0.x, f0.y, f0.z, f0.w, f1.x, f1.y, f1.z, f1.w};
            uint4 h, l; pack8(fa, h, l);
            *(uint4*)(sm + RSB_H + k * 144 + nq * 2) = h;
            *(uint4*)(sm + RSB_L + k * 144 + nq * 2) = l;
        }
        __syncthreads();
        mma32(sm, w, lane, d0, d1);
    }

    int mf = w & 1, ng = w >> 1;
    int tig = lane & 3, gid = lane >> 2;
    int r0 = m0 + mf * 16 + gid;
    #pragma unroll
    for (int f = 0; f < 2; f++) {
        const float* d = f ? d1 : d0;
        int col = ng * 16 + f * 8 + 2 * tig;
        float b0 = bias[col], b1v = bias[col + 1];
        out[OUT_REC_OFF + r0 * 64 + col]            = 1.0f / (1.0f + expf(-(d[0] + b0)));
        out[OUT_REC_OFF + r0 * 64 + col + 1]        = 1.0f / (1.0f + expf(-(d[1] + b1v)));
        out[OUT_REC_OFF + (r0 + 8) * 64 + col]      = 1.0f / (1.0f + expf(-(d[2] + b0)));
        out[OUT_REC_OFF + (r0 + 8) * 64 + col + 1]  = 1.0f / (1.0f + expf(-(d[3] + b1v)));
    }
}

// ---------------- decoder dec1/dec2: proven R9 64-row GEMM -------------------
__device__ __forceinline__ void stage_A_rm(const float* A, size_t lda, int m0, int k0,
                                           char* sm, int tid) {
    int m = tid >> 2, kq = (tid & 3) * 8;
    const float* p = A + (size_t)(m0 + m) * lda + k0 + kq;
    float4 f0 = *(const float4*)p, f1 = *(const float4*)(p + 4);
    float fa[8] = {f0.x, f0.y, f0.z, f0.w, f1.x, f1.y, f1.z, f1.w};
    uint4 h, l; pack8(fa, h, l);
    *(uint4*)(sm + GAH + m * 80 + kq * 2) = h;
    *(uint4*)(sm + GAL + m * 80 + kq * 2) = l;
}
__device__ __forceinline__ void stage_B64(const float* B, size_t ldb, int k0, int n0,
                                          char* sm, int tid) {
    int k = tid >> 3, nq = (tid & 7) * 8;
    const float* p = B + (size_t)(k0 + k) * ldb + n0 + nq;
    float4 f0 = *(const float4*)p, f1 = *(const float4*)(p + 4);
    float fa[8] = {f0.x, f0.y, f0.z, f0.w, f1.x, f1.y, f1.z, f1.w};
    uint4 h, l; pack8(fa, h, l);
    *(uint4*)(sm + GBH + k * 144 + nq * 2) = h;
    *(uint4*)(sm + GBL + k * 144 + nq * 2) = l;
}
__device__ __forceinline__ void mma_tile64(char* sm, int w, int lane, float (&d)[2][2][4]) {
    int mf = w & 3, ng = w >> 2;
    int mloc = lane & 15, chalf = lane >> 4;
    uint32_t smb = smem_u32(sm);
    #pragma unroll
    for (int ks = 0; ks < 2; ks++) {
        uint32_t ah[4], al[4];
        uint32_t aaddr = smb + GAH + (uint32_t)((mf * 16 + mloc) * 80 + (ks * 16 + chalf * 8) * 2);
        ldsm_x4(ah[0], ah[1], ah[2], ah[3], aaddr);
        ldsm_x4(al[0], al[1], al[2], al[3], aaddr + (GAL - GAH));
        #pragma unroll
        for (int h = 0; h < 2; h++) {
            uint32_t bh[4], bl[4];
            uint32_t baddr = smb + GBH
                + (uint32_t)((ks * 16 + mloc) * 144 + (ng * 32 + h * 16 + chalf * 8) * 2);
            ldsm_x4_t(bh[0], bh[1], bh[2], bh[3], baddr);
            ldsm_x4_t(bl[0], bl[1], bl[2], bl[3], baddr + (GBL - GBH));
            mma_bf16(d[h][0], ah, bh[0], bh[1]);
            mma_bf16(d[h][1], ah, bh[2], bh[3]);
            mma_bf16(d[h][0], ah, bl[0], bl[1]);
            mma_bf16(d[h][1], ah, bl[2], bl[3]);
            mma_bf16(d[h][0], al, bh[0], bh[1]);
            mma_bf16(d[h][1], al, bh[2], bh[3]);
        }
    }
}
__global__ void __launch_bounds__(256) tgemm_rm_bias(
    const float* __restrict__ A, const float* __restrict__ B,
    const float* __restrict__ bias, float* __restrict__ C, int K, int N, int act)
{
    __shared__ char sm[GSMB];
    int tid = threadIdx.x, w = tid >> 5, lane = tid & 31;
    int n0 = blockIdx.x * 64, m0 = blockIdx.y * 64;
    float d[2][2][4] = {};
    for (int k0 = 0; k0 < K; k0 += 32) {
        __syncthreads();
        stage_A_rm(A, K, m0, k0, sm, tid);
        stage_B64(B, N, k0, n0, sm, tid);
        __syncthreads();
        mma_tile64(sm, w, lane, d);
    }
    int mf = w & 3, ng = w >> 2;
    int tig = lane & 3, gid = lane >> 2;
    #pragma unroll
    for (int h = 0; h < 2; h++)
        #pragma unroll
        for (int f = 0; f < 2; f++) {
            int col = n0 + ng * 32 + h * 16 + f * 8 + 2 * tig;
            int row = m0 + mf * 16 + gid;
            #pragma unroll
            for (int e = 0; e < 4; e++) {
                int rr = row + (e >> 1) * 8;
                int cc = col + (e & 1);
                float v = d[h][f][e] + bias[cc];
                if (act == 1) v = fmaxf(v, 0.0f);
                C[(size_t)rr * N + cc] = v;
            }
        }
}

// ---------------- launch ----------------
extern "C" void kernel_launch(void* const* d_in, const int* in_sizes, int n_in,
                              void* d_out, int out_size)
{
    const float* data    = (const float*)d_in[0];
    const float* conv1_w = (const float*)d_in[1];
    const float* conv1_b = (const float*)d_in[2];
    const float* prim_w  = (const float*)d_in[3];
    const float* prim_b  = (const float*)d_in[4];
    const float* W_digit = (const float*)d_in[5];
    const float* dec1_w  = (const float*)d_in[6];
    const float* dec1_b  = (const float*)d_in[7];
    const float* dec2_w  = (const float*)d_in[8];
    const float* dec2_b  = (const float*)d_in[9];
    const float* dec3_w  = (const float*)d_in[10];
    const float* dec3_b  = (const float*)d_in[11];
    float* out = (float*)d_out;

    float *p_bij, *p_h0, *p_h1, *p_h2;
    cudaGetSymbolAddress((void**)&p_bij, g_bij);
    cudaGetSymbolAddress((void**)&p_h0,  g_h0);
    cudaGetSymbolAddress((void**)&p_h1,  g_h1);
    cudaGetSymbolAddress((void**)&p_h2,  g_h2);

    static int smem_set = 0;
    if (!smem_set) {
        cudaFuncSetAttribute(conv_tc_kernel,
                             cudaFuncAttributeMaxDynamicSharedMemorySize, CONV_SMEM);
        smem_set = 1;
    }

    wb_split_kernel<<<576, 256>>>(prim_w);                           // 0
    zero_kernel<<<4, 256>>>(p_bij, NR * 2);                          // 1
    conv_tc_kernel<<<BATCH, 512, CONV_SMEM>>>(data, conv1_w, conv1_b, prim_b);  // 2
    w_perm_kernel<<<1024, 256>>>(W_digit);                           // 3

    for (int it = 0; it < 3; it++) {
        routing_s_kernel<<<128, 256>>>(out, it == 2 ? 1 : 0);
        if (it < 2) routing_g_kernel<<<128, 256>>>(W_digit);
    }

    tgemm_rm_bias<<<dim3(8, 64), 256>>>(p_h0, dec1_w, dec1_b, p_h1, 64, 512, 1);
    tgemm_rm_bias<<<dim3(16, 64), 256>>>(p_h1, dec2_w, dec2_b, p_h2, 512, 1024, 1);
    dec3_kernel<<<128, 256>>>(dec3_w, dec3_b, out);
}

// round 12
// speedup vs baseline: 1.2447x; 1.2447x over previous
#include <cuda_runtime.h>
#include <cuda_bf16.h>
#include <math.h>
#include <stdint.h>

#define BATCH 4096
#define NR 512
#define RI 4096
#define OUT_REC_OFF 262144
#define OUT_MASK_OFF 524288

// conv-kernel SMEM layout (bytes)
#define XROW 264
#define XT_HI 0
#define XT_LO 84480
#define BBUF  168960
#define BPLANE 9216
#define BBUFSZ 18432
#define CONV_SMEM 205824

// pipelined GEMM staging: per buffer A 64x32 (pitch 80) hi/lo + B 32x64 (pitch 144) hi/lo
#define GAH 0
#define GAL 5120
#define GBH 10240
#define GBL 14848
#define GBUF 19456

// ---------------- device globals ----------------
__device__ __align__(16) __nv_bfloat16 g_wB_hi[2304 * 64];
__device__ __align__(16) __nv_bfloat16 g_wB_lo[2304 * 64];
__device__ __align__(16) __nv_bfloat16 g_u_hi[(size_t)BATCH * RI];
__device__ __align__(16) __nv_bfloat16 g_u_lo[(size_t)BATCH * RI];
__device__ __align__(16) __nv_bfloat16 g_wct_hi[RI * 64];
__device__ __align__(16) __nv_bfloat16 g_wct_lo[RI * 64];
__device__ __align__(16) __nv_bfloat16 g_h0_hi[BATCH * 64];
__device__ __align__(16) __nv_bfloat16 g_h0_lo[BATCH * 64];
__device__ __align__(16) __nv_bfloat16 g_h1_hi[(size_t)BATCH * 512];
__device__ __align__(16) __nv_bfloat16 g_h1_lo[(size_t)BATCH * 512];
__device__ __align__(16) __nv_bfloat16 g_h2_hi[(size_t)BATCH * 1024];
__device__ __align__(16) __nv_bfloat16 g_h2_lo[(size_t)BATCH * 1024];
__device__ __align__(16) __nv_bfloat16 g_w1_hi[64 * 512];
__device__ __align__(16) __nv_bfloat16 g_w1_lo[64 * 512];
__device__ __align__(16) __nv_bfloat16 g_w2_hi[512 * 1024];
__device__ __align__(16) __nv_bfloat16 g_w2_lo[512 * 1024];
__device__ __align__(16) __nv_bfloat16 g_w3_hi[1024 * 64];
__device__ __align__(16) __nv_bfloat16 g_w3_lo[1024 * 64];
__device__ float g_bij[NR * 2];
__device__ float g_c[NR * 2];
__device__ float g_s[BATCH * 64];
__device__ float g_v[BATCH * 64];
__device__ float g_GT[64 * RI];
__device__ float g_r[BATCH * 64];

// ---------------- helpers ----------------
__device__ __forceinline__ float warp_sum(float v) {
    #pragma unroll
    for (int s = 16; s > 0; s >>= 1) v += __shfl_xor_sync(0xFFFFFFFFu, v, s);
    return v;
}
__device__ __forceinline__ float sq8(float v) {
    float t = v * v;
    t += __shfl_xor_sync(0xFFFFFFFFu, t, 4);
    t += __shfl_xor_sync(0xFFFFFFFFu, t, 8);
    t += __shfl_xor_sync(0xFFFFFFFFu, t, 16);
    return t;
}
__device__ __forceinline__ uint32_t smem_u32(const void* p) {
    return (uint32_t)__cvta_generic_to_shared(p);
}
__device__ __forceinline__ void ldsm_x4(uint32_t& r0, uint32_t& r1, uint32_t& r2, uint32_t& r3,
                                        uint32_t addr) {
    asm volatile("ldmatrix.sync.aligned.m8n8.x4.shared.b16 {%0,%1,%2,%3}, [%4];"
                 : "=r"(r0), "=r"(r1), "=r"(r2), "=r"(r3) : "r"(addr));
}
__device__ __forceinline__ void ldsm_x4_t(uint32_t& r0, uint32_t& r1, uint32_t& r2, uint32_t& r3,
                                          uint32_t addr) {
    asm volatile("ldmatrix.sync.aligned.m8n8.x4.trans.shared.b16 {%0,%1,%2,%3}, [%4];"
                 : "=r"(r0), "=r"(r1), "=r"(r2), "=r"(r3) : "r"(addr));
}
__device__ __forceinline__ void mma_bf16(float d[4], const uint32_t a[4],
                                         uint32_t b0, uint32_t b1) {
    asm volatile(
        "mma.sync.aligned.m16n8k16.row.col.f32.bf16.bf16.f32 "
        "{%0,%1,%2,%3}, {%4,%5,%6,%7}, {%8,%9}, {%0,%1,%2,%3};"
        : "+f"(d[0]), "+f"(d[1]), "+f"(d[2]), "+f"(d[3])
        : "r"(a[0]), "r"(a[1]), "r"(a[2]), "r"(a[3]), "r"(b0), "r"(b1));
}
__device__ __forceinline__ void cp_async16(uint32_t dst, const void* src) {
    asm volatile("cp.async.cg.shared.global [%0], [%1], 16;" :: "r"(dst), "l"(src) : "memory");
}
__device__ __forceinline__ void split_bf(float v, __nv_bfloat16& h, __nv_bfloat16& l) {
    h = __float2bfloat16(v);
    l = __float2bfloat16(v - __bfloat162float(h));
}

// ---------------- basic kernels ----------------
__global__ void zero_kernel(float* p, int n) {
    int i = blockIdx.x * blockDim.x + threadIdx.x;
    if (i < n) p[i] = 0.0f;
}
// generic fp32 -> bf16 hi/lo splitter
__global__ void split_kernel(const float* __restrict__ src,
                             __nv_bfloat16* __restrict__ hi,
                             __nv_bfloat16* __restrict__ lo, int n) {
    int i = blockIdx.x * blockDim.x + threadIdx.x;
    if (i >= n) return;
    __nv_bfloat16 h, l;
    split_bf(src[i], h, l);
    hi[i] = h; lo[i] = l;
}
// conv weights: permute [oc][ic][9] -> [k=j*256+ic][oc] with split
__global__ void wb_split_kernel(const float* __restrict__ pw) {
    int idx = blockIdx.x * blockDim.x + threadIdx.x;
    if (idx >= 147456) return;
    int k = idx >> 6, oc = idx & 63;
    int j = k >> 8, ic = k & 255;
    __nv_bfloat16 h, l;
    split_bf(pw[oc * 2304 + ic * 9 + j], h, l);
    g_wB_hi[idx] = h;
    g_wB_lo[idx] = l;
}

// ---------------- fused conv1 + bf16 3-term mma primary conv + squash --------
__global__ void __launch_bounds__(512, 1) conv_tc_kernel(
    const float* __restrict__ data, const float* __restrict__ w1,
    const float* __restrict__ b1, const float* __restrict__ pb)
{
    extern __shared__ char smem[];
    __shared__ float s_img[64];
    __nv_bfloat16* xhi = (__nv_bfloat16*)(smem + XT_HI);
    __nv_bfloat16* xlo = (__nv_bfloat16*)(smem + XT_LO);

    int b = blockIdx.x;
    int tid = threadIdx.x;
    int w = tid >> 5, lane = tid & 31;
    uint32_t sm_base = smem_u32(smem);

    #pragma unroll
    for (int o = 0; o < 2; o++) {
        int idx = o * 512 + tid;
        int plane = idx >> 9, rem = idx & 511, r = rem >> 3, seg = rem & 7;
        const __nv_bfloat16* src = (plane ? g_wB_lo : g_wB_hi) + (size_t)r * 64 + seg * 8;
        cp_async16(sm_base + BBUF + plane * BPLANE + r * 144 + seg * 16, src);
    }
    asm volatile("cp.async.commit_group;");

    {
        uint4 z = make_uint4(0, 0, 0, 0);
        uint4* p = (uint4*)smem;
        for (int i = tid; i < (XT_LO * 2) / 16; i += 512) p[i] = z;
    }
    if (tid < 64) s_img[tid] = data[b * 64 + tid];
    __syncthreads();

    {
        int ic = tid & 255, half = tid >> 8;
        float wr[9];
        #pragma unroll
        for (int k = 0; k < 9; k++) wr[k] = w1[ic * 9 + k];
        float bias = b1[ic];
        #pragma unroll
        for (int yy = 0; yy < 4; yy++) {
            int y = half * 4 + yy;
            #pragma unroll
            for (int x = 0; x < 8; x++) {
                float acc = bias;
                #pragma unroll
                for (int ky = 0; ky < 3; ky++) {
                    int iy = y + ky - 1;
                    if (iy < 0 || iy > 7) continue;
                    #pragma unroll
                    for (int kx = 0; kx < 3; kx++) {
                        int ix = x + kx - 1;
                        if (ix < 0 || ix > 7) continue;
                        acc += wr[ky * 3 + kx] * s_img[iy * 8 + ix];
                    }
                }
                acc = fmaxf(acc, 0.0f);
                __nv_bfloat16 hi, lo;
                split_bf(acc, hi, lo);
                int p = (y + 1) * 16 + (x + 1);
                xhi[p * XROW + ic] = hi;
                xlo[p * XROW + ic] = lo;
            }
        }
    }

    int mf = w & 3, ng = w >> 2;
    int mloc = lane & 15, chalf = lane >> 4;
    int m = mf * 16 + mloc;
    int pbase = (m >> 3) * 16 + (m & 7);

    float d0[4] = {0.f, 0.f, 0.f, 0.f};
    float d1[4] = {0.f, 0.f, 0.f, 0.f};
    uint32_t xhi_u = sm_base + XT_HI;
    const int lo_delta = XT_LO - XT_HI;

    for (int cid = 0; cid < 36; cid++) {
        int buf = cid & 1;
        int js = cid >> 2, kc = cid & 3;
        int ky = js / 3, kx = js - ky * 3;

        asm volatile("cp.async.wait_group 0;");
        __syncthreads();

        if (cid + 1 < 36) {
            int njs = (cid + 1) >> 2, nkc = (cid + 1) & 3;
            int krow0 = njs * 256 + nkc * 64;
            #pragma unroll
            for (int o = 0; o < 2; o++) {
                int idx = o * 512 + tid;
                int plane = idx >> 9, rem = idx & 511, r = rem >> 3, seg = rem & 7;
                const __nv_bfloat16* src =
                    (plane ? g_wB_lo : g_wB_hi) + (size_t)(krow0 + r) * 64 + seg * 8;
                cp_async16(sm_base + BBUF + (buf ^ 1) * BBUFSZ + plane * BPLANE
                           + r * 144 + seg * 16, src);
            }
            asm volatile("cp.async.commit_group;");
        }

        uint32_t bbase = sm_base + BBUF + buf * BBUFSZ;
        int ashift = (pbase + ky * 16 + kx) * XROW;

        #pragma unroll
        for (int k16 = 0; k16 < 4; k16++) {
            int ic0 = kc * 64 + k16 * 16;
            uint32_t ah[4], al[4];
            uint32_t aaddr = xhi_u + (uint32_t)(ashift + ic0 + chalf * 8) * 2u;
            ldsm_x4(ah[0], ah[1], ah[2], ah[3], aaddr);
            ldsm_x4(al[0], al[1], al[2], al[3], aaddr + lo_delta);
            uint32_t bh[4], bl[4];
            uint32_t baddr = bbase + (uint32_t)(k16 * 16 + mloc) * 144u
                           + (uint32_t)(ng * 16 + chalf * 8) * 2u;
            ldsm_x4_t(bh[0], bh[1], bh[2], bh[3], baddr);
            ldsm_x4_t(bl[0], bl[1], bl[2], bl[3], baddr + BPLANE);
            mma_bf16(d0, ah, bh[0], bh[1]);
            mma_bf16(d1, ah, bh[2], bh[3]);
            mma_bf16(d0, ah, bl[0], bl[1]);
            mma_bf16(d1, ah, bl[2], bl[3]);
            mma_bf16(d0, al, bh[0], bh[1]);
            mma_bf16(d1, al, bh[2], bh[3]);
        }
    }

    {   // epilogue: bias + squash; store u as bf16 hi/lo planes
        int tig = lane & 3, gid = lane >> 2;
        size_t base = (size_t)b * RI;
        #pragma unroll
        for (int f = 0; f < 2; f++) {
            const float* d = f ? d1 : d0;
            int oc = ng * 16 + f * 8 + 2 * tig;
            float b0 = pb[oc], b1v = pb[oc + 1];
            float v00 = d[0] + b0, v01 = d[1] + b1v;
            float v10 = d[2] + b0, v11 = d[3] + b1v;
            float q00 = sq8(v00), q01 = sq8(v01), q10 = sq8(v10), q11 = sq8(v11);
            float u00 = v00 * (q00 / ((1.0f + q00) * sqrtf(q00 + 1e-9f)));
            float u01 = v01 * (q01 / ((1.0f + q01) * sqrtf(q01 + 1e-9f)));
            float u10 = v10 * (q10 / ((1.0f + q10) * sqrtf(q10 + 1e-9f)));
            float u11 = v11 * (q11 / ((1.0f + q11) * sqrtf(q11 + 1e-9f)));
            int y0 = 2 * mf;
            size_t i00 = base + (size_t)(oc * 8 + y0) * 8 + gid;
            size_t i01 = base + (size_t)((oc + 1) * 8 + y0) * 8 + gid;
            size_t i10 = i00 + 8, i11 = i01 + 8;
            __nv_bfloat16 h, l;
            split_bf(u00, h, l); g_u_hi[i00] = h; g_u_lo[i00] = l;
            split_bf(u01, h, l); g_u_hi[i01] = h; g_u_lo[i01] = l;
            split_bf(u10, h, l); g_u_hi[i10] = h; g_u_lo[i10] = l;
            split_bf(u11, h, l); g_u_hi[i11] = h; g_u_lo[i11] = l;
        }
    }
}

// ---------------- routing small kernels ----------------
__global__ void softmax_routes_kernel() {
    __shared__ float red[512];
    int t = threadIdx.x;
    for (int o = 0; o < 2; o++) {
        float val = g_bij[t * 2 + o];
        red[t] = val; __syncthreads();
        for (int s = 256; s > 0; s >>= 1) {
            if (t < s) red[t] = fmaxf(red[t], red[t + s]);
            __syncthreads();
        }
        float mx = red[0]; __syncthreads();
        float e = expf(val - mx);
        red[t] = e; __syncthreads();
        for (int s = 256; s > 0; s >>= 1) {
            if (t < s) red[t] += red[t + s];
            __syncthreads();
        }
        float sum = red[0]; __syncthreads();
        g_c[t * 2 + o] = e / sum;
    }
}

__global__ void build_wct_kernel(const float* __restrict__ W) {
    int idx = blockIdx.x * blockDim.x + threadIdx.x;
    if (idx >= RI * 64) return;
    int od = idx & 63, ri = idx >> 6;
    int r = ri >> 3, i = ri & 7, o = od >> 5, dd = od & 31;
    float v = g_c[r * 2 + o] * W[((r * 2 + o) * 32 + dd) * 8 + i];
    __nv_bfloat16 h, l;
    split_bf(v, h, l);
    g_wct_hi[idx] = h;
    g_wct_lo[idx] = l;
}

__global__ void squash_v_kernel() {
    int gid = blockIdx.x * blockDim.x + threadIdx.x;
    int warp = gid >> 5, lane = gid & 31;
    if (warp >= BATCH * 2) return;
    int b = warp >> 1, o = warp & 1;
    float x = g_s[b * 64 + o * 32 + lane];
    float sq = warp_sum(x * x);
    float sc = sq / ((1.0f + sq) * sqrtf(sq + 1e-9f));
    g_v[b * 64 + o * 32 + lane] = x * sc;
}

__global__ void b_update_kernel(const float* __restrict__ W) {
    int gid = blockIdx.x * blockDim.x + threadIdx.x;
    int warp = gid >> 5, lane = gid & 31;
    if (warp >= NR * 2) return;
    int r = warp >> 1, o = warp & 1;
    float sum = 0.0f;
    for (int t = lane; t < 256; t += 32) {
        int dd = t >> 3, i = t & 7;
        sum += W[(r * 2 + o) * 256 + t] * g_GT[(o * 32 + dd) * RI + r * 8 + i];
    }
    sum = warp_sum(sum);
    if (lane == 0) g_bij[r * 2 + o] += sum;
}

__global__ void mask_kernel(float* __restrict__ out) {
    int gid = blockIdx.x * blockDim.x + threadIdx.x;
    int b = gid >> 5, lane = gid & 31;
    if (b >= BATCH) return;
    float v0 = g_v[b * 64 + lane];
    float v1 = g_v[b * 64 + 32 + lane];
    float n0 = warp_sum(v0 * v0);
    float n1 = warp_sum(v1 * v1);
    float m0 = (n1 > n0) ? 0.0f : 1.0f;
    float m1 = 1.0f - m0;
    out[b * 64 + lane] = v0;
    out[b * 64 + 32 + lane] = v1;
    if (lane == 0) {
        out[OUT_MASK_OFF + b * 2 + 0] = m0;
        out[OUT_MASK_OFF + b * 2 + 1] = m1;
    }
    __nv_bfloat16 h, l;
    split_bf(v0 * m0, h, l);
    g_h0_hi[b * 64 + lane] = h; g_h0_lo[b * 64 + lane] = l;
    split_bf(v1 * m1, h, l);
    g_h0_hi[b * 64 + 32 + lane] = h; g_h0_lo[b * 64 + 32 + lane] = l;
}

__global__ void sigmoid_bias_kernel(const float* __restrict__ bias, float* __restrict__ out) {
    int i = blockIdx.x * blockDim.x + threadIdx.x;
    if (i >= BATCH * 64) return;
    float v = g_r[i] + bias[i & 63];
    out[OUT_REC_OFF + i] = 1.0f / (1.0f + expf(-v));
}

// ---------------- pipelined plane-GEMM pieces ----------------
__device__ __forceinline__ void cp_stage_A(const __nv_bfloat16* hi, const __nv_bfloat16* lo,
                                           int ldA, int m0, int k0, uint32_t bufb, int tid) {
    #pragma unroll
    for (int q = 0; q < 2; q++) {
        int idx = q * 256 + tid;
        int plane = idx >> 8, rem = idx & 255;
        int row = rem >> 2, seg = rem & 3;
        const __nv_bfloat16* src = (plane ? lo : hi) + (size_t)(m0 + row) * ldA + k0 + seg * 8;
        cp_async16(bufb + (plane ? GAL : GAH) + row * 80 + seg * 16, src);
    }
}
__device__ __forceinline__ void cp_stage_B(const __nv_bfloat16* hi, const __nv_bfloat16* lo,
                                           int ldB, int k0, int n0, uint32_t bufb, int tid) {
    #pragma unroll
    for (int q = 0; q < 2; q++) {
        int idx = q * 256 + tid;
        int plane = idx >> 8, rem = idx & 255;
        int row = rem >> 3, seg = rem & 7;
        const __nv_bfloat16* src = (plane ? lo : hi) + (size_t)(k0 + row) * ldB + n0 + seg * 8;
        cp_async16(bufb + (plane ? GBL : GBH) + row * 144 + seg * 16, src);
    }
}
__device__ __forceinline__ void mma_tile(uint32_t bufb, int w, int lane, float (&d)[2][2][4]) {
    int mf = w & 3, ng = w >> 2;
    int mloc = lane & 15, chalf = lane >> 4;
    #pragma unroll
    for (int ks = 0; ks < 2; ks++) {
        uint32_t ah[4], al[4];
        uint32_t aaddr = bufb + GAH + (uint32_t)((mf * 16 + mloc) * 80 + (ks * 16 + chalf * 8) * 2);
        ldsm_x4(ah[0], ah[1], ah[2], ah[3], aaddr);
        ldsm_x4(al[0], al[1], al[2], al[3], aaddr + (GAL - GAH));
        #pragma unroll
        for (int h = 0; h < 2; h++) {
            uint32_t bh[4], bl[4];
            uint32_t baddr = bufb + GBH
                + (uint32_t)((ks * 16 + mloc) * 144 + (ng * 32 + h * 16 + chalf * 8) * 2);
            ldsm_x4_t(bh[0], bh[1], bh[2], bh[3], baddr);
            ldsm_x4_t(bl[0], bl[1], bl[2], bl[3], baddr + (GBL - GBH));
            mma_bf16(d[h][0], ah, bh[0], bh[1]);
            mma_bf16(d[h][1], ah, bh[2], bh[3]);
            mma_bf16(d[h][0], ah, bl[0], bl[1]);
            mma_bf16(d[h][1], ah, bl[2], bl[3]);
            mma_bf16(d[h][0], al, bh[0], bh[1]);
            mma_bf16(d[h][1], al, bh[2], bh[3]);
        }
    }
}

// C += alpha * A@B  (A,B prestaged planes), split-K atomic
__global__ void __launch_bounds__(256) tgemm_pp_splitk(
    const __nv_bfloat16* __restrict__ Ahi, const __nv_bfloat16* __restrict__ Alo, int ldA,
    const __nv_bfloat16* __restrict__ Bhi, const __nv_bfloat16* __restrict__ Blo, int ldB,
    float* __restrict__ C, int ldC, int Kchunk, float alpha)
{
    __shared__ __align__(16) char sm[2 * GBUF];
    int tid = threadIdx.x, w = tid >> 5, lane = tid & 31;
    int n0 = blockIdx.x * 64, m0 = blockIdx.y * 64, kbase = blockIdx.z * Kchunk;
    uint32_t smb = smem_u32(sm);
    int nc = Kchunk / 32;

    cp_stage_A(Ahi, Alo, ldA, m0, kbase, smb, tid);
    cp_stage_B(Bhi, Blo, ldB, kbase, n0, smb, tid);
    asm volatile("cp.async.commit_group;");

    float d[2][2][4] = {};
    for (int c = 0; c < nc; c++) {
        asm volatile("cp.async.wait_group 0;");
        __syncthreads();
        if (c + 1 < nc) {
            uint32_t nb = smb + ((c + 1) & 1) * GBUF;
            cp_stage_A(Ahi, Alo, ldA, m0, kbase + (c + 1) * 32, nb, tid);
            cp_stage_B(Bhi, Blo, ldB, kbase + (c + 1) * 32, n0, nb, tid);
            asm volatile("cp.async.commit_group;");
        }
        mma_tile(smb + (c & 1) * GBUF, w, lane, d);
    }
    int mf = w & 3, ng = w >> 2;
    int tig = lane & 3, gid = lane >> 2;
    #pragma unroll
    for (int h = 0; h < 2; h++)
        #pragma unroll
        for (int f = 0; f < 2; f++) {
            int col = n0 + ng * 32 + h * 16 + f * 8 + 2 * tig;
            int row = m0 + mf * 16 + gid;
            atomicAdd(&C[(size_t)row * ldC + col],           alpha * d[h][f][0]);
            atomicAdd(&C[(size_t)row * ldC + col + 1],       alpha * d[h][f][1]);
            atomicAdd(&C[(size_t)(row + 8) * ldC + col],     alpha * d[h][f][2]);
            atomicAdd(&C[(size_t)(row + 8) * ldC + col + 1], alpha * d[h][f][3]);
        }
}

// GT += alpha * V^T @ B  (V fp32 [K][64] scalar-staged; B planes), split-K atomic
__global__ void __launch_bounds__(256) tgemm_trv_splitk(
    const float* __restrict__ V,
    const __nv_bfloat16* __restrict__ Bhi, const __nv_bfloat16* __restrict__ Blo, int ldB,
    float* __restrict__ C, int ldC, int Kchunk, float alpha)
{
    __shared__ __align__(16) char sm[2 * GBUF];
    int tid = threadIdx.x, w = tid >> 5, lane = tid & 31;
    int n0 = blockIdx.x * 64, kbase = blockIdx.z * Kchunk;
    uint32_t smb = smem_u32(sm);
    int nc = Kchunk / 32;

    // scalar A staging: A[m=od][k=b] = V[b][od]
    auto stageA = [&](int k0, char* buf) {
        int k = tid >> 3, mq = (tid & 7) * 8;
        const float* p = V + (size_t)(k0 + k) * 64 + mq;
        float4 f0 = *(const float4*)p, f1 = *(const float4*)(p + 4);
        float fa[8] = {f0.x, f0.y, f0.z, f0.w, f1.x, f1.y, f1.z, f1.w};
        #pragma unroll
        for (int i = 0; i < 8; i++) {
            __nv_bfloat16 h, l;
            split_bf(fa[i], h, l);
            *(__nv_bfloat16*)(buf + GAH + (mq + i) * 80 + k * 2) = h;
            *(__nv_bfloat16*)(buf + GAL + (mq + i) * 80 + k * 2) = l;
        }
    };

    stageA(kbase, sm);
    cp_stage_B(Bhi, Blo, ldB, kbase, n0, smb, tid);
    asm volatile("cp.async.commit_group;");
    __syncthreads();   // publish scalar A stores of chunk 0

    float d[2][2][4] = {};
    for (int c = 0; c < nc; c++) {
        asm volatile("cp.async.wait_group 0;");
        __syncthreads();
        if (c + 1 < nc) {
            char* nbuf = sm + ((c + 1) & 1) * GBUF;
            stageA(kbase + (c + 1) * 32, nbuf);
            cp_stage_B(Bhi, Blo, ldB, kbase + (c + 1) * 32, n0, smb + ((c + 1) & 1) * GBUF, tid);
            asm volatile("cp.async.commit_group;");
        }
        mma_tile(smb + (c & 1) * GBUF, w, lane, d);
    }
    int mf = w & 3, ng = w >> 2;
    int tig = lane & 3, gid = lane >> 2;
    #pragma unroll
    for (int h = 0; h < 2; h++)
        #pragma unroll
        for (int f = 0; f < 2; f++) {
            int col = n0 + ng * 32 + h * 16 + f * 8 + 2 * tig;
            int row = mf * 16 + gid;
            atomicAdd(&C[(size_t)row * ldC + col],           alpha * d[h][f][0]);
            atomicAdd(&C[(size_t)row * ldC + col + 1],       alpha * d[h][f][1]);
            atomicAdd(&C[(size_t)(row + 8) * ldC + col],     alpha * d[h][f][2]);
            atomicAdd(&C[(size_t)(row + 8) * ldC + col + 1], alpha * d[h][f][3]);
        }
}

// Chi/Clo = split(relu(A@B + bias)), full K (A,B planes)
__global__ void __launch_bounds__(256) tgemm_pp_bias(
    const __nv_bfloat16* __restrict__ Ahi, const __nv_bfloat16* __restrict__ Alo, int ldA,
    const __nv_bfloat16* __restrict__ Bhi, const __nv_bfloat16* __restrict__ Blo, int ldB,
    const float* __restrict__ bias,
    __nv_bfloat16* __restrict__ Chi, __nv_bfloat16* __restrict__ Clo, int N, int K)
{
    __shared__ __align__(16) char sm[2 * GBUF];
    int tid = threadIdx.x, w = tid >> 5, lane = tid & 31;
    int n0 = blockIdx.x * 64, m0 = blockIdx.y * 64;
    uint32_t smb = smem_u32(sm);
    int nc = K / 32;

    cp_stage_A(Ahi, Alo, ldA, m0, 0, smb, tid);
    cp_stage_B(Bhi, Blo, ldB, 0, n0, smb, tid);
    asm volatile("cp.async.commit_group;");

    float d[2][2][4] = {};
    for (int c = 0; c < nc; c++) {
        asm volatile("cp.async.wait_group 0;");
        __syncthreads();
        if (c + 1 < nc) {
            uint32_t nb = smb + ((c + 1) & 1) * GBUF;
            cp_stage_A(Ahi, Alo, ldA, m0, (c + 1) * 32, nb, tid);
            cp_stage_B(Bhi, Blo, ldB, (c + 1) * 32, n0, nb, tid);
            asm volatile("cp.async.commit_group;");
        }
        mma_tile(smb + (c & 1) * GBUF, w, lane, d);
    }
    int mf = w & 3, ng = w >> 2;
    int tig = lane & 3, gid = lane >> 2;
    #pragma unroll
    for (int h = 0; h < 2; h++)
        #pragma unroll
        for (int f = 0; f < 2; f++) {
            int col = n0 + ng * 32 + h * 16 + f * 8 + 2 * tig;
            int row = m0 + mf * 16 + gid;
            #pragma unroll
            for (int e = 0; e < 4; e++) {
                int rr = row + (e >> 1) * 8;
                int cc = col + (e & 1);
                float v = fmaxf(d[h][f][e] + bias[cc], 0.0f);
                __nv_bfloat16 hh, ll;
                split_bf(v, hh, ll);
                Chi[(size_t)rr * N + cc] = hh;
                Clo[(size_t)rr * N + cc] = ll;
            }
        }
}

// ---------------- launch ----------------
extern "C" void kernel_launch(void* const* d_in, const int* in_sizes, int n_in,
                              void* d_out, int out_size)
{
    const float* data    = (const float*)d_in[0];
    const float* conv1_w = (const float*)d_in[1];
    const float* conv1_b = (const float*)d_in[2];
    const float* prim_w  = (const float*)d_in[3];
    const float* prim_b  = (const float*)d_in[4];
    const float* W_digit = (const float*)d_in[5];
    const float* dec1_w  = (const float*)d_in[6];
    const float* dec1_b  = (const float*)d_in[7];
    const float* dec2_w  = (const float*)d_in[8];
    const float* dec2_b  = (const float*)d_in[9];
    const float* dec3_w  = (const float*)d_in[10];
    const float* dec3_b  = (const float*)d_in[11];
    float* out = (float*)d_out;

    float *p_bij, *p_s, *p_GT, *p_v, *p_r;
    cudaGetSymbolAddress((void**)&p_bij, g_bij);
    cudaGetSymbolAddress((void**)&p_s,   g_s);
    cudaGetSymbolAddress((void**)&p_GT,  g_GT);
    cudaGetSymbolAddress((void**)&p_v,   g_v);
    cudaGetSymbolAddress((void**)&p_r,   g_r);

    __nv_bfloat16 *u_hi, *u_lo, *wct_hi, *wct_lo, *h0_hi, *h0_lo;
    __nv_bfloat16 *h1_hi, *h1_lo, *h2_hi, *h2_lo;
    __nv_bfloat16 *w1_hi, *w1_lo, *w2_hi, *w2_lo, *w3_hi, *w3_lo;
    cudaGetSymbolAddress((void**)&u_hi, g_u_hi);
    cudaGetSymbolAddress((void**)&u_lo, g_u_lo);
    cudaGetSymbolAddress((void**)&wct_hi, g_wct_hi);
    cudaGetSymbolAddress((void**)&wct_lo, g_wct_lo);
    cudaGetSymbolAddress((void**)&h0_hi, g_h0_hi);
    cudaGetSymbolAddress((void**)&h0_lo, g_h0_lo);
    cudaGetSymbolAddress((void**)&h1_hi, g_h1_hi);
    cudaGetSymbolAddress((void**)&h1_lo, g_h1_lo);
    cudaGetSymbolAddress((void**)&h2_hi, g_h2_hi);
    cudaGetSymbolAddress((void**)&h2_lo, g_h2_lo);
    cudaGetSymbolAddress((void**)&w1_hi, g_w1_hi);
    cudaGetSymbolAddress((void**)&w1_lo, g_w1_lo);
    cudaGetSymbolAddress((void**)&w2_hi, g_w2_hi);
    cudaGetSymbolAddress((void**)&w2_lo, g_w2_lo);
    cudaGetSymbolAddress((void**)&w3_hi, g_w3_hi);
    cudaGetSymbolAddress((void**)&w3_lo, g_w3_lo);

    static int smem_set = 0;
    if (!smem_set) {
        cudaFuncSetAttribute(conv_tc_kernel,
                             cudaFuncAttributeMaxDynamicSharedMemorySize, CONV_SMEM);
        smem_set = 1;
    }

    wb_split_kernel<<<576, 256>>>(prim_w);                             // 0
    split_kernel<<<128, 256>>>(dec1_w, w1_hi, w1_lo, 64 * 512);        // 1
    split_kernel<<<2048, 256>>>(dec2_w, w2_hi, w2_lo, 512 * 1024);     // 2
    conv_tc_kernel<<<BATCH, 512, CONV_SMEM>>>(data, conv1_w, conv1_b, prim_b);  // 3
    split_kernel<<<256, 256>>>(dec3_w, w3_hi, w3_lo, 1024 * 64);       // 4
    zero_kernel<<<4, 256>>>(p_bij, NR * 2);                            // 5

    for (int it = 0; it < 3; it++) {
        softmax_routes_kernel<<<1, 512>>>();
        build_wct_kernel<<<1024, 256>>>(W_digit);
        zero_kernel<<<1024, 256>>>(p_s, BATCH * 64);
        tgemm_pp_splitk<<<dim3(1, 64, 8), 256>>>(u_hi, u_lo, RI, wct_hi, wct_lo, 64,
                                                 p_s, 64, 512, 1.0f);
        squash_v_kernel<<<1024, 256>>>();
        if (it < 2) {
            zero_kernel<<<1024, 256>>>(p_GT, 64 * RI);
            tgemm_trv_splitk<<<dim3(64, 1, 8), 256>>>(p_v, u_hi, u_lo, RI,
                                                      p_GT, RI, 512, 1.0f / (float)BATCH);
            b_update_kernel<<<128, 256>>>(W_digit);
        }
    }

    mask_kernel<<<512, 256>>>(out);
    zero_kernel<<<1024, 256>>>(p_r, BATCH * 64);

    tgemm_pp_bias<<<dim3(8, 64), 256>>>(h0_hi, h0_lo, 64, w1_hi, w1_lo, 512,
                                        dec1_b, h1_hi, h1_lo, 512, 64);
    tgemm_pp_bias<<<dim3(16, 64), 256>>>(h1_hi, h1_lo, 512, w2_hi, w2_lo, 1024,
                                         dec2_b, h2_hi, h2_lo, 1024, 512);
    tgemm_pp_splitk<<<dim3(1, 64, 4), 256>>>(h2_hi, h2_lo, 1024, w3_hi, w3_lo, 64,
                                             p_r, 64, 256, 1.0f);
    sigmoid_bias_kernel<<<1024, 256>>>(dec3_b, out);
}

// round 13
// speedup vs baseline: 1.2506x; 1.0048x over previous
#include <cuda_runtime.h>
#include <cuda_bf16.h>
#include <math.h>
#include <stdint.h>

#define BATCH 4096
#define NR 512
#define RI 4096
#define OUT_REC_OFF 262144
#define OUT_MASK_OFF 524288

// conv-kernel SMEM layout (bytes)
#define XROW 264
#define XT_HI 0
#define XT_LO 84480
#define BBUF  168960
#define BPLANE 9216
#define BBUFSZ 18432
#define CONV_SMEM 205824

// pipelined GEMM staging: per buffer A 64x32 (pitch 80) hi/lo + B 32x64 (pitch 144) hi/lo
#define GAH 0
#define GAL 5120
#define GBH 10240
#define GBL 14848
#define GBUF 19456

// ---------------- device globals ----------------
__device__ __align__(16) __nv_bfloat16 g_wB_hi[2304 * 64];
__device__ __align__(16) __nv_bfloat16 g_wB_lo[2304 * 64];
__device__ __align__(16) __nv_bfloat16 g_u_hi[(size_t)BATCH * RI];
__device__ __align__(16) __nv_bfloat16 g_u_lo[(size_t)BATCH * RI];
__device__ __align__(16) __nv_bfloat16 g_wct_hi[RI * 64];
__device__ __align__(16) __nv_bfloat16 g_wct_lo[RI * 64];
__device__ __align__(16) __nv_bfloat16 g_h0_hi[BATCH * 64];
__device__ __align__(16) __nv_bfloat16 g_h0_lo[BATCH * 64];
__device__ __align__(16) __nv_bfloat16 g_h1_hi[(size_t)BATCH * 512];
__device__ __align__(16) __nv_bfloat16 g_h1_lo[(size_t)BATCH * 512];
__device__ __align__(16) __nv_bfloat16 g_h2_hi[(size_t)BATCH * 1024];
__device__ __align__(16) __nv_bfloat16 g_h2_lo[(size_t)BATCH * 1024];
__device__ __align__(16) __nv_bfloat16 g_w1_hi[64 * 512];
__device__ __align__(16) __nv_bfloat16 g_w1_lo[64 * 512];
__device__ __align__(16) __nv_bfloat16 g_w2_hi[512 * 1024];
__device__ __align__(16) __nv_bfloat16 g_w2_lo[512 * 1024];
__device__ __align__(16) __nv_bfloat16 g_w3_hi[1024 * 64];
__device__ __align__(16) __nv_bfloat16 g_w3_lo[1024 * 64];
__device__ float g_bij[NR * 2];
__device__ float g_c[NR * 2];
__device__ float g_s[BATCH * 64];
__device__ float g_v[BATCH * 64];
__device__ float g_GT[64 * RI];
__device__ float g_r[BATCH * 64];

// ---------------- helpers ----------------
__device__ __forceinline__ float warp_sum(float v) {
    #pragma unroll
    for (int s = 16; s > 0; s >>= 1) v += __shfl_xor_sync(0xFFFFFFFFu, v, s);
    return v;
}
__device__ __forceinline__ uint32_t smem_u32(const void* p) {
    return (uint32_t)__cvta_generic_to_shared(p);
}
__device__ __forceinline__ void ldsm_x4(uint32_t& r0, uint32_t& r1, uint32_t& r2, uint32_t& r3,
                                        uint32_t addr) {
    asm volatile("ldmatrix.sync.aligned.m8n8.x4.shared.b16 {%0,%1,%2,%3}, [%4];"
                 : "=r"(r0), "=r"(r1), "=r"(r2), "=r"(r3) : "r"(addr));
}
__device__ __forceinline__ void ldsm_x4_t(uint32_t& r0, uint32_t& r1, uint32_t& r2, uint32_t& r3,
                                          uint32_t addr) {
    asm volatile("ldmatrix.sync.aligned.m8n8.x4.trans.shared.b16 {%0,%1,%2,%3}, [%4];"
                 : "=r"(r0), "=r"(r1), "=r"(r2), "=r"(r3) : "r"(addr));
}
__device__ __forceinline__ void mma_bf16(float d[4], const uint32_t a[4],
                                         uint32_t b0, uint32_t b1) {
    asm volatile(
        "mma.sync.aligned.m16n8k16.row.col.f32.bf16.bf16.f32 "
        "{%0,%1,%2,%3}, {%4,%5,%6,%7}, {%8,%9}, {%0,%1,%2,%3};"
        : "+f"(d[0]), "+f"(d[1]), "+f"(d[2]), "+f"(d[3])
        : "r"(a[0]), "r"(a[1]), "r"(a[2]), "r"(a[3]), "r"(b0), "r"(b1));
}
__device__ __forceinline__ void cp_async16(uint32_t dst, const void* src) {
    asm volatile("cp.async.cg.shared.global [%0], [%1], 16;" :: "r"(dst), "l"(src) : "memory");
}
__device__ __forceinline__ void split_bf(float v, __nv_bfloat16& h, __nv_bfloat16& l) {
    h = __float2bfloat16(v);
    l = __float2bfloat16(v - __bfloat162float(h));
}
__device__ __forceinline__ uint32_t pk2bf(__nv_bfloat16 a, __nv_bfloat16 b) {
    return (uint32_t)__bfloat16_as_ushort(a) | ((uint32_t)__bfloat16_as_ushort(b) << 16);
}

// ---------------- basic kernels ----------------
__global__ void zero_kernel(float* p, int n) {
    int i = blockIdx.x * blockDim.x + threadIdx.x;
    if (i < n) p[i] = 0.0f;
}
__global__ void split_kernel(const float* __restrict__ src,
                             __nv_bfloat16* __restrict__ hi,
                             __nv_bfloat16* __restrict__ lo, int n) {
    int i = blockIdx.x * blockDim.x + threadIdx.x;
    if (i >= n) return;
    __nv_bfloat16 h, l;
    split_bf(src[i], h, l);
    hi[i] = h; lo[i] = l;
}
__global__ void wb_split_kernel(const float* __restrict__ pw) {
    int idx = blockIdx.x * blockDim.x + threadIdx.x;
    if (idx >= 147456) return;
    int k = idx >> 6, oc = idx & 63;
    int j = k >> 8, ic = k & 255;
    __nv_bfloat16 h, l;
    split_bf(pw[oc * 2304 + ic * 9 + j], h, l);
    g_wB_hi[idx] = h;
    g_wB_lo[idx] = l;
}

// ---------------- fused conv1 + bf16 3-term mma primary conv + squash --------
// one CTA per image, 512 threads; warp = (mf = w&3, kg = w>>2); warp tile m16 x n64 over K/4
__global__ void __launch_bounds__(512, 1) conv_tc_kernel(
    const float* __restrict__ data, const float* __restrict__ w1,
    const float* __restrict__ b1, const float* __restrict__ pb)
{
    extern __shared__ char smem[];
    __shared__ float s_img[64];
    __nv_bfloat16* xhi = (__nv_bfloat16*)(smem + XT_HI);
    __nv_bfloat16* xlo = (__nv_bfloat16*)(smem + XT_LO);

    int b = blockIdx.x;
    int tid = threadIdx.x;
    int w = tid >> 5, lane = tid & 31;
    uint32_t sm_base = smem_u32(smem);

    #pragma unroll
    for (int o = 0; o < 2; o++) {
        int idx = o * 512 + tid;
        int plane = idx >> 9, rem = idx & 511, r = rem >> 3, seg = rem & 7;
        const __nv_bfloat16* src = (plane ? g_wB_lo : g_wB_hi) + (size_t)r * 64 + seg * 8;
        cp_async16(sm_base + BBUF + plane * BPLANE + r * 144 + seg * 16, src);
    }
    asm volatile("cp.async.commit_group;");

    {
        uint4 z = make_uint4(0, 0, 0, 0);
        uint4* p = (uint4*)smem;
        for (int i = tid; i < (XT_LO * 2) / 16; i += 512) p[i] = z;
    }
    if (tid < 64) s_img[tid] = data[b * 64 + tid];
    __syncthreads();

    {   // conv1 3x3 pad1 + relu -> bf16 hi/lo planes
        int ic = tid & 255, half = tid >> 8;
        float wr[9];
        #pragma unroll
        for (int k = 0; k < 9; k++) wr[k] = w1[ic * 9 + k];
        float bias = b1[ic];
        #pragma unroll
        for (int yy = 0; yy < 4; yy++) {
            int y = half * 4 + yy;
            #pragma unroll
            for (int x = 0; x < 8; x++) {
                float acc = bias;
                #pragma unroll
                for (int ky = 0; ky < 3; ky++) {
                    int iy = y + ky - 1;
                    if (iy < 0 || iy > 7) continue;
                    #pragma unroll
                    for (int kx = 0; kx < 3; kx++) {
                        int ix = x + kx - 1;
                        if (ix < 0 || ix > 7) continue;
                        acc += wr[ky * 3 + kx] * s_img[iy * 8 + ix];
                    }
                }
                acc = fmaxf(acc, 0.0f);
                __nv_bfloat16 hi, lo;
                split_bf(acc, hi, lo);
                int p = (y + 1) * 16 + (x + 1);
                xhi[p * XROW + ic] = hi;
                xlo[p * XROW + ic] = lo;
            }
        }
    }

    int mf = w & 3, kg = w >> 2;
    int mloc = lane & 15, chalf = lane >> 4;
    int m = mf * 16 + mloc;
    int pbase = (m >> 3) * 16 + (m & 7);

    float d[8][4] = {};
    uint32_t xhi_u = sm_base + XT_HI;
    const int lo_delta = XT_LO - XT_HI;

    for (int cid = 0; cid < 36; cid++) {
        int buf = cid & 1;
        int js = cid >> 2, kc = cid & 3;
        int ky = js / 3, kx = js - ky * 3;

        asm volatile("cp.async.wait_group 0;");
        __syncthreads();

        if (cid + 1 < 36) {
            int njs = (cid + 1) >> 2, nkc = (cid + 1) & 3;
            int krow0 = njs * 256 + nkc * 64;
            #pragma unroll
            for (int o = 0; o < 2; o++) {
                int idx = o * 512 + tid;
                int plane = idx >> 9, rem = idx & 511, r = rem >> 3, seg = rem & 7;
                const __nv_bfloat16* src =
                    (plane ? g_wB_lo : g_wB_hi) + (size_t)(krow0 + r) * 64 + seg * 8;
                cp_async16(sm_base + BBUF + (buf ^ 1) * BBUFSZ + plane * BPLANE
                           + r * 144 + seg * 16, src);
            }
            asm volatile("cp.async.commit_group;");
        }

        uint32_t bbase = sm_base + BBUF + buf * BBUFSZ;
        int ashift = (pbase + ky * 16 + kx) * XROW;
        int ic0 = kc * 64 + kg * 16;

        // A frags: one k16 slice (this warp's kg)
        uint32_t ah[4], al[4];
        uint32_t aaddr = xhi_u + (uint32_t)(ashift + ic0 + chalf * 8) * 2u;
        ldsm_x4(ah[0], ah[1], ah[2], ah[3], aaddr);
        ldsm_x4(al[0], al[1], al[2], al[3], aaddr + lo_delta);
        // B frags: all 64 oc for this k16
        uint32_t bh[16], bl[16];
        uint32_t brow = bbase + (uint32_t)(kg * 16 + mloc) * 144u;
        #pragma unroll
        for (int c4 = 0; c4 < 4; c4++) {
            uint32_t baddr = brow + (uint32_t)(c4 * 16 + chalf * 8) * 2u;
            ldsm_x4_t(bh[c4*4+0], bh[c4*4+1], bh[c4*4+2], bh[c4*4+3], baddr);
            ldsm_x4_t(bl[c4*4+0], bl[c4*4+1], bl[c4*4+2], bl[c4*4+3], baddr + BPLANE);
        }
        #pragma unroll
        for (int f = 0; f < 8; f++) mma_bf16(d[f], ah, bh[f*2], bh[f*2+1]);
        #pragma unroll
        for (int f = 0; f < 8; f++) mma_bf16(d[f], ah, bl[f*2], bl[f*2+1]);
        #pragma unroll
        for (int f = 0; f < 8; f++) mma_bf16(d[f], al, bh[f*2], bh[f*2+1]);
    }

    // ---- cross-kg reduction into fp32 tile [64 pos][pitch 68] at smem+0 ----
    float* tile = (float*)smem;   // A planes dead after main loop
    int tig = lane & 3, gid = lane >> 2;
    #pragma unroll 1
    for (int g = 0; g < 4; g++) {
        __syncthreads();
        if (kg == g) {
            int r0 = mf * 16 + gid;
            #pragma unroll
            for (int f = 0; f < 8; f++) {
                int col = f * 8 + 2 * tig;
                if (g == 0) {
                    tile[r0 * 68 + col]           = d[f][0];
                    tile[r0 * 68 + col + 1]       = d[f][1];
                    tile[(r0 + 8) * 68 + col]     = d[f][2];
                    tile[(r0 + 8) * 68 + col + 1] = d[f][3];
                } else {
                    tile[r0 * 68 + col]           += d[f][0];
                    tile[r0 * 68 + col + 1]       += d[f][1];
                    tile[(r0 + 8) * 68 + col]     += d[f][2];
                    tile[(r0 + 8) * 68 + col + 1] += d[f][3];
                }
            }
        }
    }
    __syncthreads();

    // ---- epilogue: thread = (oc, y); bias + squash over x; vector store ----
    {
        int oc = tid & 63, y = tid >> 6;
        float bias = pb[oc];
        float xv[8];
        float q = 0.0f;
        #pragma unroll
        for (int x = 0; x < 8; x++) {
            float v = tile[(y * 8 + x) * 68 + oc] + bias;
            xv[x] = v;
            q += v * v;
        }
        float sc = q / ((1.0f + q) * sqrtf(q + 1e-9f));
        uint32_t hp[4], lp[4];
        #pragma unroll
        for (int p = 0; p < 4; p++) {
            __nv_bfloat16 h0, l0, h1, l1;
            split_bf(xv[2*p] * sc, h0, l0);
            split_bf(xv[2*p+1] * sc, h1, l1);
            hp[p] = pk2bf(h0, h1);
            lp[p] = pk2bf(l0, l1);
        }
        size_t idx = (size_t)b * RI + (size_t)(oc * 8 + y) * 8;
        *(uint4*)&g_u_hi[idx] = make_uint4(hp[0], hp[1], hp[2], hp[3]);
        *(uint4*)&g_u_lo[idx] = make_uint4(lp[0], lp[1], lp[2], lp[3]);
    }
}

// ---------------- routing small kernels ----------------
__global__ void softmax_routes_kernel() {
    __shared__ float red[512];
    int t = threadIdx.x;
    for (int o = 0; o < 2; o++) {
        float val = g_bij[t * 2 + o];
        red[t] = val; __syncthreads();
        for (int s = 256; s > 0; s >>= 1) {
            if (t < s) red[t] = fmaxf(red[t], red[t + s]);
            __syncthreads();
        }
        float mx = red[0]; __syncthreads();
        float e = expf(val - mx);
        red[t] = e; __syncthreads();
        for (int s = 256; s > 0; s >>= 1) {
            if (t < s) red[t] += red[t + s];
            __syncthreads();
        }
        float sum = red[0]; __syncthreads();
        g_c[t * 2 + o] = e / sum;
    }
}

__global__ void build_wct_kernel(const float* __restrict__ W) {
    int idx = blockIdx.x * blockDim.x + threadIdx.x;
    if (idx >= RI * 64) return;
    int od = idx & 63, ri = idx >> 6;
    int r = ri >> 3, i = ri & 7, o = od >> 5, dd = od & 31;
    float v = g_c[r * 2 + o] * W[((r * 2 + o) * 32 + dd) * 8 + i];
    __nv_bfloat16 h, l;
    split_bf(v, h, l);
    g_wct_hi[idx] = h;
    g_wct_lo[idx] = l;
}

__global__ void squash_v_kernel() {
    int gid = blockIdx.x * blockDim.x + threadIdx.x;
    int warp = gid >> 5, lane = gid & 31;
    if (warp >= BATCH * 2) return;
    int b = warp >> 1, o = warp & 1;
    float x = g_s[b * 64 + o * 32 + lane];
    float sq = warp_sum(x * x);
    float sc = sq / ((1.0f + sq) * sqrtf(sq + 1e-9f));
    g_v[b * 64 + o * 32 + lane] = x * sc;
}

__global__ void b_update_kernel(const float* __restrict__ W) {
    int gid = blockIdx.x * blockDim.x + threadIdx.x;
    int warp = gid >> 5, lane = gid & 31;
    if (warp >= NR * 2) return;
    int r = warp >> 1, o = warp & 1;
    float sum = 0.0f;
    for (int t = lane; t < 256; t += 32) {
        int dd = t >> 3, i = t & 7;
        sum += W[(r * 2 + o) * 256 + t] * g_GT[(o * 32 + dd) * RI + r * 8 + i];
    }
    sum = warp_sum(sum);
    if (lane == 0) g_bij[r * 2 + o] += sum;
}

__global__ void mask_kernel(float* __restrict__ out) {
    int gid = blockIdx.x * blockDim.x + threadIdx.x;
    int b = gid >> 5, lane = gid & 31;
    if (b >= BATCH) return;
    float v0 = g_v[b * 64 + lane];
    float v1 = g_v[b * 64 + 32 + lane];
    float n0 = warp_sum(v0 * v0);
    float n1 = warp_sum(v1 * v1);
    float m0 = (n1 > n0) ? 0.0f : 1.0f;
    float m1 = 1.0f - m0;
    out[b * 64 + lane] = v0;
    out[b * 64 + 32 + lane] = v1;
    if (lane == 0) {
        out[OUT_MASK_OFF + b * 2 + 0] = m0;
        out[OUT_MASK_OFF + b * 2 + 1] = m1;
    }
    __nv_bfloat16 h, l;
    split_bf(v0 * m0, h, l);
    g_h0_hi[b * 64 + lane] = h; g_h0_lo[b * 64 + lane] = l;
    split_bf(v1 * m1, h, l);
    g_h0_hi[b * 64 + 32 + lane] = h; g_h0_lo[b * 64 + 32 + lane] = l;
}

__global__ void sigmoid_bias_kernel(const float* __restrict__ bias, float* __restrict__ out) {
    int i = blockIdx.x * blockDim.x + threadIdx.x;
    if (i >= BATCH * 64) return;
    float v = g_r[i] + bias[i & 63];
    out[OUT_REC_OFF + i] = 1.0f / (1.0f + expf(-v));
}

// ---------------- pipelined plane-GEMM pieces ----------------
__device__ __forceinline__ void cp_stage_A(const __nv_bfloat16* hi, const __nv_bfloat16* lo,
                                           int ldA, int m0, int k0, uint32_t bufb, int tid) {
    #pragma unroll
    for (int q = 0; q < 2; q++) {
        int idx = q * 256 + tid;
        int plane = idx >> 8, rem = idx & 255;
        int row = rem >> 2, seg = rem & 3;
        const __nv_bfloat16* src = (plane ? lo : hi) + (size_t)(m0 + row) * ldA + k0 + seg * 8;
        cp_async16(bufb + (plane ? GAL : GAH) + row * 80 + seg * 16, src);
    }
}
__device__ __forceinline__ void cp_stage_B(const __nv_bfloat16* hi, const __nv_bfloat16* lo,
                                           int ldB, int k0, int n0, uint32_t bufb, int tid) {
    #pragma unroll
    for (int q = 0; q < 2; q++) {
        int idx = q * 256 + tid;
        int plane = idx >> 8, rem = idx & 255;
        int row = rem >> 3, seg = rem & 7;
        const __nv_bfloat16* src = (plane ? lo : hi) + (size_t)(k0 + row) * ldB + n0 + seg * 8;
        cp_async16(bufb + (plane ? GBL : GBH) + row * 144 + seg * 16, src);
    }
}
__device__ __forceinline__ void mma_tile(uint32_t bufb, int w, int lane, float (&d)[2][2][4]) {
    int mf = w & 3, ng = w >> 2;
    int mloc = lane & 15, chalf = lane >> 4;
    #pragma unroll
    for (int ks = 0; ks < 2; ks++) {
        uint32_t ah[4], al[4];
        uint32_t aaddr = bufb + GAH + (uint32_t)((mf * 16 + mloc) * 80 + (ks * 16 + chalf * 8) * 2);
        ldsm_x4(ah[0], ah[1], ah[2], ah[3], aaddr);
        ldsm_x4(al[0], al[1], al[2], al[3], aaddr + (GAL - GAH));
        #pragma unroll
        for (int h = 0; h < 2; h++) {
            uint32_t bh[4], bl[4];
            uint32_t baddr = bufb + GBH
                + (uint32_t)((ks * 16 + mloc) * 144 + (ng * 32 + h * 16 + chalf * 8) * 2);
            ldsm_x4_t(bh[0], bh[1], bh[2], bh[3], baddr);
            ldsm_x4_t(bl[0], bl[1], bl[2], bl[3], baddr + (GBL - GBH));
            mma_bf16(d[h][0], ah, bh[0], bh[1]);
            mma_bf16(d[h][1], ah, bh[2], bh[3]);
            mma_bf16(d[h][0], ah, bl[0], bl[1]);
            mma_bf16(d[h][1], ah, bl[2], bl[3]);
            mma_bf16(d[h][0], al, bh[0], bh[1]);
            mma_bf16(d[h][1], al, bh[2], bh[3]);
        }
    }
}

// C += alpha * A@B  (A,B prestaged planes), split-K atomic
__global__ void __launch_bounds__(256) tgemm_pp_splitk(
    const __nv_bfloat16* __restrict__ Ahi, const __nv_bfloat16* __restrict__ Alo, int ldA,
    const __nv_bfloat16* __restrict__ Bhi, const __nv_bfloat16* __restrict__ Blo, int ldB,
    float* __restrict__ C, int ldC, int Kchunk, float alpha)
{
    __shared__ __align__(16) char sm[2 * GBUF];
    int tid = threadIdx.x, w = tid >> 5, lane = tid & 31;
    int n0 = blockIdx.x * 64, m0 = blockIdx.y * 64, kbase = blockIdx.z * Kchunk;
    uint32_t smb = smem_u32(sm);
    int nc = Kchunk / 32;

    cp_stage_A(Ahi, Alo, ldA, m0, kbase, smb, tid);
    cp_stage_B(Bhi, Blo, ldB, kbase, n0, smb, tid);
    asm volatile("cp.async.commit_group;");

    float d[2][2][4] = {};
    for (int c = 0; c < nc; c++) {
        asm volatile("cp.async.wait_group 0;");
        __syncthreads();
        if (c + 1 < nc) {
            uint32_t nb = smb + ((c + 1) & 1) * GBUF;
            cp_stage_A(Ahi, Alo, ldA, m0, kbase + (c + 1) * 32, nb, tid);
            cp_stage_B(Bhi, Blo, ldB, kbase + (c + 1) * 32, n0, nb, tid);
            asm volatile("cp.async.commit_group;");
        }
        mma_tile(smb + (c & 1) * GBUF, w, lane, d);
    }
    int mf = w & 3, ng = w >> 2;
    int tig = lane & 3, gid = lane >> 2;
    #pragma unroll
    for (int h = 0; h < 2; h++)
        #pragma unroll
        for (int f = 0; f < 2; f++) {
            int col = n0 + ng * 32 + h * 16 + f * 8 + 2 * tig;
            int row = m0 + mf * 16 + gid;
            atomicAdd(&C[(size_t)row * ldC + col],           alpha * d[h][f][0]);
            atomicAdd(&C[(size_t)row * ldC + col + 1],       alpha * d[h][f][1]);
            atomicAdd(&C[(size_t)(row + 8) * ldC + col],     alpha * d[h][f][2]);
            atomicAdd(&C[(size_t)(row + 8) * ldC + col + 1], alpha * d[h][f][3]);
        }
}

// GT += alpha * V^T @ B  (V fp32 [K][64] scalar-staged; B planes), split-K atomic
__global__ void __launch_bounds__(256) tgemm_trv_splitk(
    const float* __restrict__ V,
    const __nv_bfloat16* __restrict__ Bhi, const __nv_bfloat16* __restrict__ Blo, int ldB,
    float* __restrict__ C, int ldC, int Kchunk, float alpha)
{
    __shared__ __align__(16) char sm[2 * GBUF];
    int tid = threadIdx.x, w = tid >> 5, lane = tid & 31;
    int n0 = blockIdx.x * 64, kbase = blockIdx.z * Kchunk;
    uint32_t smb = smem_u32(sm);
    int nc = Kchunk / 32;

    auto stageA = [&](int k0, char* buf) {
        int k = tid >> 3, mq = (tid & 7) * 8;
        const float* p = V + (size_t)(k0 + k) * 64 + mq;
        float4 f0 = *(const float4*)p, f1 = *(const float4*)(p + 4);
        float fa[8] = {f0.x, f0.y, f0.z, f0.w, f1.x, f1.y, f1.z, f1.w};
        #pragma unroll
        for (int i = 0; i < 8; i++) {
            __nv_bfloat16 h, l;
            split_bf(fa[i], h, l);
            *(__nv_bfloat16*)(buf + GAH + (mq + i) * 80 + k * 2) = h;
            *(__nv_bfloat16*)(buf + GAL + (mq + i) * 80 + k * 2) = l;
        }
    };

    stageA(kbase, sm);
    cp_stage_B(Bhi, Blo, ldB, kbase, n0, smb, tid);
    asm volatile("cp.async.commit_group;");
    __syncthreads();

    float d[2][2][4] = {};
    for (int c = 0; c < nc; c++) {
        asm volatile("cp.async.wait_group 0;");
        __syncthreads();
        if (c + 1 < nc) {
            char* nbuf = sm + ((c + 1) & 1) * GBUF;
            stageA(kbase + (c + 1) * 32, nbuf);
            cp_stage_B(Bhi, Blo, ldB, kbase + (c + 1) * 32, n0, smb + ((c + 1) & 1) * GBUF, tid);
            asm volatile("cp.async.commit_group;");
        }
        mma_tile(smb + (c & 1) * GBUF, w, lane, d);
    }
    int mf = w & 3, ng = w >> 2;
    int tig = lane & 3, gid = lane >> 2;
    #pragma unroll
    for (int h = 0; h < 2; h++)
        #pragma unroll
        for (int f = 0; f < 2; f++) {
            int col = n0 + ng * 32 + h * 16 + f * 8 + 2 * tig;
            int row = mf * 16 + gid;
            atomicAdd(&C[(size_t)row * ldC + col],           alpha * d[h][f][0]);
            atomicAdd(&C[(size_t)row * ldC + col + 1],       alpha * d[h][f][1]);
            atomicAdd(&C[(size_t)(row + 8) * ldC + col],     alpha * d[h][f][2]);
            atomicAdd(&C[(size_t)(row + 8) * ldC + col + 1], alpha * d[h][f][3]);
        }
}

// Chi/Clo = split(relu(A@B + bias)), full K (A,B planes)
__global__ void __launch_bounds__(256) tgemm_pp_bias(
    const __nv_bfloat16* __restrict__ Ahi, const __nv_bfloat16* __restrict__ Alo, int ldA,
    const __nv_bfloat16* __restrict__ Bhi, const __nv_bfloat16* __restrict__ Blo, int ldB,
    const float* __restrict__ bias,
    __nv_bfloat16* __restrict__ Chi, __nv_bfloat16* __restrict__ Clo, int N, int K)
{
    __shared__ __align__(16) char sm[2 * GBUF];
    int tid = threadIdx.x, w = tid >> 5, lane = tid & 31;
    int n0 = blockIdx.x * 64, m0 = blockIdx.y * 64;
    uint32_t smb = smem_u32(sm);
    int nc = K / 32;

    cp_stage_A(Ahi, Alo, ldA, m0, 0, smb, tid);
    cp_stage_B(Bhi, Blo, ldB, 0, n0, smb, tid);
    asm volatile("cp.async.commit_group;");

    float d[2][2][4] = {};
    for (int c = 0; c < nc; c++) {
        asm volatile("cp.async.wait_group 0;");
        __syncthreads();
        if (c + 1 < nc) {
            uint32_t nb = smb + ((c + 1) & 1) * GBUF;
            cp_stage_A(Ahi, Alo, ldA, m0, (c + 1) * 32, nb, tid);
            cp_stage_B(Bhi, Blo, ldB, (c + 1) * 32, n0, nb, tid);
            asm volatile("cp.async.commit_group;");
        }
        mma_tile(smb + (c & 1) * GBUF, w, lane, d);
    }
    int mf = w & 3, ng = w >> 2;
    int tig = lane & 3, gid = lane >> 2;
    #pragma unroll
    for (int h = 0; h < 2; h++)
        #pragma unroll
        for (int f = 0; f < 2; f++) {
            int col = n0 + ng * 32 + h * 16 + f * 8 + 2 * tig;
            int row = m0 + mf * 16 + gid;
            #pragma unroll
            for (int e = 0; e < 4; e++) {
                int rr = row + (e >> 1) * 8;
                int cc = col + (e & 1);
                float v = fmaxf(d[h][f][e] + bias[cc], 0.0f);
                __nv_bfloat16 hh, ll;
                split_bf(v, hh, ll);
                Chi[(size_t)rr * N + cc] = hh;
                Clo[(size_t)rr * N + cc] = ll;
            }
        }
}

// ---------------- launch ----------------
extern "C" void kernel_launch(void* const* d_in, const int* in_sizes, int n_in,
                              void* d_out, int out_size)
{
    const float* data    = (const float*)d_in[0];
    const float* conv1_w = (const float*)d_in[1];
    const float* conv1_b = (const float*)d_in[2];
    const float* prim_w  = (const float*)d_in[3];
    const float* prim_b  = (const float*)d_in[4];
    const float* W_digit = (const float*)d_in[5];
    const float* dec1_w  = (const float*)d_in[6];
    const float* dec1_b  = (const float*)d_in[7];
    const float* dec2_w  = (const float*)d_in[8];
    const float* dec2_b  = (const float*)d_in[9];
    const float* dec3_w  = (const float*)d_in[10];
    const float* dec3_b  = (const float*)d_in[11];
    float* out = (float*)d_out;

    float *p_bij, *p_s, *p_GT, *p_v, *p_r;
    cudaGetSymbolAddress((void**)&p_bij, g_bij);
    cudaGetSymbolAddress((void**)&p_s,   g_s);
    cudaGetSymbolAddress((void**)&p_GT,  g_GT);
    cudaGetSymbolAddress((void**)&p_v,   g_v);
    cudaGetSymbolAddress((void**)&p_r,   g_r);

    __nv_bfloat16 *u_hi, *u_lo, *wct_hi, *wct_lo, *h0_hi, *h0_lo;
    __nv_bfloat16 *h1_hi, *h1_lo, *h2_hi, *h2_lo;
    __nv_bfloat16 *w1_hi, *w1_lo, *w2_hi, *w2_lo, *w3_hi, *w3_lo;
    cudaGetSymbolAddress((void**)&u_hi, g_u_hi);
    cudaGetSymbolAddress((void**)&u_lo, g_u_lo);
    cudaGetSymbolAddress((void**)&wct_hi, g_wct_hi);
    cudaGetSymbolAddress((void**)&wct_lo, g_wct_lo);
    cudaGetSymbolAddress((void**)&h0_hi, g_h0_hi);
    cudaGetSymbolAddress((void**)&h0_lo, g_h0_lo);
    cudaGetSymbolAddress((void**)&h1_hi, g_h1_hi);
    cudaGetSymbolAddress((void**)&h1_lo, g_h1_lo);
    cudaGetSymbolAddress((void**)&h2_hi, g_h2_hi);
    cudaGetSymbolAddress((void**)&h2_lo, g_h2_lo);
    cudaGetSymbolAddress((void**)&w1_hi, g_w1_hi);
    cudaGetSymbolAddress((void**)&w1_lo, g_w1_lo);
    cudaGetSymbolAddress((void**)&w2_hi, g_w2_hi);
    cudaGetSymbolAddress((void**)&w2_lo, g_w2_lo);
    cudaGetSymbolAddress((void**)&w3_hi, g_w3_hi);
    cudaGetSymbolAddress((void**)&w3_lo, g_w3_lo);

    static int smem_set = 0;
    if (!smem_set) {
        cudaFuncSetAttribute(conv_tc_kernel,
                             cudaFuncAttributeMaxDynamicSharedMemorySize, CONV_SMEM);
        smem_set = 1;
    }

    wb_split_kernel<<<576, 256>>>(prim_w);                             // 0
    split_kernel<<<128, 256>>>(dec1_w, w1_hi, w1_lo, 64 * 512);        // 1
    split_kernel<<<2048, 256>>>(dec2_w, w2_hi, w2_lo, 512 * 1024);     // 2
    conv_tc_kernel<<<BATCH, 512, CONV_SMEM>>>(data, conv1_w, conv1_b, prim_b);  // 3
    split_kernel<<<256, 256>>>(dec3_w, w3_hi, w3_lo, 1024 * 64);       // 4
    zero_kernel<<<4, 256>>>(p_bij, NR * 2);                            // 5

    for (int it = 0; it < 3; it++) {
        softmax_routes_kernel<<<1, 512>>>();
        build_wct_kernel<<<1024, 256>>>(W_digit);
        zero_kernel<<<1024, 256>>>(p_s, BATCH * 64);
        tgemm_pp_splitk<<<dim3(1, 64, 8), 256>>>(u_hi, u_lo, RI, wct_hi, wct_lo, 64,
                                                 p_s, 64, 512, 1.0f);
        squash_v_kernel<<<1024, 256>>>();
        if (it < 2) {
            zero_kernel<<<1024, 256>>>(p_GT, 64 * RI);
            tgemm_trv_splitk<<<dim3(64, 1, 8), 256>>>(p_v, u_hi, u_lo, RI,
                                                      p_GT, RI, 512, 1.0f / (float)BATCH);
            b_update_kernel<<<128, 256>>>(W_digit);
        }
    }

    mask_kernel<<<512, 256>>>(out);
    zero_kernel<<<1024, 256>>>(p_r, BATCH * 64);

    tgemm_pp_bias<<<dim3(8, 64), 256>>>(h0_hi, h0_lo, 64, w1_hi, w1_lo, 512,
                                        dec1_b, h1_hi, h1_lo, 512, 64);
    tgemm_pp_bias<<<dim3(16, 64), 256>>>(h1_hi, h1_lo, 512, w2_hi, w2_lo, 1024,
                                         dec2_b, h2_hi, h2_lo, 1024, 512);
    tgemm_pp_splitk<<<dim3(1, 64, 4), 256>>>(h2_hi, h2_lo, 1024, w3_hi, w3_lo, 64,
                                             p_r, 64, 256, 1.0f);
    sigmoid_bias_kernel<<<1024, 256>>>(dec3_b, out);
}

// round 14
// speedup vs baseline: 1.4282x; 1.1420x over previous
#include <cuda_runtime.h>
#include <cuda_bf16.h>
#include <math.h>
#include <stdint.h>

#define BATCH 4096
#define NR 512
#define RI 4096
#define OUT_REC_OFF 262144
#define OUT_MASK_OFF 524288

// conv-kernel SMEM (bytes): A planes 100pos x 136 bf16 (halo 10x10, 128ic+8pad), 2 planes
#define XROW2 136
#define PLANE2 27200
#define XT2_HI 0
#define XT2_LO 27200
#define BBUF2 54400
#define BPLANE 9216
#define BBUFSZ 18432
#define CONV_SMEM 91264

// pipelined GEMM staging: per buffer A 64x32 (pitch 80) hi/lo + B 32x64 (pitch 144) hi/lo
#define GAH 0
#define GAL 5120
#define GBH 10240
#define GBL 14848
#define GBUF 19456

// ---------------- device globals ----------------
__device__ __align__(16) __nv_bfloat16 g_wB_hi[2304 * 64];
__device__ __align__(16) __nv_bfloat16 g_wB_lo[2304 * 64];
__device__ __align__(16) __nv_bfloat16 g_u_hi[(size_t)BATCH * RI];
__device__ __align__(16) __nv_bfloat16 g_u_lo[(size_t)BATCH * RI];
__device__ __align__(16) __nv_bfloat16 g_wct_hi[RI * 64];
__device__ __align__(16) __nv_bfloat16 g_wct_lo[RI * 64];
__device__ __align__(16) __nv_bfloat16 g_h0_hi[BATCH * 64];
__device__ __align__(16) __nv_bfloat16 g_h0_lo[BATCH * 64];
__device__ __align__(16) __nv_bfloat16 g_h1_hi[(size_t)BATCH * 512];
__device__ __align__(16) __nv_bfloat16 g_h1_lo[(size_t)BATCH * 512];
__device__ __align__(16) __nv_bfloat16 g_h2_hi[(size_t)BATCH * 1024];
__device__ __align__(16) __nv_bfloat16 g_h2_lo[(size_t)BATCH * 1024];
__device__ __align__(16) __nv_bfloat16 g_w1_hi[64 * 512];
__device__ __align__(16) __nv_bfloat16 g_w1_lo[64 * 512];
__device__ __align__(16) __nv_bfloat16 g_w2_hi[512 * 1024];
__device__ __align__(16) __nv_bfloat16 g_w2_lo[512 * 1024];
__device__ __align__(16) __nv_bfloat16 g_w3_hi[1024 * 64];
__device__ __align__(16) __nv_bfloat16 g_w3_lo[1024 * 64];
__device__ float g_bij[NR * 2];
__device__ float g_c[NR * 2];
__device__ float g_s[BATCH * 64];
__device__ float g_v[BATCH * 64];
__device__ float g_GT[64 * RI];
__device__ float g_r[BATCH * 64];

// ---------------- helpers ----------------
__device__ __forceinline__ float warp_sum(float v) {
    #pragma unroll
    for (int s = 16; s > 0; s >>= 1) v += __shfl_xor_sync(0xFFFFFFFFu, v, s);
    return v;
}
__device__ __forceinline__ uint32_t smem_u32(const void* p) {
    return (uint32_t)__cvta_generic_to_shared(p);
}
__device__ __forceinline__ void ldsm_x4(uint32_t& r0, uint32_t& r1, uint32_t& r2, uint32_t& r3,
                                        uint32_t addr) {
    asm volatile("ldmatrix.sync.aligned.m8n8.x4.shared.b16 {%0,%1,%2,%3}, [%4];"
                 : "=r"(r0), "=r"(r1), "=r"(r2), "=r"(r3) : "r"(addr));
}
__device__ __forceinline__ void ldsm_x4_t(uint32_t& r0, uint32_t& r1, uint32_t& r2, uint32_t& r3,
                                          uint32_t addr) {
    asm volatile("ldmatrix.sync.aligned.m8n8.x4.trans.shared.b16 {%0,%1,%2,%3}, [%4];"
                 : "=r"(r0), "=r"(r1), "=r"(r2), "=r"(r3) : "r"(addr));
}
__device__ __forceinline__ void mma_bf16(float d[4], const uint32_t a[4],
                                         uint32_t b0, uint32_t b1) {
    asm volatile(
        "mma.sync.aligned.m16n8k16.row.col.f32.bf16.bf16.f32 "
        "{%0,%1,%2,%3}, {%4,%5,%6,%7}, {%8,%9}, {%0,%1,%2,%3};"
        : "+f"(d[0]), "+f"(d[1]), "+f"(d[2]), "+f"(d[3])
        : "r"(a[0]), "r"(a[1]), "r"(a[2]), "r"(a[3]), "r"(b0), "r"(b1));
}
__device__ __forceinline__ void cp_async16(uint32_t dst, const void* src) {
    asm volatile("cp.async.cg.shared.global [%0], [%1], 16;" :: "r"(dst), "l"(src) : "memory");
}
__device__ __forceinline__ void split_bf(float v, __nv_bfloat16& h, __nv_bfloat16& l) {
    h = __float2bfloat16(v);
    l = __float2bfloat16(v - __bfloat162float(h));
}
__device__ __forceinline__ uint32_t pk2bf(__nv_bfloat16 a, __nv_bfloat16 b) {
    return (uint32_t)__bfloat16_as_ushort(a) | ((uint32_t)__bfloat16_as_ushort(b) << 16);
}

// ---------------- basic kernels ----------------
__global__ void zero_kernel(float* p, int n) {
    int i = blockIdx.x * blockDim.x + threadIdx.x;
    if (i < n) p[i] = 0.0f;
}
__global__ void split_kernel(const float* __restrict__ src,
                             __nv_bfloat16* __restrict__ hi,
                             __nv_bfloat16* __restrict__ lo, int n) {
    int i = blockIdx.x * blockDim.x + threadIdx.x;
    if (i >= n) return;
    __nv_bfloat16 h, l;
    split_bf(src[i], h, l);
    hi[i] = h; lo[i] = l;
}
__global__ void wb_split_kernel(const float* __restrict__ pw) {
    int idx = blockIdx.x * blockDim.x + threadIdx.x;
    if (idx >= 147456) return;
    int k = idx >> 6, oc = idx & 63;
    int j = k >> 8, ic = k & 255;
    __nv_bfloat16 h, l;
    split_bf(pw[oc * 2304 + ic * 9 + j], h, l);
    g_wB_hi[idx] = h;
    g_wB_lo[idx] = l;
}

// ---------------- fused conv1 + bf16 3-term mma primary conv + squash --------
// one CTA per image, 512 threads, 2 CTAs/SM; ic processed in two halves of 128.
// warp = (mf = w&3, kg = w>>2); warp tile m16 x n64 over one k16 slice per chunk.
__global__ void __launch_bounds__(512, 2) conv_tc_kernel(
    const float* __restrict__ data, const float* __restrict__ w1,
    const float* __restrict__ b1, const float* __restrict__ pb)
{
    extern __shared__ char smem[];
    __shared__ float s_img[64];
    __nv_bfloat16* xhi = (__nv_bfloat16*)(smem + XT2_HI);
    __nv_bfloat16* xlo = (__nv_bfloat16*)(smem + XT2_LO);

    int b = blockIdx.x;
    int tid = threadIdx.x;
    int w = tid >> 5, lane = tid & 31;
    uint32_t sm_base = smem_u32(smem);

    // prefetch B chunk 0 (half 0, tap 0, kc 0)
    #pragma unroll
    for (int o = 0; o < 2; o++) {
        int idx = o * 512 + tid;
        int plane = idx >> 9, rem = idx & 511, r = rem >> 3, seg = rem & 7;
        const __nv_bfloat16* src = (plane ? g_wB_lo : g_wB_hi) + (size_t)r * 64 + seg * 8;
        cp_async16(sm_base + BBUF2 + plane * BPLANE + r * 144 + seg * 16, src);
    }
    asm volatile("cp.async.commit_group;");

    {   // zero both A planes (borders must be 0; written cells get overwritten)
        uint4 z = make_uint4(0, 0, 0, 0);
        uint4* p = (uint4*)smem;
        for (int i = tid; i < BBUF2 / 16; i += 512) p[i] = z;
    }
    if (tid < 64) s_img[tid] = data[b * 64 + tid];
    __syncthreads();

    int mf = w & 3, kg = w >> 2;
    int mloc = lane & 15, chalf = lane >> 4;
    int m = mf * 16 + mloc;
    int pbase = (m >> 3) * 10 + (m & 7);

    float d[8][4] = {};
    uint32_t xhi_u = sm_base + XT2_HI;
    const int lo_delta = XT2_LO - XT2_HI;

    for (int half = 0; half < 2; half++) {
        if (half == 1) __syncthreads();   // all warps done reading half-0 A planes

        {   // phase 1: conv1 for this half's 128 ic; thread = (icl, quarter)
            int icl = tid & 127, q = tid >> 7;
            int ic = half * 128 + icl;
            float wr[9];
            #pragma unroll
            for (int k = 0; k < 9; k++) wr[k] = w1[ic * 9 + k];
            float bias = b1[ic];
            #pragma unroll
            for (int yy = 0; yy < 2; yy++) {
                int y = q * 2 + yy;
                #pragma unroll
                for (int x = 0; x < 8; x++) {
                    float acc = bias;
                    #pragma unroll
                    for (int ky = 0; ky < 3; ky++) {
                        int iy = y + ky - 1;
                        if (iy < 0 || iy > 7) continue;
                        #pragma unroll
                        for (int kx = 0; kx < 3; kx++) {
                            int ix = x + kx - 1;
                            if (ix < 0 || ix > 7) continue;
                            acc += wr[ky * 3 + kx] * s_img[iy * 8 + ix];
                        }
                    }
                    acc = fmaxf(acc, 0.0f);
                    __nv_bfloat16 hi, lo;
                    split_bf(acc, hi, lo);
                    int p = (y + 1) * 10 + (x + 1);
                    xhi[p * XROW2 + icl] = hi;
                    xlo[p * XROW2 + icl] = lo;
                }
            }
        }

        for (int c = 0; c < 18; c++) {
            int cid = half * 18 + c;
            int buf = cid & 1;
            int j = c >> 1, kc = c & 1;
            int ky = j / 3, kx = j - ky * 3;

            asm volatile("cp.async.wait_group 0;");
            __syncthreads();   // B chunk ready; phase-1 writes visible

            if (cid + 1 < 36) {
                int nid = cid + 1;
                int nh = nid / 18, ncc = nid % 18;
                int krow0 = (ncc >> 1) * 256 + nh * 128 + (ncc & 1) * 64;
                #pragma unroll
                for (int o = 0; o < 2; o++) {
                    int idx = o * 512 + tid;
                    int plane = idx >> 9, rem = idx & 511, r = rem >> 3, seg = rem & 7;
                    const __nv_bfloat16* src =
                        (plane ? g_wB_lo : g_wB_hi) + (size_t)(krow0 + r) * 64 + seg * 8;
                    cp_async16(sm_base + BBUF2 + (buf ^ 1) * BBUFSZ + plane * BPLANE
                               + r * 144 + seg * 16, src);
                }
                asm volatile("cp.async.commit_group;");
            }

            uint32_t bbase = sm_base + BBUF2 + buf * BBUFSZ;
            int ashift = (pbase + ky * 10 + kx) * XROW2;
            int ic0 = kc * 64 + kg * 16;

            uint32_t ah[4], al[4];
            uint32_t aaddr = xhi_u + (uint32_t)(ashift + ic0 + chalf * 8) * 2u;
            ldsm_x4(ah[0], ah[1], ah[2], ah[3], aaddr);
            ldsm_x4(al[0], al[1], al[2], al[3], aaddr + lo_delta);
            uint32_t brow = bbase + (uint32_t)(kg * 16 + mloc) * 144u;
            #pragma unroll
            for (int c4 = 0; c4 < 4; c4++) {
                uint32_t bh[4], bl[4];
                uint32_t baddr = brow + (uint32_t)(c4 * 16 + chalf * 8) * 2u;
                ldsm_x4_t(bh[0], bh[1], bh[2], bh[3], baddr);
                ldsm_x4_t(bl[0], bl[1], bl[2], bl[3], baddr + BPLANE);
                mma_bf16(d[c4 * 2],     ah, bh[0], bh[1]);
                mma_bf16(d[c4 * 2 + 1], ah, bh[2], bh[3]);
                mma_bf16(d[c4 * 2],     ah, bl[0], bl[1]);
                mma_bf16(d[c4 * 2 + 1], ah, bl[2], bl[3]);
                mma_bf16(d[c4 * 2],     al, bh[0], bh[1]);
                mma_bf16(d[c4 * 2 + 1], al, bh[2], bh[3]);
            }
        }
    }

    // ---- cross-kg reduction into fp32 tile [64 pos][pitch 68] at smem+0 ----
    float* tile = (float*)smem;   // A planes dead
    int tig = lane & 3, gid = lane >> 2;
    #pragma unroll 1
    for (int g = 0; g < 4; g++) {
        __syncthreads();
        if (kg == g) {
            int r0 = mf * 16 + gid;
            #pragma unroll
            for (int f = 0; f < 8; f++) {
                int col = f * 8 + 2 * tig;
                if (g == 0) {
                    tile[r0 * 68 + col]           = d[f][0];
                    tile[r0 * 68 + col + 1]       = d[f][1];
                    tile[(r0 + 8) * 68 + col]     = d[f][2];
                    tile[(r0 + 8) * 68 + col + 1] = d[f][3];
                } else {
                    tile[r0 * 68 + col]           += d[f][0];
                    tile[r0 * 68 + col + 1]       += d[f][1];
                    tile[(r0 + 8) * 68 + col]     += d[f][2];
                    tile[(r0 + 8) * 68 + col + 1] += d[f][3];
                }
            }
        }
    }
    __syncthreads();

    // ---- epilogue: thread = (oc, y); bias + squash over x; vector store ----
    {
        int oc = tid & 63, y = tid >> 6;
        float bias = pb[oc];
        float xv[8];
        float q = 0.0f;
        #pragma unroll
        for (int x = 0; x < 8; x++) {
            float v = tile[(y * 8 + x) * 68 + oc] + bias;
            xv[x] = v;
            q += v * v;
        }
        float sc = q / ((1.0f + q) * sqrtf(q + 1e-9f));
        uint32_t hp[4], lp[4];
        #pragma unroll
        for (int p = 0; p < 4; p++) {
            __nv_bfloat16 h0, l0, h1, l1;
            split_bf(xv[2*p] * sc, h0, l0);
            split_bf(xv[2*p+1] * sc, h1, l1);
            hp[p] = pk2bf(h0, h1);
            lp[p] = pk2bf(l0, l1);
        }
        size_t idx = (size_t)b * RI + (size_t)(oc * 8 + y) * 8;
        *(uint4*)&g_u_hi[idx] = make_uint4(hp[0], hp[1], hp[2], hp[3]);
        *(uint4*)&g_u_lo[idx] = make_uint4(lp[0], lp[1], lp[2], lp[3]);
    }
}

// ---------------- routing small kernels ----------------
__global__ void softmax_routes_kernel() {
    __shared__ float red[512];
    int t = threadIdx.x;
    for (int o = 0; o < 2; o++) {
        float val = g_bij[t * 2 + o];
        red[t] = val; __syncthreads();
        for (int s = 256; s > 0; s >>= 1) {
            if (t < s) red[t] = fmaxf(red[t], red[t + s]);
            __syncthreads();
        }
        float mx = red[0]; __syncthreads();
        float e = expf(val - mx);
        red[t] = e; __syncthreads();
        for (int s = 256; s > 0; s >>= 1) {
            if (t < s) red[t] += red[t + s];
            __syncthreads();
        }
        float sum = red[0]; __syncthreads();
        g_c[t * 2 + o] = e / sum;
    }
}

__global__ void build_wct_kernel(const float* __restrict__ W) {
    int idx = blockIdx.x * blockDim.x + threadIdx.x;
    if (idx >= RI * 64) return;
    int od = idx & 63, ri = idx >> 6;
    int r = ri >> 3, i = ri & 7, o = od >> 5, dd = od & 31;
    float v = g_c[r * 2 + o] * W[((r * 2 + o) * 32 + dd) * 8 + i];
    __nv_bfloat16 h, l;
    split_bf(v, h, l);
    g_wct_hi[idx] = h;
    g_wct_lo[idx] = l;
}

__global__ void squash_v_kernel() {
    int gid = blockIdx.x * blockDim.x + threadIdx.x;
    int warp = gid >> 5, lane = gid & 31;
    if (warp >= BATCH * 2) return;
    int b = warp >> 1, o = warp & 1;
    float x = g_s[b * 64 + o * 32 + lane];
    float sq = warp_sum(x * x);
    float sc = sq / ((1.0f + sq) * sqrtf(sq + 1e-9f));
    g_v[b * 64 + o * 32 + lane] = x * sc;
}

__global__ void b_update_kernel(const float* __restrict__ W) {
    int gid = blockIdx.x * blockDim.x + threadIdx.x;
    int warp = gid >> 5, lane = gid & 31;
    if (warp >= NR * 2) return;
    int r = warp >> 1, o = warp & 1;
    float sum = 0.0f;
    for (int t = lane; t < 256; t += 32) {
        int dd = t >> 3, i = t & 7;
        sum += W[(r * 2 + o) * 256 + t] * g_GT[(o * 32 + dd) * RI + r * 8 + i];
    }
    sum = warp_sum(sum);
    if (lane == 0) g_bij[r * 2 + o] += sum;
}

__global__ void mask_kernel(float* __restrict__ out) {
    int gid = blockIdx.x * blockDim.x + threadIdx.x;
    int b = gid >> 5, lane = gid & 31;
    if (b >= BATCH) return;
    float v0 = g_v[b * 64 + lane];
    float v1 = g_v[b * 64 + 32 + lane];
    float n0 = warp_sum(v0 * v0);
    float n1 = warp_sum(v1 * v1);
    float m0 = (n1 > n0) ? 0.0f : 1.0f;
    float m1 = 1.0f - m0;
    out[b * 64 + lane] = v0;
    out[b * 64 + 32 + lane] = v1;
    if (lane == 0) {
        out[OUT_MASK_OFF + b * 2 + 0] = m0;
        out[OUT_MASK_OFF + b * 2 + 1] = m1;
    }
    __nv_bfloat16 h, l;
    split_bf(v0 * m0, h, l);
    g_h0_hi[b * 64 + lane] = h; g_h0_lo[b * 64 + lane] = l;
    split_bf(v1 * m1, h, l);
    g_h0_hi[b * 64 + 32 + lane] = h; g_h0_lo[b * 64 + 32 + lane] = l;
}

__global__ void sigmoid_bias_kernel(const float* __restrict__ bias, float* __restrict__ out) {
    int i = blockIdx.x * blockDim.x + threadIdx.x;
    if (i >= BATCH * 64) return;
    float v = g_r[i] + bias[i & 63];
    out[OUT_REC_OFF + i] = 1.0f / (1.0f + expf(-v));
}

// ---------------- pipelined plane-GEMM pieces ----------------
__device__ __forceinline__ void cp_stage_A(const __nv_bfloat16* hi, const __nv_bfloat16* lo,
                                           int ldA, int m0, int k0, uint32_t bufb, int tid) {
    #pragma unroll
    for (int q = 0; q < 2; q++) {
        int idx = q * 256 + tid;
        int plane = idx >> 8, rem = idx & 255;
        int row = rem >> 2, seg = rem & 3;
        const __nv_bfloat16* src = (plane ? lo : hi) + (size_t)(m0 + row) * ldA + k0 + seg * 8;
        cp_async16(bufb + (plane ? GAL : GAH) + row * 80 + seg * 16, src);
    }
}
__device__ __forceinline__ void cp_stage_B(const __nv_bfloat16* hi, const __nv_bfloat16* lo,
                                           int ldB, int k0, int n0, uint32_t bufb, int tid) {
    #pragma unroll
    for (int q = 0; q < 2; q++) {
        int idx = q * 256 + tid;
        int plane = idx >> 8, rem = idx & 255;
        int row = rem >> 3, seg = rem & 7;
        const __nv_bfloat16* src = (plane ? lo : hi) + (size_t)(k0 + row) * ldB + n0 + seg * 8;
        cp_async16(bufb + (plane ? GBL : GBH) + row * 144 + seg * 16, src);
    }
}
__device__ __forceinline__ void mma_tile(uint32_t bufb, int w, int lane, float (&d)[2][2][4]) {
    int mf = w & 3, ng = w >> 2;
    int mloc = lane & 15, chalf = lane >> 4;
    #pragma unroll
    for (int ks = 0; ks < 2; ks++) {
        uint32_t ah[4], al[4];
        uint32_t aaddr = bufb + GAH + (uint32_t)((mf * 16 + mloc) * 80 + (ks * 16 + chalf * 8) * 2);
        ldsm_x4(ah[0], ah[1], ah[2], ah[3], aaddr);
        ldsm_x4(al[0], al[1], al[2], al[3], aaddr + (GAL - GAH));
        #pragma unroll
        for (int h = 0; h < 2; h++) {
            uint32_t bh[4], bl[4];
            uint32_t baddr = bufb + GBH
                + (uint32_t)((ks * 16 + mloc) * 144 + (ng * 32 + h * 16 + chalf * 8) * 2);
            ldsm_x4_t(bh[0], bh[1], bh[2], bh[3], baddr);
            ldsm_x4_t(bl[0], bl[1], bl[2], bl[3], baddr + (GBL - GBH));
            mma_bf16(d[h][0], ah, bh[0], bh[1]);
            mma_bf16(d[h][1], ah, bh[2], bh[3]);
            mma_bf16(d[h][0], ah, bl[0], bl[1]);
            mma_bf16(d[h][1], ah, bl[2], bl[3]);
            mma_bf16(d[h][0], al, bh[0], bh[1]);
            mma_bf16(d[h][1], al, bh[2], bh[3]);
        }
    }
}

// C += alpha * A@B  (A,B prestaged planes), split-K atomic
__global__ void __launch_bounds__(256) tgemm_pp_splitk(
    const __nv_bfloat16* __restrict__ Ahi, const __nv_bfloat16* __restrict__ Alo, int ldA,
    const __nv_bfloat16* __restrict__ Bhi, const __nv_bfloat16* __restrict__ Blo, int ldB,
    float* __restrict__ C, int ldC, int Kchunk, float alpha)
{
    __shared__ __align__(16) char sm[2 * GBUF];
    int tid = threadIdx.x, w = tid >> 5, lane = tid & 31;
    int n0 = blockIdx.x * 64, m0 = blockIdx.y * 64, kbase = blockIdx.z * Kchunk;
    uint32_t smb = smem_u32(sm);
    int nc = Kchunk / 32;

    cp_stage_A(Ahi, Alo, ldA, m0, kbase, smb, tid);
    cp_stage_B(Bhi, Blo, ldB, kbase, n0, smb, tid);
    asm volatile("cp.async.commit_group;");

    float d[2][2][4] = {};
    for (int c = 0; c < nc; c++) {
        asm volatile("cp.async.wait_group 0;");
        __syncthreads();
        if (c + 1 < nc) {
            uint32_t nb = smb + ((c + 1) & 1) * GBUF;
            cp_stage_A(Ahi, Alo, ldA, m0, kbase + (c + 1) * 32, nb, tid);
            cp_stage_B(Bhi, Blo, ldB, kbase + (c + 1) * 32, n0, nb, tid);
            asm volatile("cp.async.commit_group;");
        }
        mma_tile(smb + (c & 1) * GBUF, w, lane, d);
    }
    int mf = w & 3, ng = w >> 2;
    int tig = lane & 3, gid = lane >> 2;
    #pragma unroll
    for (int h = 0; h < 2; h++)
        #pragma unroll
        for (int f = 0; f < 2; f++) {
            int col = n0 + ng * 32 + h * 16 + f * 8 + 2 * tig;
            int row = m0 + mf * 16 + gid;
            atomicAdd(&C[(size_t)row * ldC + col],           alpha * d[h][f][0]);
            atomicAdd(&C[(size_t)row * ldC + col + 1],       alpha * d[h][f][1]);
            atomicAdd(&C[(size_t)(row + 8) * ldC + col],     alpha * d[h][f][2]);
            atomicAdd(&C[(size_t)(row + 8) * ldC + col + 1], alpha * d[h][f][3]);
        }
}

// GT += alpha * V^T @ B  (V fp32 [K][64] scalar-staged; B planes), split-K atomic
__global__ void __launch_bounds__(256) tgemm_trv_splitk(
    const float* __restrict__ V,
    const __nv_bfloat16* __restrict__ Bhi, const __nv_bfloat16* __restrict__ Blo, int ldB,
    float* __restrict__ C, int ldC, int Kchunk, float alpha)
{
    __shared__ __align__(16) char sm[2 * GBUF];
    int tid = threadIdx.x, w = tid >> 5, lane = tid & 31;
    int n0 = blockIdx.x * 64, kbase = blockIdx.z * Kchunk;
    uint32_t smb = smem_u32(sm);
    int nc = Kchunk / 32;

    auto stageA = [&](int k0, char* buf) {
        int k = tid >> 3, mq = (tid & 7) * 8;
        const float* p = V + (size_t)(k0 + k) * 64 + mq;
        float4 f0 = *(const float4*)p, f1 = *(const float4*)(p + 4);
        float fa[8] = {f0.x, f0.y, f0.z, f0.w, f1.x, f1.y, f1.z, f1.w};
        #pragma unroll
        for (int i = 0; i < 8; i++) {
            __nv_bfloat16 h, l;
            split_bf(fa[i], h, l);
            *(__nv_bfloat16*)(buf + GAH + (mq + i) * 80 + k * 2) = h;
            *(__nv_bfloat16*)(buf + GAL + (mq + i) * 80 + k * 2) = l;
        }
    };

    stageA(kbase, sm);
    cp_stage_B(Bhi, Blo, ldB, kbase, n0, smb, tid);
    asm volatile("cp.async.commit_group;");
    __syncthreads();

    float d[2][2][4] = {};
    for (int c = 0; c < nc; c++) {
        asm volatile("cp.async.wait_group 0;");
        __syncthreads();
        if (c + 1 < nc) {
            char* nbuf = sm + ((c + 1) & 1) * GBUF;
            stageA(kbase + (c + 1) * 32, nbuf);
            cp_stage_B(Bhi, Blo, ldB, kbase + (c + 1) * 32, n0, smb + ((c + 1) & 1) * GBUF, tid);
            asm volatile("cp.async.commit_group;");
        }
        mma_tile(smb + (c & 1) * GBUF, w, lane, d);
    }
    int mf = w & 3, ng = w >> 2;
    int tig = lane & 3, gid = lane >> 2;
    #pragma unroll
    for (int h = 0; h < 2; h++)
        #pragma unroll
        for (int f = 0; f < 2; f++) {
            int col = n0 + ng * 32 + h * 16 + f * 8 + 2 * tig;
            int row = mf * 16 + gid;
            atomicAdd(&C[(size_t)row * ldC + col],           alpha * d[h][f][0]);
            atomicAdd(&C[(size_t)row * ldC + col + 1],       alpha * d[h][f][1]);
            atomicAdd(&C[(size_t)(row + 8) * ldC + col],     alpha * d[h][f][2]);
            atomicAdd(&C[(size_t)(row + 8) * ldC + col + 1], alpha * d[h][f][3]);
        }
}

// Chi/Clo = split(relu(A@B + bias)), full K (A,B planes)
__global__ void __launch_bounds__(256) tgemm_pp_bias(
    const __nv_bfloat16* __restrict__ Ahi, const __nv_bfloat16* __restrict__ Alo, int ldA,
    const __nv_bfloat16* __restrict__ Bhi, const __nv_bfloat16* __restrict__ Blo, int ldB,
    const float* __restrict__ bias,
    __nv_bfloat16* __restrict__ Chi, __nv_bfloat16* __restrict__ Clo, int N, int K)
{
    __shared__ __align__(16) char sm[2 * GBUF];
    int tid = threadIdx.x, w = tid >> 5, lane = tid & 31;
    int n0 = blockIdx.x * 64, m0 = blockIdx.y * 64;
    uint32_t smb = smem_u32(sm);
    int nc = K / 32;

    cp_stage_A(Ahi, Alo, ldA, m0, 0, smb, tid);
    cp_stage_B(Bhi, Blo, ldB, 0, n0, smb, tid);
    asm volatile("cp.async.commit_group;");

    float d[2][2][4] = {};
    for (int c = 0; c < nc; c++) {
        asm volatile("cp.async.wait_group 0;");
        __syncthreads();
        if (c + 1 < nc) {
            uint32_t nb = smb + ((c + 1) & 1) * GBUF;
            cp_stage_A(Ahi, Alo, ldA, m0, (c + 1) * 32, nb, tid);
            cp_stage_B(Bhi, Blo, ldB, (c + 1) * 32, n0, nb, tid);
            asm volatile("cp.async.commit_group;");
        }
        mma_tile(smb + (c & 1) * GBUF, w, lane, d);
    }
    int mf = w & 3, ng = w >> 2;
    int tig = lane & 3, gid = lane >> 2;
    #pragma unroll
    for (int h = 0; h < 2; h++)
        #pragma unroll
        for (int f = 0; f < 2; f++) {
            int col = n0 + ng * 32 + h * 16 + f * 8 + 2 * tig;
            int row = m0 + mf * 16 + gid;
            #pragma unroll
            for (int e = 0; e < 4; e++) {
                int rr = row + (e >> 1) * 8;
                int cc = col + (e & 1);
                float v = fmaxf(d[h][f][e] + bias[cc], 0.0f);
                __nv_bfloat16 hh, ll;
                split_bf(v, hh, ll);
                Chi[(size_t)rr * N + cc] = hh;
                Clo[(size_t)rr * N + cc] = ll;
            }
        }
}

// ---------------- launch ----------------
extern "C" void kernel_launch(void* const* d_in, const int* in_sizes, int n_in,
                              void* d_out, int out_size)
{
    const float* data    = (const float*)d_in[0];
    const float* conv1_w = (const float*)d_in[1];
    const float* conv1_b = (const float*)d_in[2];
    const float* prim_w  = (const float*)d_in[3];
    const float* prim_b  = (const float*)d_in[4];
    const float* W_digit = (const float*)d_in[5];
    const float* dec1_w  = (const float*)d_in[6];
    const float* dec1_b  = (const float*)d_in[7];
    const float* dec2_w  = (const float*)d_in[8];
    const float* dec2_b  = (const float*)d_in[9];
    const float* dec3_w  = (const float*)d_in[10];
    const float* dec3_b  = (const float*)d_in[11];
    float* out = (float*)d_out;

    float *p_bij, *p_s, *p_GT, *p_v, *p_r;
    cudaGetSymbolAddress((void**)&p_bij, g_bij);
    cudaGetSymbolAddress((void**)&p_s,   g_s);
    cudaGetSymbolAddress((void**)&p_GT,  g_GT);
    cudaGetSymbolAddress((void**)&p_v,   g_v);
    cudaGetSymbolAddress((void**)&p_r,   g_r);

    __nv_bfloat16 *u_hi, *u_lo, *wct_hi, *wct_lo, *h0_hi, *h0_lo;
    __nv_bfloat16 *h1_hi, *h1_lo, *h2_hi, *h2_lo;
    __nv_bfloat16 *w1_hi, *w1_lo, *w2_hi, *w2_lo, *w3_hi, *w3_lo;
    cudaGetSymbolAddress((void**)&u_hi, g_u_hi);
    cudaGetSymbolAddress((void**)&u_lo, g_u_lo);
    cudaGetSymbolAddress((void**)&wct_hi, g_wct_hi);
    cudaGetSymbolAddress((void**)&wct_lo, g_wct_lo);
    cudaGetSymbolAddress((void**)&h0_hi, g_h0_hi);
    cudaGetSymbolAddress((void**)&h0_lo, g_h0_lo);
    cudaGetSymbolAddress((void**)&h1_hi, g_h1_hi);
    cudaGetSymbolAddress((void**)&h1_lo, g_h1_lo);
    cudaGetSymbolAddress((void**)&h2_hi, g_h2_hi);
    cudaGetSymbolAddress((void**)&h2_lo, g_h2_lo);
    cudaGetSymbolAddress((void**)&w1_hi, g_w1_hi);
    cudaGetSymbolAddress((void**)&w1_lo, g_w1_lo);
    cudaGetSymbolAddress((void**)&w2_hi, g_w2_hi);
    cudaGetSymbolAddress((void**)&w2_lo, g_w2_lo);
    cudaGetSymbolAddress((void**)&w3_hi, g_w3_hi);
    cudaGetSymbolAddress((void**)&w3_lo, g_w3_lo);

    static int smem_set = 0;
    if (!smem_set) {
        cudaFuncSetAttribute(conv_tc_kernel,
                             cudaFuncAttributeMaxDynamicSharedMemorySize, CONV_SMEM);
        smem_set = 1;
    }

    wb_split_kernel<<<576, 256>>>(prim_w);                             // 0
    split_kernel<<<128, 256>>>(dec1_w, w1_hi, w1_lo, 64 * 512);        // 1
    split_kernel<<<2048, 256>>>(dec2_w, w2_hi, w2_lo, 512 * 1024);     // 2
    conv_tc_kernel<<<BATCH, 512, CONV_SMEM>>>(data, conv1_w, conv1_b, prim_b);  // 3
    split_kernel<<<256, 256>>>(dec3_w, w3_hi, w3_lo, 1024 * 64);       // 4
    zero_kernel<<<4, 256>>>(p_bij, NR * 2);                            // 5

    for (int it = 0; it < 3; it++) {
        softmax_routes_kernel<<<1, 512>>>();
        build_wct_kernel<<<1024, 256>>>(W_digit);
        zero_kernel<<<1024, 256>>>(p_s, BATCH * 64);
        tgemm_pp_splitk<<<dim3(1, 64, 8), 256>>>(u_hi, u_lo, RI, wct_hi, wct_lo, 64,
                                                 p_s, 64, 512, 1.0f);
        squash_v_kernel<<<1024, 256>>>();
        if (it < 2) {
            zero_kernel<<<1024, 256>>>(p_GT, 64 * RI);
            tgemm_trv_splitk<<<dim3(64, 1, 8), 256>>>(p_v, u_hi, u_lo, RI,
                                                      p_GT, RI, 512, 1.0f / (float)BATCH);
            b_update_kernel<<<128, 256>>>(W_digit);
        }
    }

    mask_kernel<<<512, 256>>>(out);
    zero_kernel<<<1024, 256>>>(p_r, BATCH * 64);

    tgemm_pp_bias<<<dim3(8, 64), 256>>>(h0_hi, h0_lo, 64, w1_hi, w1_lo, 512,
                                        dec1_b, h1_hi, h1_lo, 512, 64);
    tgemm_pp_bias<<<dim3(16, 64), 256>>>(h1_hi, h1_lo, 512, w2_hi, w2_lo, 1024,
                                         dec2_b, h2_hi, h2_lo, 1024, 512);
    tgemm_pp_splitk<<<dim3(1, 64, 4), 256>>>(h2_hi, h2_lo, 1024, w3_hi, w3_lo, 64,
                                             p_r, 64, 256, 1.0f);
    sigmoid_bias_kernel<<<1024, 256>>>(dec3_b, out);
}

// round 15
// speedup vs baseline: 1.4731x; 1.0314x over previous
#include <cuda_runtime.h>
#include <cuda_bf16.h>
#include <math.h>
#include <stdint.h>

#define BATCH 4096
#define NR 512
#define RI 4096
#define OUT_REC_OFF 262144
#define OUT_MASK_OFF 524288

// conv-kernel SMEM (bytes): A planes 100pos x 136 bf16 (halo 10x10, 128ic+8pad), 2 planes
#define XROW2 136
#define XT2_HI 0
#define XT2_LO 27200
#define BBUF2 54400
#define BPLANE 9216
#define BBUFSZ 18432
#define CONV_SMEM 91264

// pipelined GEMM staging: per buffer A 64x32 (pitch 80) hi/lo + B 32x64 (pitch 144) hi/lo
#define GAH 0
#define GAL 5120
#define GBH 10240
#define GBL 14848
#define GBUF 19456

// ---------------- device globals ----------------
__device__ __align__(16) __nv_bfloat16 g_wB_hi[2304 * 64];
__device__ __align__(16) __nv_bfloat16 g_wB_lo[2304 * 64];
__device__ __align__(16) __nv_bfloat16 g_u_hi[(size_t)BATCH * RI];
__device__ __align__(16) __nv_bfloat16 g_u_lo[(size_t)BATCH * RI];
__device__ __align__(16) __nv_bfloat16 g_wct_hi[RI * 64];
__device__ __align__(16) __nv_bfloat16 g_wct_lo[RI * 64];
__device__ __align__(16) __nv_bfloat16 g_h0_hi[BATCH * 64];
__device__ __align__(16) __nv_bfloat16 g_h0_lo[BATCH * 64];
__device__ __align__(16) __nv_bfloat16 g_h1_hi[(size_t)BATCH * 512];
__device__ __align__(16) __nv_bfloat16 g_h1_lo[(size_t)BATCH * 512];
__device__ __align__(16) __nv_bfloat16 g_h2_hi[(size_t)BATCH * 1024];
__device__ __align__(16) __nv_bfloat16 g_h2_lo[(size_t)BATCH * 1024];
__device__ __align__(16) __nv_bfloat16 g_w1_hi[64 * 512];
__device__ __align__(16) __nv_bfloat16 g_w1_lo[64 * 512];
__device__ __align__(16) __nv_bfloat16 g_w2_hi[512 * 1024];
__device__ __align__(16) __nv_bfloat16 g_w2_lo[512 * 1024];
__device__ __align__(16) __nv_bfloat16 g_w3_hi[1024 * 64];
__device__ __align__(16) __nv_bfloat16 g_w3_lo[1024 * 64];
__device__ float g_bij[NR * 2];
__device__ float g_s[BATCH * 64];
__device__ float g_v[BATCH * 64];
__device__ float g_GT[64 * RI];
__device__ float g_r[BATCH * 64];

// ---------------- helpers ----------------
__device__ __forceinline__ float warp_sum(float v) {
    #pragma unroll
    for (int s = 16; s > 0; s >>= 1) v += __shfl_xor_sync(0xFFFFFFFFu, v, s);
    return v;
}
__device__ __forceinline__ uint32_t smem_u32(const void* p) {
    return (uint32_t)__cvta_generic_to_shared(p);
}
__device__ __forceinline__ void ldsm_x4(uint32_t& r0, uint32_t& r1, uint32_t& r2, uint32_t& r3,
                                        uint32_t addr) {
    asm volatile("ldmatrix.sync.aligned.m8n8.x4.shared.b16 {%0,%1,%2,%3}, [%4];"
                 : "=r"(r0), "=r"(r1), "=r"(r2), "=r"(r3) : "r"(addr));
}
__device__ __forceinline__ void ldsm_x4_t(uint32_t& r0, uint32_t& r1, uint32_t& r2, uint32_t& r3,
                                          uint32_t addr) {
    asm volatile("ldmatrix.sync.aligned.m8n8.x4.trans.shared.b16 {%0,%1,%2,%3}, [%4];"
                 : "=r"(r0), "=r"(r1), "=r"(r2), "=r"(r3) : "r"(addr));
}
__device__ __forceinline__ void mma_bf16(float d[4], const uint32_t a[4],
                                         uint32_t b0, uint32_t b1) {
    asm volatile(
        "mma.sync.aligned.m16n8k16.row.col.f32.bf16.bf16.f32 "
        "{%0,%1,%2,%3}, {%4,%5,%6,%7}, {%8,%9}, {%0,%1,%2,%3};"
        : "+f"(d[0]), "+f"(d[1]), "+f"(d[2]), "+f"(d[3])
        : "r"(a[0]), "r"(a[1]), "r"(a[2]), "r"(a[3]), "r"(b0), "r"(b1));
}
__device__ __forceinline__ void cp_async16(uint32_t dst, const void* src) {
    asm volatile("cp.async.cg.shared.global [%0], [%1], 16;" :: "r"(dst), "l"(src) : "memory");
}
__device__ __forceinline__ void split_bf(float v, __nv_bfloat16& h, __nv_bfloat16& l) {
    h = __float2bfloat16(v);
    l = __float2bfloat16(v - __bfloat162float(h));
}
__device__ __forceinline__ uint32_t pk2bf(__nv_bfloat16 a, __nv_bfloat16 b) {
    return (uint32_t)__bfloat16_as_ushort(a) | ((uint32_t)__bfloat16_as_ushort(b) << 16);
}

// ---------------- basic kernels ----------------
__global__ void zero_kernel(float* p, int n) {
    int i = blockIdx.x * blockDim.x + threadIdx.x;
    if (i < n) p[i] = 0.0f;
}
__global__ void split_kernel(const float* __restrict__ src,
                             __nv_bfloat16* __restrict__ hi,
                             __nv_bfloat16* __restrict__ lo, int n) {
    int i = blockIdx.x * blockDim.x + threadIdx.x;
    if (i >= n) return;
    __nv_bfloat16 h, l;
    split_bf(src[i], h, l);
    hi[i] = h; lo[i] = l;
}
__global__ void wb_split_kernel(const float* __restrict__ pw) {
    int idx = blockIdx.x * blockDim.x + threadIdx.x;
    if (idx >= 147456) return;
    int k = idx >> 6, oc = idx & 63;
    int j = k >> 8, ic = k & 255;
    __nv_bfloat16 h, l;
    split_bf(pw[oc * 2304 + ic * 9 + j], h, l);
    g_wB_hi[idx] = h;
    g_wB_lo[idx] = l;
}

// ---------------- fused conv1 + bf16 3-term mma primary conv + squash --------
// one CTA per image, 512 threads, 2 CTAs/SM; ic in two halves of 128.
// warp = (kg = w&3, q = w>>2); warp tile m32 x n32 for its k16 slice per chunk.
__global__ void __launch_bounds__(512, 2) conv_tc_kernel(
    const float* __restrict__ data, const float* __restrict__ w1,
    const float* __restrict__ b1, const float* __restrict__ pb)
{
    extern __shared__ char smem[];
    __shared__ float s_img[64];
    __nv_bfloat16* xhi = (__nv_bfloat16*)(smem + XT2_HI);
    __nv_bfloat16* xlo = (__nv_bfloat16*)(smem + XT2_LO);

    int b = blockIdx.x;
    int tid = threadIdx.x;
    int w = tid >> 5, lane = tid & 31;
    uint32_t sm_base = smem_u32(smem);

    // prefetch B chunk 0 (half 0, tap 0, kc 0)
    #pragma unroll
    for (int o = 0; o < 2; o++) {
        int idx = o * 512 + tid;
        int plane = idx >> 9, rem = idx & 511, r = rem >> 3, seg = rem & 7;
        const __nv_bfloat16* src = (plane ? g_wB_lo : g_wB_hi) + (size_t)r * 64 + seg * 8;
        cp_async16(sm_base + BBUF2 + plane * BPLANE + r * 144 + seg * 16, src);
    }
    asm volatile("cp.async.commit_group;");

    {   // zero both A planes
        uint4 z = make_uint4(0, 0, 0, 0);
        uint4* p = (uint4*)smem;
        for (int i = tid; i < BBUF2 / 16; i += 512) p[i] = z;
    }
    if (tid < 64) s_img[tid] = data[b * 64 + tid];
    __syncthreads();

    int kg = w & 3, q = w >> 2;
    int mq = q & 1, nq = q >> 1;
    int mloc = lane & 15, chalf = lane >> 4;
    int mA0 = mq * 32 + mloc;
    int mA1 = mA0 + 16;
    int pbase0 = (mA0 >> 3) * 10 + (mA0 & 7);
    int pbase1 = (mA1 >> 3) * 10 + (mA1 & 7);

    float d[2][4][4] = {};
    uint32_t xhi_u = sm_base + XT2_HI;
    const int lo_delta = XT2_LO - XT2_HI;

    for (int half = 0; half < 2; half++) {
        if (half == 1) __syncthreads();   // all warps done reading half-0 A planes

        {   // phase 1: conv1 for this half's 128 ic; thread = (icl, quarter)
            int icl = tid & 127, qq = tid >> 7;
            int ic = half * 128 + icl;
            float wr[9];
            #pragma unroll
            for (int k = 0; k < 9; k++) wr[k] = w1[ic * 9 + k];
            float bias = b1[ic];
            #pragma unroll
            for (int yy = 0; yy < 2; yy++) {
                int y = qq * 2 + yy;
                #pragma unroll
                for (int x = 0; x < 8; x++) {
                    float acc = bias;
                    #pragma unroll
                    for (int ky = 0; ky < 3; ky++) {
                        int iy = y + ky - 1;
                        if (iy < 0 || iy > 7) continue;
                        #pragma unroll
                        for (int kx = 0; kx < 3; kx++) {
                            int ix = x + kx - 1;
                            if (ix < 0 || ix > 7) continue;
                            acc += wr[ky * 3 + kx] * s_img[iy * 8 + ix];
                        }
                    }
                    acc = fmaxf(acc, 0.0f);
                    __nv_bfloat16 hi, lo;
                    split_bf(acc, hi, lo);
                    int p = (y + 1) * 10 + (x + 1);
                    xhi[p * XROW2 + icl] = hi;
                    xlo[p * XROW2 + icl] = lo;
                }
            }
        }

        for (int c = 0; c < 18; c++) {
            int cid = half * 18 + c;
            int buf = cid & 1;
            int j = c >> 1, kc = c & 1;
            int ky = j / 3, kx = j - ky * 3;

            asm volatile("cp.async.wait_group 0;");
            __syncthreads();   // B chunk ready; phase-1 writes visible

            if (cid + 1 < 36) {
                int nid = cid + 1;
                int nh = nid / 18, ncc = nid % 18;
                int krow0 = (ncc >> 1) * 256 + nh * 128 + (ncc & 1) * 64;
                #pragma unroll
                for (int o = 0; o < 2; o++) {
                    int idx = o * 512 + tid;
                    int plane = idx >> 9, rem = idx & 511, r = rem >> 3, seg = rem & 7;
                    const __nv_bfloat16* src =
                        (plane ? g_wB_lo : g_wB_hi) + (size_t)(krow0 + r) * 64 + seg * 8;
                    cp_async16(sm_base + BBUF2 + (buf ^ 1) * BBUFSZ + plane * BPLANE
                               + r * 144 + seg * 16, src);
                }
                asm volatile("cp.async.commit_group;");
            }

            uint32_t bbase = sm_base + BBUF2 + buf * BBUFSZ;
            int toff = (ky * 10 + kx) * XROW2;
            int ic0 = kc * 64 + kg * 16;

            uint32_t a0 = xhi_u + (uint32_t)(pbase0 * XROW2 + toff + ic0 + chalf * 8) * 2u;
            uint32_t a1 = xhi_u + (uint32_t)(pbase1 * XROW2 + toff + ic0 + chalf * 8) * 2u;
            uint32_t ah0[4], al0[4], ah1[4], al1[4];
            ldsm_x4(ah0[0], ah0[1], ah0[2], ah0[3], a0);
            ldsm_x4(al0[0], al0[1], al0[2], al0[3], a0 + lo_delta);
            ldsm_x4(ah1[0], ah1[1], ah1[2], ah1[3], a1);
            ldsm_x4(al1[0], al1[1], al1[2], al1[3], a1 + lo_delta);

            uint32_t brow = bbase + (uint32_t)(kg * 16 + mloc) * 144u
                          + (uint32_t)(nq * 32 + chalf * 8) * 2u;
            #pragma unroll
            for (int g16 = 0; g16 < 2; g16++) {
                uint32_t bh[4], bl[4];
                uint32_t baddr = brow + g16 * 32;
                ldsm_x4_t(bh[0], bh[1], bh[2], bh[3], baddr);
                ldsm_x4_t(bl[0], bl[1], bl[2], bl[3], baddr + BPLANE);
                int n0j = g16 * 2, n1j = g16 * 2 + 1;
                mma_bf16(d[0][n0j], ah0, bh[0], bh[1]);
                mma_bf16(d[0][n1j], ah0, bh[2], bh[3]);
                mma_bf16(d[1][n0j], ah1, bh[0], bh[1]);
                mma_bf16(d[1][n1j], ah1, bh[2], bh[3]);
                mma_bf16(d[0][n0j], ah0, bl[0], bl[1]);
                mma_bf16(d[0][n1j], ah0, bl[2], bl[3]);
                mma_bf16(d[1][n0j], ah1, bl[0], bl[1]);
                mma_bf16(d[1][n1j], ah1, bl[2], bl[3]);
                mma_bf16(d[0][n0j], al0, bh[0], bh[1]);
                mma_bf16(d[0][n1j], al0, bh[2], bh[3]);
                mma_bf16(d[1][n0j], al1, bh[0], bh[1]);
                mma_bf16(d[1][n1j], al1, bh[2], bh[3]);
            }
        }
    }

    // ---- cross-kg reduction into fp32 tile [64 pos][pitch 68] at smem+0 ----
    float* tile = (float*)smem;   // A planes dead
    int tig = lane & 3, gid = lane >> 2;
    #pragma unroll 1
    for (int g = 0; g < 4; g++) {
        __syncthreads();
        if (kg == g) {
            #pragma unroll
            for (int mi = 0; mi < 2; mi++) {
                int r0 = mq * 32 + mi * 16 + gid;
                #pragma unroll
                for (int nj = 0; nj < 4; nj++) {
                    int col = nq * 32 + nj * 8 + 2 * tig;
                    if (g == 0) {
                        tile[r0 * 68 + col]           = d[mi][nj][0];
                        tile[r0 * 68 + col + 1]       = d[mi][nj][1];
                        tile[(r0 + 8) * 68 + col]     = d[mi][nj][2];
                        tile[(r0 + 8) * 68 + col + 1] = d[mi][nj][3];
                    } else {
                        tile[r0 * 68 + col]           += d[mi][nj][0];
                        tile[r0 * 68 + col + 1]       += d[mi][nj][1];
                        tile[(r0 + 8) * 68 + col]     += d[mi][nj][2];
                        tile[(r0 + 8) * 68 + col + 1] += d[mi][nj][3];
                    }
                }
            }
        }
    }
    __syncthreads();

    // ---- epilogue: thread = (oc, y); bias + squash over x; vector store ----
    {
        int oc = tid & 63, y = tid >> 6;
        float bias = pb[oc];
        float xv[8];
        float qn = 0.0f;
        #pragma unroll
        for (int x = 0; x < 8; x++) {
            float v = tile[(y * 8 + x) * 68 + oc] + bias;
            xv[x] = v;
            qn += v * v;
        }
        float sc = qn / ((1.0f + qn) * sqrtf(qn + 1e-9f));
        uint32_t hp[4], lp[4];
        #pragma unroll
        for (int p = 0; p < 4; p++) {
            __nv_bfloat16 h0, l0, h1, l1;
            split_bf(xv[2*p] * sc, h0, l0);
            split_bf(xv[2*p+1] * sc, h1, l1);
            hp[p] = pk2bf(h0, h1);
            lp[p] = pk2bf(l0, l1);
        }
        size_t idx = (size_t)b * RI + (size_t)(oc * 8 + y) * 8;
        *(uint4*)&g_u_hi[idx] = make_uint4(hp[0], hp[1], hp[2], hp[3]);
        *(uint4*)&g_u_lo[idx] = make_uint4(lp[0], lp[1], lp[2], lp[3]);
    }
}

// ---------------- routing small kernels ----------------
// build_wct with inline softmax over routes (axis 0)
__global__ void build_wct_kernel(const float* __restrict__ W) {
    __shared__ float red[256];
    __shared__ float c_s[NR * 2];
    int tid = threadIdx.x;
    #pragma unroll
    for (int o = 0; o < 2; o++) {
        float mx = -1e30f;
        for (int r = tid; r < NR; r += 256) mx = fmaxf(mx, g_bij[r * 2 + o]);
        red[tid] = mx; __syncthreads();
        for (int s = 128; s > 0; s >>= 1) {
            if (tid < s) red[tid] = fmaxf(red[tid], red[tid + s]);
            __syncthreads();
        }
        mx = red[0]; __syncthreads();
        float sum = 0.0f;
        for (int r = tid; r < NR; r += 256) sum += expf(g_bij[r * 2 + o] - mx);
        red[tid] = sum; __syncthreads();
        for (int s = 128; s > 0; s >>= 1) {
            if (tid < s) red[tid] += red[tid + s];
            __syncthreads();
        }
        sum = red[0]; __syncthreads();
        for (int r = tid; r < NR; r += 256)
            c_s[r * 2 + o] = expf(g_bij[r * 2 + o] - mx) / sum;
    }
    __syncthreads();

    int idx = blockIdx.x * 256 + tid;   // 1024 blocks x 256
    if (idx >= RI * 64) return;
    int od = idx & 63, ri = idx >> 6;
    int r = ri >> 3, i = ri & 7, o = od >> 5, dd = od & 31;
    float v = c_s[r * 2 + o] * W[((r * 2 + o) * 32 + dd) * 8 + i];
    __nv_bfloat16 h, l;
    split_bf(v, h, l);
    g_wct_hi[idx] = h;
    g_wct_lo[idx] = l;
}

__global__ void squash_v_kernel() {
    int gid = blockIdx.x * blockDim.x + threadIdx.x;
    int warp = gid >> 5, lane = gid & 31;
    if (warp >= BATCH * 2) return;
    int b = warp >> 1, o = warp & 1;
    float x = g_s[b * 64 + o * 32 + lane];
    float sq = warp_sum(x * x);
    float sc = sq / ((1.0f + sq) * sqrtf(sq + 1e-9f));
    g_v[b * 64 + o * 32 + lane] = x * sc;
}

__global__ void b_update_kernel(const float* __restrict__ W) {
    int gid = blockIdx.x * blockDim.x + threadIdx.x;
    int warp = gid >> 5, lane = gid & 31;
    if (warp >= NR * 2) return;
    int r = warp >> 1, o = warp & 1;
    float sum = 0.0f;
    for (int t = lane; t < 256; t += 32) {
        int dd = t >> 3, i = t & 7;
        sum += W[(r * 2 + o) * 256 + t] * g_GT[(o * 32 + dd) * RI + r * 8 + i];
    }
    sum = warp_sum(sum);
    if (lane == 0) g_bij[r * 2 + o] += sum;
}

__global__ void mask_kernel(float* __restrict__ out) {
    int gid = blockIdx.x * blockDim.x + threadIdx.x;
    int b = gid >> 5, lane = gid & 31;
    if (b >= BATCH) return;
    float v0 = g_v[b * 64 + lane];
    float v1 = g_v[b * 64 + 32 + lane];
    float n0 = warp_sum(v0 * v0);
    float n1 = warp_sum(v1 * v1);
    float m0 = (n1 > n0) ? 0.0f : 1.0f;
    float m1 = 1.0f - m0;
    out[b * 64 + lane] = v0;
    out[b * 64 + 32 + lane] = v1;
    if (lane == 0) {
        out[OUT_MASK_OFF + b * 2 + 0] = m0;
        out[OUT_MASK_OFF + b * 2 + 1] = m1;
    }
    __nv_bfloat16 h, l;
    split_bf(v0 * m0, h, l);
    g_h0_hi[b * 64 + lane] = h; g_h0_lo[b * 64 + lane] = l;
    split_bf(v1 * m1, h, l);
    g_h0_hi[b * 64 + 32 + lane] = h; g_h0_lo[b * 64 + 32 + lane] = l;
}

__global__ void sigmoid_bias_kernel(const float* __restrict__ bias, float* __restrict__ out) {
    int i = blockIdx.x * blockDim.x + threadIdx.x;
    if (i >= BATCH * 64) return;
    float v = g_r[i] + bias[i & 63];
    out[OUT_REC_OFF + i] = 1.0f / (1.0f + expf(-v));
}

// ---------------- pipelined plane-GEMM pieces ----------------
__device__ __forceinline__ void cp_stage_A(const __nv_bfloat16* hi, const __nv_bfloat16* lo,
                                           int ldA, int m0, int k0, uint32_t bufb, int tid) {
    #pragma unroll
    for (int q = 0; q < 2; q++) {
        int idx = q * 256 + tid;
        int plane = idx >> 8, rem = idx & 255;
        int row = rem >> 2, seg = rem & 3;
        const __nv_bfloat16* src = (plane ? lo : hi) + (size_t)(m0 + row) * ldA + k0 + seg * 8;
        cp_async16(bufb + (plane ? GAL : GAH) + row * 80 + seg * 16, src);
    }
}
__device__ __forceinline__ void cp_stage_B(const __nv_bfloat16* hi, const __nv_bfloat16* lo,
                                           int ldB, int k0, int n0, uint32_t bufb, int tid) {
    #pragma unroll
    for (int q = 0; q < 2; q++) {
        int idx = q * 256 + tid;
        int plane = idx >> 8, rem = idx & 255;
        int row = rem >> 3, seg = rem & 7;
        const __nv_bfloat16* src = (plane ? lo : hi) + (size_t)(k0 + row) * ldB + n0 + seg * 8;
        cp_async16(bufb + (plane ? GBL : GBH) + row * 144 + seg * 16, src);
    }
}
__device__ __forceinline__ void mma_tile(uint32_t bufb, int w, int lane, float (&d)[2][2][4]) {
    int mf = w & 3, ng = w >> 2;
    int mloc = lane & 15, chalf = lane >> 4;
    #pragma unroll
    for (int ks = 0; ks < 2; ks++) {
        uint32_t ah[4], al[4];
        uint32_t aaddr = bufb + GAH + (uint32_t)((mf * 16 + mloc) * 80 + (ks * 16 + chalf * 8) * 2);
        ldsm_x4(ah[0], ah[1], ah[2], ah[3], aaddr);
        ldsm_x4(al[0], al[1], al[2], al[3], aaddr + (GAL - GAH));
        #pragma unroll
        for (int h = 0; h < 2; h++) {
            uint32_t bh[4], bl[4];
            uint32_t baddr = bufb + GBH
                + (uint32_t)((ks * 16 + mloc) * 144 + (ng * 32 + h * 16 + chalf * 8) * 2);
            ldsm_x4_t(bh[0], bh[1], bh[2], bh[3], baddr);
            ldsm_x4_t(bl[0], bl[1], bl[2], bl[3], baddr + (GBL - GBH));
            mma_bf16(d[h][0], ah, bh[0], bh[1]);
            mma_bf16(d[h][1], ah, bh[2], bh[3]);
            mma_bf16(d[h][0], ah, bl[0], bl[1]);
            mma_bf16(d[h][1], ah, bl[2], bl[3]);
            mma_bf16(d[h][0], al, bh[0], bh[1]);
            mma_bf16(d[h][1], al, bh[2], bh[3]);
        }
    }
}

// C += alpha * A@B  (A,B prestaged planes), split-K atomic
__global__ void __launch_bounds__(256) tgemm_pp_splitk(
    const __nv_bfloat16* __restrict__ Ahi, const __nv_bfloat16* __restrict__ Alo, int ldA,
    const __nv_bfloat16* __restrict__ Bhi, const __nv_bfloat16* __restrict__ Blo, int ldB,
    float* __restrict__ C, int ldC, int Kchunk, float alpha)
{
    __shared__ __align__(16) char sm[2 * GBUF];
    int tid = threadIdx.x, w = tid >> 5, lane = tid & 31;
    int n0 = blockIdx.x * 64, m0 = blockIdx.y * 64, kbase = blockIdx.z * Kchunk;
    uint32_t smb = smem_u32(sm);
    int nc = Kchunk / 32;

    cp_stage_A(Ahi, Alo, ldA, m0, kbase, smb, tid);
    cp_stage_B(Bhi, Blo, ldB, kbase, n0, smb, tid);
    asm volatile("cp.async.commit_group;");

    float d[2][2][4] = {};
    for (int c = 0; c < nc; c++) {
        asm volatile("cp.async.wait_group 0;");
        __syncthreads();
        if (c + 1 < nc) {
            uint32_t nb = smb + ((c + 1) & 1) * GBUF;
            cp_stage_A(Ahi, Alo, ldA, m0, kbase + (c + 1) * 32, nb, tid);
            cp_stage_B(Bhi, Blo, ldB, kbase + (c + 1) * 32, n0, nb, tid);
            asm volatile("cp.async.commit_group;");
        }
        mma_tile(smb + (c & 1) * GBUF, w, lane, d);
    }
    int mf = w & 3, ng = w >> 2;
    int tig = lane & 3, gid = lane >> 2;
    #pragma unroll
    for (int h = 0; h < 2; h++)
        #pragma unroll
        for (int f = 0; f < 2; f++) {
            int col = n0 + ng * 32 + h * 16 + f * 8 + 2 * tig;
            int row = m0 + mf * 16 + gid;
            atomicAdd(&C[(size_t)row * ldC + col],           alpha * d[h][f][0]);
            atomicAdd(&C[(size_t)row * ldC + col + 1],       alpha * d[h][f][1]);
            atomicAdd(&C[(size_t)(row + 8) * ldC + col],     alpha * d[h][f][2]);
            atomicAdd(&C[(size_t)(row + 8) * ldC + col + 1], alpha * d[h][f][3]);
        }
}

// GT += alpha * V^T @ B  (V fp32 [K][64] scalar-staged; B planes), split-K atomic
__global__ void __launch_bounds__(256) tgemm_trv_splitk(
    const float* __restrict__ V,
    const __nv_bfloat16* __restrict__ Bhi, const __nv_bfloat16* __restrict__ Blo, int ldB,
    float* __restrict__ C, int ldC, int Kchunk, float alpha)
{
    __shared__ __align__(16) char sm[2 * GBUF];
    int tid = threadIdx.x, w = tid >> 5, lane = tid & 31;
    int n0 = blockIdx.x * 64, kbase = blockIdx.z * Kchunk;
    uint32_t smb = smem_u32(sm);
    int nc = Kchunk / 32;

    auto stageA = [&](int k0, char* buf) {
        int k = tid >> 3, mq = (tid & 7) * 8;
        const float* p = V + (size_t)(k0 + k) * 64 + mq;
        float4 f0 = *(const float4*)p, f1 = *(const float4*)(p + 4);
        float fa[8] = {f0.x, f0.y, f0.z, f0.w, f1.x, f1.y, f1.z, f1.w};
        #pragma unroll
        for (int i = 0; i < 8; i++) {
            __nv_bfloat16 h, l;
            split_bf(fa[i], h, l);
            *(__nv_bfloat16*)(buf + GAH + (mq + i) * 80 + k * 2) = h;
            *(__nv_bfloat16*)(buf + GAL + (mq + i) * 80 + k * 2) = l;
        }
    };

    stageA(kbase, sm);
    cp_stage_B(Bhi, Blo, ldB, kbase, n0, smb, tid);
    asm volatile("cp.async.commit_group;");
    __syncthreads();

    float d[2][2][4] = {};
    for (int c = 0; c < nc; c++) {
        asm volatile("cp.async.wait_group 0;");
        __syncthreads();
        if (c + 1 < nc) {
            char* nbuf = sm + ((c + 1) & 1) * GBUF;
            stageA(kbase + (c + 1) * 32, nbuf);
            cp_stage_B(Bhi, Blo, ldB, kbase + (c + 1) * 32, n0, smb + ((c + 1) & 1) * GBUF, tid);
            asm volatile("cp.async.commit_group;");
        }
        mma_tile(smb + (c & 1) * GBUF, w, lane, d);
    }
    int mf = w & 3, ng = w >> 2;
    int tig = lane & 3, gid = lane >> 2;
    #pragma unroll
    for (int h = 0; h < 2; h++)
        #pragma unroll
        for (int f = 0; f < 2; f++) {
            int col = n0 + ng * 32 + h * 16 + f * 8 + 2 * tig;
            int row = mf * 16 + gid;
            atomicAdd(&C[(size_t)row * ldC + col],           alpha * d[h][f][0]);
            atomicAdd(&C[(size_t)row * ldC + col + 1],       alpha * d[h][f][1]);
            atomicAdd(&C[(size_t)(row + 8) * ldC + col],     alpha * d[h][f][2]);
            atomicAdd(&C[(size_t)(row + 8) * ldC + col + 1], alpha * d[h][f][3]);
        }
}

// Chi/Clo = split(relu(A@B + bias)), full K (A,B planes)
__global__ void __launch_bounds__(256) tgemm_pp_bias(
    const __nv_bfloat16* __restrict__ Ahi, const __nv_bfloat16* __restrict__ Alo, int ldA,
    const __nv_bfloat16* __restrict__ Bhi, const __nv_bfloat16* __restrict__ Blo, int ldB,
    const float* __restrict__ bias,
    __nv_bfloat16* __restrict__ Chi, __nv_bfloat16* __restrict__ Clo, int N, int K)
{
    __shared__ __align__(16) char sm[2 * GBUF];
    int tid = threadIdx.x, w = tid >> 5, lane = tid & 31;
    int n0 = blockIdx.x * 64, m0 = blockIdx.y * 64;
    uint32_t smb = smem_u32(sm);
    int nc = K / 32;

    cp_stage_A(Ahi, Alo, ldA, m0, 0, smb, tid);
    cp_stage_B(Bhi, Blo, ldB, 0, n0, smb, tid);
    asm volatile("cp.async.commit_group;");

    float d[2][2][4] = {};
    for (int c = 0; c < nc; c++) {
        asm volatile("cp.async.wait_group 0;");
        __syncthreads();
        if (c + 1 < nc) {
            uint32_t nb = smb + ((c + 1) & 1) * GBUF;
            cp_stage_A(Ahi, Alo, ldA, m0, (c + 1) * 32, nb, tid);
            cp_stage_B(Bhi, Blo, ldB, (c + 1) * 32, n0, nb, tid);
            asm volatile("cp.async.commit_group;");
        }
        mma_tile(smb + (c & 1) * GBUF, w, lane, d);
    }
    int mf = w & 3, ng = w >> 2;
    int tig = lane & 3, gid = lane >> 2;
    #pragma unroll
    for (int h = 0; h < 2; h++)
        #pragma unroll
        for (int f = 0; f < 2; f++) {
            int col = n0 + ng * 32 + h * 16 + f * 8 + 2 * tig;
            int row = m0 + mf * 16 + gid;
            #pragma unroll
            for (int e = 0; e < 4; e++) {
                int rr = row + (e >> 1) * 8;
                int cc = col + (e & 1);
                float v = fmaxf(d[h][f][e] + bias[cc], 0.0f);
                __nv_bfloat16 hh, ll;
                split_bf(v, hh, ll);
                Chi[(size_t)rr * N + cc] = hh;
                Clo[(size_t)rr * N + cc] = ll;
            }
        }
}

// ---------------- launch ----------------
extern "C" void kernel_launch(void* const* d_in, const int* in_sizes, int n_in,
                              void* d_out, int out_size)
{
    const float* data    = (const float*)d_in[0];
    const float* conv1_w = (const float*)d_in[1];
    const float* conv1_b = (const float*)d_in[2];
    const float* prim_w  = (const float*)d_in[3];
    const float* prim_b  = (const float*)d_in[4];
    const float* W_digit = (const float*)d_in[5];
    const float* dec1_w  = (const float*)d_in[6];
    const float* dec1_b  = (const float*)d_in[7];
    const float* dec2_w  = (const float*)d_in[8];
    const float* dec2_b  = (const float*)d_in[9];
    const float* dec3_w  = (const float*)d_in[10];
    const float* dec3_b  = (const float*)d_in[11];
    float* out = (float*)d_out;

    float *p_bij, *p_s, *p_GT, *p_v, *p_r;
    cudaGetSymbolAddress((void**)&p_bij, g_bij);
    cudaGetSymbolAddress((void**)&p_s,   g_s);
    cudaGetSymbolAddress((void**)&p_GT,  g_GT);
    cudaGetSymbolAddress((void**)&p_v,   g_v);
    cudaGetSymbolAddress((void**)&p_r,   g_r);

    __nv_bfloat16 *u_hi, *u_lo, *wct_hi, *wct_lo, *h0_hi, *h0_lo;
    __nv_bfloat16 *h1_hi, *h1_lo, *h2_hi, *h2_lo;
    __nv_bfloat16 *w1_hi, *w1_lo, *w2_hi, *w2_lo, *w3_hi, *w3_lo;
    cudaGetSymbolAddress((void**)&u_hi, g_u_hi);
    cudaGetSymbolAddress((void**)&u_lo, g_u_lo);
    cudaGetSymbolAddress((void**)&wct_hi, g_wct_hi);
    cudaGetSymbolAddress((void**)&wct_lo, g_wct_lo);
    cudaGetSymbolAddress((void**)&h0_hi, g_h0_hi);
    cudaGetSymbolAddress((void**)&h0_lo, g_h0_lo);
    cudaGetSymbolAddress((void**)&h1_hi, g_h1_hi);
    cudaGetSymbolAddress((void**)&h1_lo, g_h1_lo);
    cudaGetSymbolAddress((void**)&h2_hi, g_h2_hi);
    cudaGetSymbolAddress((void**)&h2_lo, g_h2_lo);
    cudaGetSymbolAddress((void**)&w1_hi, g_w1_hi);
    cudaGetSymbolAddress((void**)&w1_lo, g_w1_lo);
    cudaGetSymbolAddress((void**)&w2_hi, g_w2_hi);
    cudaGetSymbolAddress((void**)&w2_lo, g_w2_lo);
    cudaGetSymbolAddress((void**)&w3_hi, g_w3_hi);
    cudaGetSymbolAddress((void**)&w3_lo, g_w3_lo);

    static int smem_set = 0;
    if (!smem_set) {
        cudaFuncSetAttribute(conv_tc_kernel,
                             cudaFuncAttributeMaxDynamicSharedMemorySize, CONV_SMEM);
        smem_set = 1;
    }

    wb_split_kernel<<<576, 256>>>(prim_w);                             // 0
    split_kernel<<<128, 256>>>(dec1_w, w1_hi, w1_lo, 64 * 512);        // 1
    split_kernel<<<2048, 256>>>(dec2_w, w2_hi, w2_lo, 512 * 1024);     // 2
    conv_tc_kernel<<<BATCH, 512, CONV_SMEM>>>(data, conv1_w, conv1_b, prim_b);  // 3
    split_kernel<<<256, 256>>>(dec3_w, w3_hi, w3_lo, 1024 * 64);       // 4
    zero_kernel<<<4, 256>>>(p_bij, NR * 2);                            // 5

    for (int it = 0; it < 3; it++) {
        build_wct_kernel<<<1024, 256>>>(W_digit);   // inline softmax
        zero_kernel<<<1024, 256>>>(p_s, BATCH * 64);
        tgemm_pp_splitk<<<dim3(1, 64, 8), 256>>>(u_hi, u_lo, RI, wct_hi, wct_lo, 64,
                                                 p_s, 64, 512, 1.0f);
        squash_v_kernel<<<1024, 256>>>();
        if (it < 2) {
            zero_kernel<<<1024, 256>>>(p_GT, 64 * RI);
            tgemm_trv_splitk<<<dim3(64, 1, 8), 256>>>(p_v, u_hi, u_lo, RI,
                                                      p_GT, RI, 512, 1.0f / (float)BATCH);
            b_update_kernel<<<128, 256>>>(W_digit);
        }
    }

    mask_kernel<<<512, 256>>>(out);
    zero_kernel<<<1024, 256>>>(p_r, BATCH * 64);

    tgemm_pp_bias<<<dim3(8, 64), 256>>>(h0_hi, h0_lo, 64, w1_hi, w1_lo, 512,
                                        dec1_b, h1_hi, h1_lo, 512, 64);
    tgemm_pp_bias<<<dim3(16, 64), 256>>>(h1_hi, h1_lo, 512, w2_hi, w2_lo, 1024,
                                         dec2_b, h2_hi, h2_lo, 1024, 512);
    tgemm_pp_splitk<<<dim3(1, 64, 4), 256>>>(h2_hi, h2_lo, 1024, w3_hi, w3_lo, 64,
                                             p_r, 64, 256, 1.0f);
    sigmoid_bias_kernel<<<1024, 256>>>(dec3_b, out);
}

// round 16
// speedup vs baseline: 1.4749x; 1.0013x over previous
#include <cuda_runtime.h>
#include <cuda_bf16.h>
#include <math.h>
#include <stdint.h>

#define BATCH 4096
#define NR 512
#define RI 4096
#define OUT_REC_OFF 262144
#define OUT_MASK_OFF 524288

// conv-kernel SMEM (bytes): A planes 100pos x 136 bf16 (halo 10x10, 128ic+8pad), 2 planes
#define XROW2 136
#define XT2_HI 0
#define XT2_LO 27200
#define BBUF2 54400
#define BPLANE 9216
#define BBUFSZ 18432
#define CONV_SMEM 91264

// pipelined GEMM staging: per buffer A 64x32 (pitch 80) hi/lo + B 32x64 (pitch 144) hi/lo
#define GAH 0
#define GAL 5120
#define GBH 10240
#define GBL 14848
#define GBUF 19456

// ---------------- device globals ----------------
__device__ __align__(16) __nv_bfloat16 g_wBc[36 * 8192];   // [chunk][plane][r*64+oc]
__device__ __align__(16) __nv_bfloat16 g_u_hi[(size_t)BATCH * RI];
__device__ __align__(16) __nv_bfloat16 g_u_lo[(size_t)BATCH * RI];
__device__ __align__(16) __nv_bfloat16 g_wct_hi[RI * 64];
__device__ __align__(16) __nv_bfloat16 g_wct_lo[RI * 64];
__device__ __align__(16) __nv_bfloat16 g_h0_hi[BATCH * 64];
__device__ __align__(16) __nv_bfloat16 g_h0_lo[BATCH * 64];
__device__ __align__(16) __nv_bfloat16 g_h1_hi[(size_t)BATCH * 512];
__device__ __align__(16) __nv_bfloat16 g_h1_lo[(size_t)BATCH * 512];
__device__ __align__(16) __nv_bfloat16 g_h2_hi[(size_t)BATCH * 1024];
__device__ __align__(16) __nv_bfloat16 g_h2_lo[(size_t)BATCH * 1024];
__device__ __align__(16) __nv_bfloat16 g_w1_hi[64 * 512];
__device__ __align__(16) __nv_bfloat16 g_w1_lo[64 * 512];
__device__ __align__(16) __nv_bfloat16 g_w2_hi[512 * 1024];
__device__ __align__(16) __nv_bfloat16 g_w2_lo[512 * 1024];
__device__ __align__(16) __nv_bfloat16 g_w3_hi[1024 * 64];
__device__ __align__(16) __nv_bfloat16 g_w3_lo[1024 * 64];
__device__ float g_bij[NR * 2];
__device__ float g_s[BATCH * 64];
__device__ float g_v[BATCH * 64];
__device__ float g_GT[64 * RI];
__device__ float g_r[BATCH * 64];

// ---------------- helpers ----------------
__device__ __forceinline__ float warp_sum(float v) {
    #pragma unroll
    for (int s = 16; s > 0; s >>= 1) v += __shfl_xor_sync(0xFFFFFFFFu, v, s);
    return v;
}
__device__ __forceinline__ uint32_t smem_u32(const void* p) {
    return (uint32_t)__cvta_generic_to_shared(p);
}
__device__ __forceinline__ void ldsm_x4(uint32_t& r0, uint32_t& r1, uint32_t& r2, uint32_t& r3,
                                        uint32_t addr) {
    asm volatile("ldmatrix.sync.aligned.m8n8.x4.shared.b16 {%0,%1,%2,%3}, [%4];"
                 : "=r"(r0), "=r"(r1), "=r"(r2), "=r"(r3) : "r"(addr));
}
__device__ __forceinline__ void ldsm_x4_t(uint32_t& r0, uint32_t& r1, uint32_t& r2, uint32_t& r3,
                                          uint32_t addr) {
    asm volatile("ldmatrix.sync.aligned.m8n8.x4.trans.shared.b16 {%0,%1,%2,%3}, [%4];"
                 : "=r"(r0), "=r"(r1), "=r"(r2), "=r"(r3) : "r"(addr));
}
__device__ __forceinline__ void mma_bf16(float d[4], const uint32_t a[4],
                                         uint32_t b0, uint32_t b1) {
    asm volatile(
        "mma.sync.aligned.m16n8k16.row.col.f32.bf16.bf16.f32 "
        "{%0,%1,%2,%3}, {%4,%5,%6,%7}, {%8,%9}, {%0,%1,%2,%3};"
        : "+f"(d[0]), "+f"(d[1]), "+f"(d[2]), "+f"(d[3])
        : "r"(a[0]), "r"(a[1]), "r"(a[2]), "r"(a[3]), "r"(b0), "r"(b1));
}
__device__ __forceinline__ void cp_async16(uint32_t dst, const void* src) {
    asm volatile("cp.async.cg.shared.global [%0], [%1], 16;" :: "r"(dst), "l"(src) : "memory");
}
__device__ __forceinline__ void split_bf(float v, __nv_bfloat16& h, __nv_bfloat16& l) {
    h = __float2bfloat16(v);
    l = __float2bfloat16(v - __bfloat162float(h));
}
__device__ __forceinline__ uint32_t pk2bf(__nv_bfloat16 a, __nv_bfloat16 b) {
    return (uint32_t)__bfloat16_as_ushort(a) | ((uint32_t)__bfloat16_as_ushort(b) << 16);
}

// ---------------- basic kernels ----------------
__global__ void zero_kernel(float* p, int n) {
    int i = blockIdx.x * blockDim.x + threadIdx.x;
    if (i < n) p[i] = 0.0f;
}
__global__ void split_kernel(const float* __restrict__ src,
                             __nv_bfloat16* __restrict__ hi,
                             __nv_bfloat16* __restrict__ lo, int n) {
    int i = blockIdx.x * blockDim.x + threadIdx.x;
    if (i >= n) return;
    __nv_bfloat16 h, l;
    split_bf(src[i], h, l);
    hi[i] = h; lo[i] = l;
}
// conv weights -> chunk-consumption-ordered planes
__global__ void wb_split_kernel(const float* __restrict__ pw) {
    int idx = blockIdx.x * blockDim.x + threadIdx.x;
    if (idx >= 147456) return;
    int cid = idx >> 12, t = idx & 4095;
    int r = t >> 6, col = t & 63;
    int half = cid / 18, cc = cid % 18;
    int j = cc >> 1, kc = cc & 1;
    int krow = j * 256 + half * 128 + kc * 64 + r;
    int ic = krow & 255, jj = krow >> 8;
    __nv_bfloat16 h, l;
    split_bf(pw[col * 2304 + ic * 9 + jj], h, l);
    g_wBc[cid * 8192 + t] = h;
    g_wBc[cid * 8192 + 4096 + t] = l;
}

// ---------------- fused conv1 + bf16 3-term mma primary conv + squash --------
// one CTA per image, 512 threads, 2 CTAs/SM; ic in two halves of 128.
// warp = (kg = w&3, q = w>>2); warp tile m32 x n32 for its k16 slice per chunk.
__global__ void __launch_bounds__(512, 2) conv_tc_kernel(
    const float* __restrict__ data, const float* __restrict__ w1,
    const float* __restrict__ b1, const float* __restrict__ pb)
{
    extern __shared__ char smem[];
    __shared__ float s_img[64];
    __nv_bfloat16* xhi = (__nv_bfloat16*)(smem + XT2_HI);
    __nv_bfloat16* xlo = (__nv_bfloat16*)(smem + XT2_LO);

    int b = blockIdx.x;
    int tid = threadIdx.x;
    int w = tid >> 5, lane = tid & 31;
    uint32_t sm_base = smem_u32(smem);

    // hoisted staging addresses: linear src, fixed dst pair
    const char* wsrc = (const char*)g_wBc + tid * 16;
    uint32_t pdst = sm_base + BBUF2 + (tid >> 3) * 144 + (tid & 7) * 16;

    // prefetch B chunk 0 into buffer 0
    cp_async16(pdst, wsrc);
    cp_async16(pdst + BPLANE, wsrc + 8192);
    asm volatile("cp.async.commit_group;");

    {   // zero both A planes
        uint4 z = make_uint4(0, 0, 0, 0);
        uint4* p = (uint4*)smem;
        for (int i = tid; i < BBUF2 / 16; i += 512) p[i] = z;
    }
    if (tid < 64) s_img[tid] = data[b * 64 + tid];
    __syncthreads();

    int kg = w & 3, q = w >> 2;
    int mq = q & 1, nq = q >> 1;
    int mloc = lane & 15, chalf = lane >> 4;
    int mA0 = mq * 32 + mloc;
    int mA1 = mA0 + 16;
    int pbase0 = (mA0 >> 3) * 10 + (mA0 & 7);
    int pbase1 = (mA1 >> 3) * 10 + (mA1 & 7);

    // hoisted ldsm bases
    uint32_t xhi_u = sm_base + XT2_HI;
    const int lo_delta = XT2_LO - XT2_HI;
    uint32_t aB0 = xhi_u + (uint32_t)(pbase0 * XROW2 + kg * 16 + chalf * 8) * 2u;
    uint32_t aB1 = xhi_u + (uint32_t)(pbase1 * XROW2 + kg * 16 + chalf * 8) * 2u;
    uint32_t broff = (uint32_t)(kg * 16 + mloc) * 144u + (uint32_t)(nq * 32 + chalf * 8) * 2u;
    uint32_t bb0 = sm_base + BBUF2 + broff;
    uint32_t bb1 = bb0 + BBUFSZ;

    float d[2][4][4] = {};
    int cid = 0;

    #pragma unroll 1
    for (int half = 0; half < 2; half++) {
        if (half == 1) __syncthreads();   // all warps done reading half-0 A planes

        {   // phase 1: conv1 for this half's 128 ic; thread = (icl, quarter)
            int icl = tid & 127, qq = tid >> 7;
            int ic = half * 128 + icl;
            float wr[9];
            #pragma unroll
            for (int k = 0; k < 9; k++) wr[k] = w1[ic * 9 + k];
            float bias = b1[ic];
            #pragma unroll
            for (int yy = 0; yy < 2; yy++) {
                int y = qq * 2 + yy;
                #pragma unroll
                for (int x = 0; x < 8; x++) {
                    float acc = bias;
                    #pragma unroll
                    for (int ky = 0; ky < 3; ky++) {
                        int iy = y + ky - 1;
                        if (iy < 0 || iy > 7) continue;
                        #pragma unroll
                        for (int kx = 0; kx < 3; kx++) {
                            int ix = x + kx - 1;
                            if (ix < 0 || ix > 7) continue;
                            acc += wr[ky * 3 + kx] * s_img[iy * 8 + ix];
                        }
                    }
                    acc = fmaxf(acc, 0.0f);
                    __nv_bfloat16 hi, lo;
                    split_bf(acc, hi, lo);
                    int p = (y + 1) * 10 + (x + 1);
                    xhi[p * XROW2 + icl] = hi;
                    xlo[p * XROW2 + icl] = lo;
                }
            }
        }

        #pragma unroll 1
        for (int ky = 0; ky < 3; ky++) {
            #pragma unroll 1
            for (int kx = 0; kx < 3; kx++) {
                int toff2 = (ky * 10 + kx) * XROW2 * 2;
                #pragma unroll
                for (int kc = 0; kc < 2; kc++) {
                    asm volatile("cp.async.wait_group 0;");
                    __syncthreads();   // B chunk ready; phase-1 writes visible

                    if (cid + 1 < 36) {
                        const char* s = wsrc + (size_t)(cid + 1) * 16384;
                        uint32_t dd = pdst + ((cid + 1) & 1) * BBUFSZ;
                        cp_async16(dd, s);
                        cp_async16(dd + BPLANE, s + 8192);
                        asm volatile("cp.async.commit_group;");
                    }

                    uint32_t aoff = (uint32_t)(toff2 + kc * 128);
                    uint32_t a0 = aB0 + aoff;
                    uint32_t a1 = aB1 + aoff;
                    uint32_t ah0[4], al0[4], ah1[4], al1[4];
                    ldsm_x4(ah0[0], ah0[1], ah0[2], ah0[3], a0);
                    ldsm_x4(al0[0], al0[1], al0[2], al0[3], a0 + lo_delta);
                    ldsm_x4(ah1[0], ah1[1], ah1[2], ah1[3], a1);
                    ldsm_x4(al1[0], al1[1], al1[2], al1[3], a1 + lo_delta);

                    uint32_t brow = (cid & 1) ? bb1 : bb0;
                    #pragma unroll
                    for (int g16 = 0; g16 < 2; g16++) {
                        uint32_t bh[4], bl[4];
                        uint32_t baddr = brow + g16 * 32;
                        ldsm_x4_t(bh[0], bh[1], bh[2], bh[3], baddr);
                        ldsm_x4_t(bl[0], bl[1], bl[2], bl[3], baddr + BPLANE);
                        int n0j = g16 * 2, n1j = g16 * 2 + 1;
                        mma_bf16(d[0][n0j], ah0, bh[0], bh[1]);
                        mma_bf16(d[0][n1j], ah0, bh[2], bh[3]);
                        mma_bf16(d[1][n0j], ah1, bh[0], bh[1]);
                        mma_bf16(d[1][n1j], ah1, bh[2], bh[3]);
                        mma_bf16(d[0][n0j], ah0, bl[0], bl[1]);
                        mma_bf16(d[0][n1j], ah0, bl[2], bl[3]);
                        mma_bf16(d[1][n0j], ah1, bl[0], bl[1]);
                        mma_bf16(d[1][n1j], ah1, bl[2], bl[3]);
                        mma_bf16(d[0][n0j], al0, bh[0], bh[1]);
                        mma_bf16(d[0][n1j], al0, bh[2], bh[3]);
                        mma_bf16(d[1][n0j], al1, bh[0], bh[1]);
                        mma_bf16(d[1][n1j], al1, bh[2], bh[3]);
                    }
                    cid++;
                }
            }
        }
    }

    // ---- cross-kg reduction into fp32 tile [64 pos][pitch 68] at smem+0 ----
    float* tile = (float*)smem;   // A planes dead
    int tig = lane & 3, gid = lane >> 2;
    #pragma unroll 1
    for (int g = 0; g < 4; g++) {
        __syncthreads();
        if (kg == g) {
            #pragma unroll
            for (int mi = 0; mi < 2; mi++) {
                int r0 = mq * 32 + mi * 16 + gid;
                #pragma unroll
                for (int nj = 0; nj < 4; nj++) {
                    int col = nq * 32 + nj * 8 + 2 * tig;
                    if (g == 0) {
                        tile[r0 * 68 + col]           = d[mi][nj][0];
                        tile[r0 * 68 + col + 1]       = d[mi][nj][1];
                        tile[(r0 + 8) * 68 + col]     = d[mi][nj][2];
                        tile[(r0 + 8) * 68 + col + 1] = d[mi][nj][3];
                    } else {
                        tile[r0 * 68 + col]           += d[mi][nj][0];
                        tile[r0 * 68 + col + 1]       += d[mi][nj][1];
                        tile[(r0 + 8) * 68 + col]     += d[mi][nj][2];
                        tile[(r0 + 8) * 68 + col + 1] += d[mi][nj][3];
                    }
                }
            }
        }
    }
    __syncthreads();

    // ---- epilogue: thread = (oc, y); bias + squash over x; vector store ----
    {
        int oc = tid & 63, y = tid >> 6;
        float bias = pb[oc];
        float xv[8];
        float qn = 0.0f;
        #pragma unroll
        for (int x = 0; x < 8; x++) {
            float v = tile[(y * 8 + x) * 68 + oc] + bias;
            xv[x] = v;
            qn += v * v;
        }
        float sc = qn / ((1.0f + qn) * sqrtf(qn + 1e-9f));
        uint32_t hp[4], lp[4];
        #pragma unroll
        for (int p = 0; p < 4; p++) {
            __nv_bfloat16 h0, l0, h1, l1;
            split_bf(xv[2*p] * sc, h0, l0);
            split_bf(xv[2*p+1] * sc, h1, l1);
            hp[p] = pk2bf(h0, h1);
            lp[p] = pk2bf(l0, l1);
        }
        size_t idx = (size_t)b * RI + (size_t)(oc * 8 + y) * 8;
        *(uint4*)&g_u_hi[idx] = make_uint4(hp[0], hp[1], hp[2], hp[3]);
        *(uint4*)&g_u_lo[idx] = make_uint4(lp[0], lp[1], lp[2], lp[3]);
    }
}

// ---------------- routing small kernels ----------------
// build_wct with inline softmax over routes (axis 0)
__global__ void build_wct_kernel(const float* __restrict__ W) {
    __shared__ float red[256];
    __shared__ float c_s[NR * 2];
    int tid = threadIdx.x;
    #pragma unroll
    for (int o = 0; o < 2; o++) {
        float mx = -1e30f;
        for (int r = tid; r < NR; r += 256) mx = fmaxf(mx, g_bij[r * 2 + o]);
        red[tid] = mx; __syncthreads();
        for (int s = 128; s > 0; s >>= 1) {
            if (tid < s) red[tid] = fmaxf(red[tid], red[tid + s]);
            __syncthreads();
        }
        mx = red[0]; __syncthreads();
        float sum = 0.0f;
        for (int r = tid; r < NR; r += 256) sum += expf(g_bij[r * 2 + o] - mx);
        red[tid] = sum; __syncthreads();
        for (int s = 128; s > 0; s >>= 1) {
            if (tid < s) red[tid] += red[tid + s];
            __syncthreads();
        }
        sum = red[0]; __syncthreads();
        for (int r = tid; r < NR; r += 256)
            c_s[r * 2 + o] = expf(g_bij[r * 2 + o] - mx) / sum;
    }
    __syncthreads();

    int idx = blockIdx.x * 256 + tid;
    if (idx >= RI * 64) return;
    int od = idx & 63, ri = idx >> 6;
    int r = ri >> 3, i = ri & 7, o = od >> 5, dd = od & 31;
    float v = c_s[r * 2 + o] * W[((r * 2 + o) * 32 + dd) * 8 + i];
    __nv_bfloat16 h, l;
    split_bf(v, h, l);
    g_wct_hi[idx] = h;
    g_wct_lo[idx] = l;
}

__global__ void squash_v_kernel() {
    int gid = blockIdx.x * blockDim.x + threadIdx.x;
    int warp = gid >> 5, lane = gid & 31;
    if (warp >= BATCH * 2) return;
    int b = warp >> 1, o = warp & 1;
    float x = g_s[b * 64 + o * 32 + lane];
    float sq = warp_sum(x * x);
    float sc = sq / ((1.0f + sq) * sqrtf(sq + 1e-9f));
    g_v[b * 64 + o * 32 + lane] = x * sc;
}

__global__ void b_update_kernel(const float* __restrict__ W) {
    int gid = blockIdx.x * blockDim.x + threadIdx.x;
    int warp = gid >> 5, lane = gid & 31;
    if (warp >= NR * 2) return;
    int r = warp >> 1, o = warp & 1;
    float sum = 0.0f;
    for (int t = lane; t < 256; t += 32) {
        int dd = t >> 3, i = t & 7;
        sum += W[(r * 2 + o) * 256 + t] * g_GT[(o * 32 + dd) * RI + r * 8 + i];
    }
    sum = warp_sum(sum);
    if (lane == 0) g_bij[r * 2 + o] += sum;
}

__global__ void mask_kernel(float* __restrict__ out) {
    int gid = blockIdx.x * blockDim.x + threadIdx.x;
    int b = gid >> 5, lane = gid & 31;
    if (b >= BATCH) return;
    float v0 = g_v[b * 64 + lane];
    float v1 = g_v[b * 64 + 32 + lane];
    float n0 = warp_sum(v0 * v0);
    float n1 = warp_sum(v1 * v1);
    float m0 = (n1 > n0) ? 0.0f : 1.0f;
    float m1 = 1.0f - m0;
    out[b * 64 + lane] = v0;
    out[b * 64 + 32 + lane] = v1;
    if (lane == 0) {
        out[OUT_MASK_OFF + b * 2 + 0] = m0;
        out[OUT_MASK_OFF + b * 2 + 1] = m1;
    }
    __nv_bfloat16 h, l;
    split_bf(v0 * m0, h, l);
    g_h0_hi[b * 64 + lane] = h; g_h0_lo[b * 64 + lane] = l;
    split_bf(v1 * m1, h, l);
    g_h0_hi[b * 64 + 32 + lane] = h; g_h0_lo[b * 64 + 32 + lane] = l;
}

__global__ void sigmoid_bias_kernel(const float* __restrict__ bias, float* __restrict__ out) {
    int i = blockIdx.x * blockDim.x + threadIdx.x;
    if (i >= BATCH * 64) return;
    float v = g_r[i] + bias[i & 63];
    out[OUT_REC_OFF + i] = 1.0f / (1.0f + expf(-v));
}

// ---------------- pipelined plane-GEMM pieces ----------------
__device__ __forceinline__ void cp_stage_A(const __nv_bfloat16* hi, const __nv_bfloat16* lo,
                                           int ldA, int m0, int k0, uint32_t bufb, int tid) {
    #pragma unroll
    for (int q = 0; q < 2; q++) {
        int idx = q * 256 + tid;
        int plane = idx >> 8, rem = idx & 255;
        int row = rem >> 2, seg = rem & 3;
        const __nv_bfloat16* src = (plane ? lo : hi) + (size_t)(m0 + row) * ldA + k0 + seg * 8;
        cp_async16(bufb + (plane ? GAL : GAH) + row * 80 + seg * 16, src);
    }
}
__device__ __forceinline__ void cp_stage_B(const __nv_bfloat16* hi, const __nv_bfloat16* lo,
                                           int ldB, int k0, int n0, uint32_t bufb, int tid) {
    #pragma unroll
    for (int q = 0; q < 2; q++) {
        int idx = q * 256 + tid;
        int plane = idx >> 8, rem = idx & 255;
        int row = rem >> 3, seg = rem & 7;
        const __nv_bfloat16* src = (plane ? lo : hi) + (size_t)(k0 + row) * ldB + n0 + seg * 8;
        cp_async16(bufb + (plane ? GBL : GBH) + row * 144 + seg * 16, src);
    }
}
__device__ __forceinline__ void mma_tile(uint32_t bufb, int w, int lane, float (&d)[2][2][4]) {
    int mf = w & 3, ng = w >> 2;
    int mloc = lane & 15, chalf = lane >> 4;
    #pragma unroll
    for (int ks = 0; ks < 2; ks++) {
        uint32_t ah[4], al[4];
        uint32_t aaddr = bufb + GAH + (uint32_t)((mf * 16 + mloc) * 80 + (ks * 16 + chalf * 8) * 2);
        ldsm_x4(ah[0], ah[1], ah[2], ah[3], aaddr);
        ldsm_x4(al[0], al[1], al[2], al[3], aaddr + (GAL - GAH));
        #pragma unroll
        for (int h = 0; h < 2; h++) {
            uint32_t bh[4], bl[4];
            uint32_t baddr = bufb + GBH
                + (uint32_t)((ks * 16 + mloc) * 144 + (ng * 32 + h * 16 + chalf * 8) * 2);
            ldsm_x4_t(bh[0], bh[1], bh[2], bh[3], baddr);
            ldsm_x4_t(bl[0], bl[1], bl[2], bl[3], baddr + (GBL - GBH));
            mma_bf16(d[h][0], ah, bh[0], bh[1]);
            mma_bf16(d[h][1], ah, bh[2], bh[3]);
            mma_bf16(d[h][0], ah, bl[0], bl[1]);
            mma_bf16(d[h][1], ah, bl[2], bl[3]);
            mma_bf16(d[h][0], al, bh[0], bh[1]);
            mma_bf16(d[h][1], al, bh[2], bh[3]);
        }
    }
}

// C += alpha * A@B  (A,B prestaged planes), split-K atomic
__global__ void __launch_bounds__(256) tgemm_pp_splitk(
    const __nv_bfloat16* __restrict__ Ahi, const __nv_bfloat16* __restrict__ Alo, int ldA,
    const __nv_bfloat16* __restrict__ Bhi, const __nv_bfloat16* __restrict__ Blo, int ldB,
    float* __restrict__ C, int ldC, int Kchunk, float alpha)
{
    __shared__ __align__(16) char sm[2 * GBUF];
    int tid = threadIdx.x, w = tid >> 5, lane = tid & 31;
    int n0 = blockIdx.x * 64, m0 = blockIdx.y * 64, kbase = blockIdx.z * Kchunk;
    uint32_t smb = smem_u32(sm);
    int nc = Kchunk / 32;

    cp_stage_A(Ahi, Alo, ldA, m0, kbase, smb, tid);
    cp_stage_B(Bhi, Blo, ldB, kbase, n0, smb, tid);
    asm volatile("cp.async.commit_group;");

    float d[2][2][4] = {};
    for (int c = 0; c < nc; c++) {
        asm volatile("cp.async.wait_group 0;");
        __syncthreads();
        if (c + 1 < nc) {
            uint32_t nb = smb + ((c + 1) & 1) * GBUF;
            cp_stage_A(Ahi, Alo, ldA, m0, kbase + (c + 1) * 32, nb, tid);
            cp_stage_B(Bhi, Blo, ldB, kbase + (c + 1) * 32, n0, nb, tid);
            asm volatile("cp.async.commit_group;");
        }
        mma_tile(smb + (c & 1) * GBUF, w, lane, d);
    }
    int mf = w & 3, ng = w >> 2;
    int tig = lane & 3, gid = lane >> 2;
    #pragma unroll
    for (int h = 0; h < 2; h++)
        #pragma unroll
        for (int f = 0; f < 2; f++) {
            int col = n0 + ng * 32 + h * 16 + f * 8 + 2 * tig;
            int row = m0 + mf * 16 + gid;
            atomicAdd(&C[(size_t)row * ldC + col],           alpha * d[h][f][0]);
            atomicAdd(&C[(size_t)row * ldC + col + 1],       alpha * d[h][f][1]);
            atomicAdd(&C[(size_t)(row + 8) * ldC + col],     alpha * d[h][f][2]);
            atomicAdd(&C[(size_t)(row + 8) * ldC + col + 1], alpha * d[h][f][3]);
        }
}

// GT += alpha * V^T @ B  (V fp32 [K][64] scalar-staged; B planes), split-K atomic
__global__ void __launch_bounds__(256) tgemm_trv_splitk(
    const float* __restrict__ V,
    const __nv_bfloat16* __restrict__ Bhi, const __nv_bfloat16* __restrict__ Blo, int ldB,
    float* __restrict__ C, int ldC, int Kchunk, float alpha)
{
    __shared__ __align__(16) char sm[2 * GBUF];
    int tid = threadIdx.x, w = tid >> 5, lane = tid & 31;
    int n0 = blockIdx.x * 64, kbase = blockIdx.z * Kchunk;
    uint32_t smb = smem_u32(sm);
    int nc = Kchunk / 32;

    auto stageA = [&](int k0, char* buf) {
        int k = tid >> 3, mq = (tid & 7) * 8;
        const float* p = V + (size_t)(k0 + k) * 64 + mq;
        float4 f0 = *(const float4*)p, f1 = *(const float4*)(p + 4);
        float fa[8] = {f0.x, f0.y, f0.z, f0.w, f1.x, f1.y, f1.z, f1.w};
        #pragma unroll
        for (int i = 0; i < 8; i++) {
            __nv_bfloat16 h, l;
            split_bf(fa[i], h, l);
            *(__nv_bfloat16*)(buf + GAH + (mq + i) * 80 + k * 2) = h;
            *(__nv_bfloat16*)(buf + GAL + (mq + i) * 80 + k * 2) = l;
        }
    };

    stageA(kbase, sm);
    cp_stage_B(Bhi, Blo, ldB, kbase, n0, smb, tid);
    asm volatile("cp.async.commit_group;");
    __syncthreads();

    float d[2][2][4] = {};
    for (int c = 0; c < nc; c++) {
        asm volatile("cp.async.wait_group 0;");
        __syncthreads();
        if (c + 1 < nc) {
            char* nbuf = sm + ((c + 1) & 1) * GBUF;
            stageA(kbase + (c + 1) * 32, nbuf);
            cp_stage_B(Bhi, Blo, ldB, kbase + (c + 1) * 32, n0, smb + ((c + 1) & 1) * GBUF, tid);
            asm volatile("cp.async.commit_group;");
        }
        mma_tile(smb + (c & 1) * GBUF, w, lane, d);
    }
    int mf = w & 3, ng = w >> 2;
    int tig = lane & 3, gid = lane >> 2;
    #pragma unroll
    for (int h = 0; h < 2; h++)
        #pragma unroll
        for (int f = 0; f < 2; f++) {
            int col = n0 + ng * 32 + h * 16 + f * 8 + 2 * tig;
            int row = mf * 16 + gid;
            atomicAdd(&C[(size_t)row * ldC + col],           alpha * d[h][f][0]);
            atomicAdd(&C[(size_t)row * ldC + col + 1],       alpha * d[h][f][1]);
            atomicAdd(&C[(size_t)(row + 8) * ldC + col],     alpha * d[h][f][2]);
            atomicAdd(&C[(size_t)(row + 8) * ldC + col + 1], alpha * d[h][f][3]);
        }
}

// Chi/Clo = split(relu(A@B + bias)), full K (A,B planes)
__global__ void __launch_bounds__(256) tgemm_pp_bias(
    const __nv_bfloat16* __restrict__ Ahi, const __nv_bfloat16* __restrict__ Alo, int ldA,
    const __nv_bfloat16* __restrict__ Bhi, const __nv_bfloat16* __restrict__ Blo, int ldB,
    const float* __restrict__ bias,
    __nv_bfloat16* __restrict__ Chi, __nv_bfloat16* __restrict__ Clo, int N, int K)
{
    __shared__ __align__(16) char sm[2 * GBUF];
    int tid = threadIdx.x, w = tid >> 5, lane = tid & 31;
    int n0 = blockIdx.x * 64, m0 = blockIdx.y * 64;
    uint32_t smb = smem_u32(sm);
    int nc = K / 32;

    cp_stage_A(Ahi, Alo, ldA, m0, 0, smb, tid);
    cp_stage_B(Bhi, Blo, ldB, 0, n0, smb, tid);
    asm volatile("cp.async.commit_group;");

    float d[2][2][4] = {};
    for (int c = 0; c < nc; c++) {
        asm volatile("cp.async.wait_group 0;");
        __syncthreads();
        if (c + 1 < nc) {
            uint32_t nb = smb + ((c + 1) & 1) * GBUF;
            cp_stage_A(Ahi, Alo, ldA, m0, (c + 1) * 32, nb, tid);
            cp_stage_B(Bhi, Blo, ldB, (c + 1) * 32, n0, nb, tid);
            asm volatile("cp.async.commit_group;");
        }
        mma_tile(smb + (c & 1) * GBUF, w, lane, d);
    }
    int mf = w & 3, ng = w >> 2;
    int tig = lane & 3, gid = lane >> 2;
    #pragma unroll
    for (int h = 0; h < 2; h++)
        #pragma unroll
        for (int f = 0; f < 2; f++) {
            int col = n0 + ng * 32 + h * 16 + f * 8 + 2 * tig;
            int row = m0 + mf * 16 + gid;
            #pragma unroll
            for (int e = 0; e < 4; e++) {
                int rr = row + (e >> 1) * 8;
                int cc = col + (e & 1);
                float v = fmaxf(d[h][f][e] + bias[cc], 0.0f);
                __nv_bfloat16 hh, ll;
                split_bf(v, hh, ll);
                Chi[(size_t)rr * N + cc] = hh;
                Clo[(size_t)rr * N + cc] = ll;
            }
        }
}

// ---------------- launch ----------------
extern "C" void kernel_launch(void* const* d_in, const int* in_sizes, int n_in,
                              void* d_out, int out_size)
{
    const float* data    = (const float*)d_in[0];
    const float* conv1_w = (const float*)d_in[1];
    const float* conv1_b = (const float*)d_in[2];
    const float* prim_w  = (const float*)d_in[3];
    const float* prim_b  = (const float*)d_in[4];
    const float* W_digit = (const float*)d_in[5];
    const float* dec1_w  = (const float*)d_in[6];
    const float* dec1_b  = (const float*)d_in[7];
    const float* dec2_w  = (const float*)d_in[8];
    const float* dec2_b  = (const float*)d_in[9];
    const float* dec3_w  = (const float*)d_in[10];
    const float* dec3_b  = (const float*)d_in[11];
    float* out = (float*)d_out;

    float *p_bij, *p_s, *p_GT, *p_v, *p_r;
    cudaGetSymbolAddress((void**)&p_bij, g_bij);
    cudaGetSymbolAddress((void**)&p_s,   g_s);
    cudaGetSymbolAddress((void**)&p_GT,  g_GT);
    cudaGetSymbolAddress((void**)&p_v,   g_v);
    cudaGetSymbolAddress((void**)&p_r,   g_r);

    __nv_bfloat16 *u_hi, *u_lo, *wct_hi, *wct_lo, *h0_hi, *h0_lo;
    __nv_bfloat16 *h1_hi, *h1_lo, *h2_hi, *h2_lo;
    __nv_bfloat16 *w1_hi, *w1_lo, *w2_hi, *w2_lo, *w3_hi, *w3_lo;
    cudaGetSymbolAddress((void**)&u_hi, g_u_hi);
    cudaGetSymbolAddress((void**)&u_lo, g_u_lo);
    cudaGetSymbolAddress((void**)&wct_hi, g_wct_hi);
    cudaGetSymbolAddress((void**)&wct_lo, g_wct_lo);
    cudaGetSymbolAddress((void**)&h0_hi, g_h0_hi);
    cudaGetSymbolAddress((void**)&h0_lo, g_h0_lo);
    cudaGetSymbolAddress((void**)&h1_hi, g_h1_hi);
    cudaGetSymbolAddress((void**)&h1_lo, g_h1_lo);
    cudaGetSymbolAddress((void**)&h2_hi, g_h2_hi);
    cudaGetSymbolAddress((void**)&h2_lo, g_h2_lo);
    cudaGetSymbolAddress((void**)&w1_hi, g_w1_hi);
    cudaGetSymbolAddress((void**)&w1_lo, g_w1_lo);
    cudaGetSymbolAddress((void**)&w2_hi, g_w2_hi);
    cudaGetSymbolAddress((void**)&w2_lo, g_w2_lo);
    cudaGetSymbolAddress((void**)&w3_hi, g_w3_hi);
    cudaGetSymbolAddress((void**)&w3_lo, g_w3_lo);

    static int smem_set = 0;
    if (!smem_set) {
        cudaFuncSetAttribute(conv_tc_kernel,
                             cudaFuncAttributeMaxDynamicSharedMemorySize, CONV_SMEM);
        smem_set = 1;
    }

    wb_split_kernel<<<576, 256>>>(prim_w);                             // 0
    split_kernel<<<128, 256>>>(dec1_w, w1_hi, w1_lo, 64 * 512);        // 1
    split_kernel<<<2048, 256>>>(dec2_w, w2_hi, w2_lo, 512 * 1024);     // 2
    conv_tc_kernel<<<BATCH, 512, CONV_SMEM>>>(data, conv1_w, conv1_b, prim_b);  // 3
    split_kernel<<<256, 256>>>(dec3_w, w3_hi, w3_lo, 1024 * 64);       // 4
    zero_kernel<<<4, 256>>>(p_bij, NR * 2);                            // 5

    for (int it = 0; it < 3; it++) {
        build_wct_kernel<<<1024, 256>>>(W_digit);   // inline softmax
        zero_kernel<<<1024, 256>>>(p_s, BATCH * 64);
        tgemm_pp_splitk<<<dim3(1, 64, 8), 256>>>(u_hi, u_lo, RI, wct_hi, wct_lo, 64,
                                                 p_s, 64, 512, 1.0f);
        squash_v_kernel<<<1024, 256>>>();
        if (it < 2) {
            zero_kernel<<<1024, 256>>>(p_GT, 64 * RI);
            tgemm_trv_splitk<<<dim3(64, 1, 8), 256>>>(p_v, u_hi, u_lo, RI,
                                                      p_GT, RI, 512, 1.0f / (float)BATCH);
            b_update_kernel<<<128, 256>>>(W_digit);
        }
    }

    mask_kernel<<<512, 256>>>(out);
    zero_kernel<<<1024, 256>>>(p_r, BATCH * 64);

    tgemm_pp_bias<<<dim3(8, 64), 256>>>(h0_hi, h0_lo, 64, w1_hi, w1_lo, 512,
                                        dec1_b, h1_hi, h1_lo, 512, 64);
    tgemm_pp_bias<<<dim3(16, 64), 256>>>(h1_hi, h1_lo, 512, w2_hi, w2_lo, 1024,
                                         dec2_b, h2_hi, h2_lo, 1024, 512);
    tgemm_pp_splitk<<<dim3(1, 64, 4), 256>>>(h2_hi, h2_lo, 1024, w3_hi, w3_lo, 64,
                                             p_r, 64, 256, 1.0f);
    sigmoid_bias_kernel<<<1024, 256>>>(dec3_b, out);
}

// round 17
// speedup vs baseline: 1.4849x; 1.0067x over previous
#include <cuda_runtime.h>
#include <cuda_bf16.h>
#include <math.h>
#include <stdint.h>

#define BATCH 4096
#define NR 512
#define RI 4096
#define OUT_REC_OFF 262144
#define OUT_MASK_OFF 524288

// conv-kernel SMEM (bytes): A planes (halo 10x10, 128ic+8pad) x2 + 3-slot B ring
#define XROW2 136
#define XT2_HI 0
#define XT2_LO 27200
#define BBUF2 54400
#define BPLANE 9216
#define BBUFSZ 18432
#define CONV_SMEM 109696

// pipelined GEMM staging: per buffer A 64x32 (pitch 80) hi/lo + B 32x64 (pitch 144) hi/lo
#define GAH 0
#define GAL 5120
#define GBH 10240
#define GBL 14848
#define GBUF 19456

// ---------------- device globals ----------------
__device__ __align__(16) __nv_bfloat16 g_wBc[36 * 8192];   // [chunk][plane][r*64+oc]
__device__ __align__(16) __nv_bfloat16 g_u_hi[(size_t)BATCH * RI];
__device__ __align__(16) __nv_bfloat16 g_u_lo[(size_t)BATCH * RI];
__device__ __align__(16) __nv_bfloat16 g_wct_hi[RI * 64];
__device__ __align__(16) __nv_bfloat16 g_wct_lo[RI * 64];
__device__ __align__(16) __nv_bfloat16 g_h0_hi[BATCH * 64];
__device__ __align__(16) __nv_bfloat16 g_h0_lo[BATCH * 64];
__device__ __align__(16) __nv_bfloat16 g_h1_hi[(size_t)BATCH * 512];
__device__ __align__(16) __nv_bfloat16 g_h1_lo[(size_t)BATCH * 512];
__device__ __align__(16) __nv_bfloat16 g_h2_hi[(size_t)BATCH * 1024];
__device__ __align__(16) __nv_bfloat16 g_h2_lo[(size_t)BATCH * 1024];
__device__ __align__(16) __nv_bfloat16 g_w1_hi[64 * 512];
__device__ __align__(16) __nv_bfloat16 g_w1_lo[64 * 512];
__device__ __align__(16) __nv_bfloat16 g_w2_hi[512 * 1024];
__device__ __align__(16) __nv_bfloat16 g_w2_lo[512 * 1024];
__device__ __align__(16) __nv_bfloat16 g_w3_hi[1024 * 64];
__device__ __align__(16) __nv_bfloat16 g_w3_lo[1024 * 64];
__device__ float g_bij[NR * 2];
__device__ float g_s[BATCH * 64];
__device__ float g_v[BATCH * 64];
__device__ float g_GT[64 * RI];
__device__ float g_r[BATCH * 64];

// ---------------- helpers ----------------
__device__ __forceinline__ float warp_sum(float v) {
    #pragma unroll
    for (int s = 16; s > 0; s >>= 1) v += __shfl_xor_sync(0xFFFFFFFFu, v, s);
    return v;
}
__device__ __forceinline__ uint32_t smem_u32(const void* p) {
    return (uint32_t)__cvta_generic_to_shared(p);
}
__device__ __forceinline__ void ldsm_x4(uint32_t& r0, uint32_t& r1, uint32_t& r2, uint32_t& r3,
                                        uint32_t addr) {
    asm volatile("ldmatrix.sync.aligned.m8n8.x4.shared.b16 {%0,%1,%2,%3}, [%4];"
                 : "=r"(r0), "=r"(r1), "=r"(r2), "=r"(r3) : "r"(addr));
}
__device__ __forceinline__ void ldsm_x4_t(uint32_t& r0, uint32_t& r1, uint32_t& r2, uint32_t& r3,
                                          uint32_t addr) {
    asm volatile("ldmatrix.sync.aligned.m8n8.x4.trans.shared.b16 {%0,%1,%2,%3}, [%4];"
                 : "=r"(r0), "=r"(r1), "=r"(r2), "=r"(r3) : "r"(addr));
}
__device__ __forceinline__ void mma_bf16(float d[4], const uint32_t a[4],
                                         uint32_t b0, uint32_t b1) {
    asm volatile(
        "mma.sync.aligned.m16n8k16.row.col.f32.bf16.bf16.f32 "
        "{%0,%1,%2,%3}, {%4,%5,%6,%7}, {%8,%9}, {%0,%1,%2,%3};"
        : "+f"(d[0]), "+f"(d[1]), "+f"(d[2]), "+f"(d[3])
        : "r"(a[0]), "r"(a[1]), "r"(a[2]), "r"(a[3]), "r"(b0), "r"(b1));
}
__device__ __forceinline__ void cp_async16(uint32_t dst, const void* src) {
    asm volatile("cp.async.cg.shared.global [%0], [%1], 16;" :: "r"(dst), "l"(src) : "memory");
}
__device__ __forceinline__ void split_bf(float v, __nv_bfloat16& h, __nv_bfloat16& l) {
    h = __float2bfloat16(v);
    l = __float2bfloat16(v - __bfloat162float(h));
}
__device__ __forceinline__ uint32_t pk2bf(__nv_bfloat16 a, __nv_bfloat16 b) {
    return (uint32_t)__bfloat16_as_ushort(a) | ((uint32_t)__bfloat16_as_ushort(b) << 16);
}

// ---------------- basic kernels ----------------
__global__ void zero_kernel(float* p, int n) {
    int i = blockIdx.x * blockDim.x + threadIdx.x;
    if (i < n) p[i] = 0.0f;
}
__global__ void split_kernel(const float* __restrict__ src,
                             __nv_bfloat16* __restrict__ hi,
                             __nv_bfloat16* __restrict__ lo, int n) {
    int i = blockIdx.x * blockDim.x + threadIdx.x;
    if (i >= n) return;
    __nv_bfloat16 h, l;
    split_bf(src[i], h, l);
    hi[i] = h; lo[i] = l;
}
// conv weights -> chunk-consumption-ordered planes
__global__ void wb_split_kernel(const float* __restrict__ pw) {
    int idx = blockIdx.x * blockDim.x + threadIdx.x;
    if (idx >= 147456) return;
    int cid = idx >> 12, t = idx & 4095;
    int r = t >> 6, col = t & 63;
    int half = cid / 18, cc = cid % 18;
    int j = cc >> 1, kc = cc & 1;
    int krow = j * 256 + half * 128 + kc * 64 + r;
    int ic = krow & 255, jj = krow >> 8;
    __nv_bfloat16 h, l;
    split_bf(pw[col * 2304 + ic * 9 + jj], h, l);
    g_wBc[cid * 8192 + t] = h;
    g_wBc[cid * 8192 + 4096 + t] = l;
}

// ---------------- fused conv1 + bf16 3-term mma primary conv + squash --------
// one CTA per image, 512 threads, 2 CTAs/SM; ic in two halves of 128.
// 3-slot B ring, 2-chunk prefetch lookahead (copy latency fully hidden).
__global__ void __launch_bounds__(512, 2) conv_tc_kernel(
    const float* __restrict__ data, const float* __restrict__ w1,
    const float* __restrict__ b1, const float* __restrict__ pb)
{
    extern __shared__ char smem[];
    __shared__ float s_img[64];
    __nv_bfloat16* xhi = (__nv_bfloat16*)(smem + XT2_HI);
    __nv_bfloat16* xlo = (__nv_bfloat16*)(smem + XT2_LO);

    int b = blockIdx.x;
    int tid = threadIdx.x;
    int w = tid >> 5, lane = tid & 31;
    uint32_t sm_base = smem_u32(smem);

    // hoisted staging addresses: linear src, fixed dst pair
    const char* wsrc = (const char*)g_wBc + tid * 16;
    uint32_t pdst = sm_base + BBUF2 + (tid >> 3) * 144 + (tid & 7) * 16;

    // prologue: prefetch chunks 0,1 into slots 0,1 (separate groups)
    cp_async16(pdst, wsrc);
    cp_async16(pdst + BPLANE, wsrc + 8192);
    asm volatile("cp.async.commit_group;");
    cp_async16(pdst + BBUFSZ, wsrc + 16384);
    cp_async16(pdst + BBUFSZ + BPLANE, wsrc + 16384 + 8192);
    asm volatile("cp.async.commit_group;");

    {   // zero both A planes
        uint4 z = make_uint4(0, 0, 0, 0);
        uint4* p = (uint4*)smem;
        for (int i = tid; i < BBUF2 / 16; i += 512) p[i] = z;
    }
    if (tid < 64) s_img[tid] = data[b * 64 + tid];
    __syncthreads();

    int kg = w & 3, q = w >> 2;
    int mq = q & 1, nq = q >> 1;
    int mloc = lane & 15, chalf = lane >> 4;
    int mA0 = mq * 32 + mloc;
    int mA1 = mA0 + 16;
    int pbase0 = (mA0 >> 3) * 10 + (mA0 & 7);
    int pbase1 = (mA1 >> 3) * 10 + (mA1 & 7);

    // hoisted ldsm bases
    uint32_t xhi_u = sm_base + XT2_HI;
    const int lo_delta = XT2_LO - XT2_HI;
    uint32_t aB0 = xhi_u + (uint32_t)(pbase0 * XROW2 + kg * 16 + chalf * 8) * 2u;
    uint32_t aB1 = xhi_u + (uint32_t)(pbase1 * XROW2 + kg * 16 + chalf * 8) * 2u;
    uint32_t broff = (uint32_t)(kg * 16 + mloc) * 144u + (uint32_t)(nq * 32 + chalf * 8) * 2u;
    uint32_t bbBase = sm_base + BBUF2 + broff;

    float d[2][4][4] = {};
    int cid = 0;
    int slot = 0;       // slot of current chunk (cid % 3)
    int pslot = 2;      // slot for prefetch target ((cid+2) % 3)

    #pragma unroll 1
    for (int half = 0; half < 2; half++) {
        if (half == 1) __syncthreads();   // all warps done reading half-0 A planes

        {   // phase 1: conv1 for this half's 128 ic; thread = (icl, quarter)
            int icl = tid & 127, qq = tid >> 7;
            int ic = half * 128 + icl;
            float wr[9];
            #pragma unroll
            for (int k = 0; k < 9; k++) wr[k] = w1[ic * 9 + k];
            float bias = b1[ic];
            #pragma unroll
            for (int yy = 0; yy < 2; yy++) {
                int y = qq * 2 + yy;
                #pragma unroll
                for (int x = 0; x < 8; x++) {
                    float acc = bias;
                    #pragma unroll
                    for (int ky = 0; ky < 3; ky++) {
                        int iy = y + ky - 1;
                        if (iy < 0 || iy > 7) continue;
                        #pragma unroll
                        for (int kx = 0; kx < 3; kx++) {
                            int ix = x + kx - 1;
                            if (ix < 0 || ix > 7) continue;
                            acc += wr[ky * 3 + kx] * s_img[iy * 8 + ix];
                        }
                    }
                    acc = fmaxf(acc, 0.0f);
                    __nv_bfloat16 hi, lo;
                    split_bf(acc, hi, lo);
                    int p = (y + 1) * 10 + (x + 1);
                    xhi[p * XROW2 + icl] = hi;
                    xlo[p * XROW2 + icl] = lo;
                }
            }
        }

        #pragma unroll 1
        for (int ky = 0; ky < 3; ky++) {
            #pragma unroll 1
            for (int kx = 0; kx < 3; kx++) {
                int toff2 = (ky * 10 + kx) * XROW2 * 2;
                #pragma unroll
                for (int kc = 0; kc < 2; kc++) {
                    __syncthreads();   // all warps done with chunk cid-1 (its slot = pslot)

                    if (cid + 2 < 36) {   // prefetch chunk cid+2 into freed slot
                        const char* s = wsrc + (size_t)(cid + 2) * 16384;
                        uint32_t dd = pdst + pslot * BBUFSZ;
                        cp_async16(dd, s);
                        cp_async16(dd + BPLANE, s + 8192);
                        asm volatile("cp.async.commit_group;");
                    }
                    // wait for chunk cid's copy (issued 2 chunks ago)
                    if (cid < 34)       asm volatile("cp.async.wait_group 2;");
                    else if (cid == 34) asm volatile("cp.async.wait_group 1;");
                    else                asm volatile("cp.async.wait_group 0;");

                    uint32_t aoff = (uint32_t)(toff2 + kc * 128);
                    uint32_t a0 = aB0 + aoff;
                    uint32_t a1 = aB1 + aoff;
                    uint32_t ah0[4], al0[4], ah1[4], al1[4];
                    ldsm_x4(ah0[0], ah0[1], ah0[2], ah0[3], a0);
                    ldsm_x4(al0[0], al0[1], al0[2], al0[3], a0 + lo_delta);
                    ldsm_x4(ah1[0], ah1[1], ah1[2], ah1[3], a1);
                    ldsm_x4(al1[0], al1[1], al1[2], al1[3], a1 + lo_delta);

                    uint32_t brow = bbBase + (uint32_t)slot * BBUFSZ;
                    #pragma unroll
                    for (int g16 = 0; g16 < 2; g16++) {
                        uint32_t bh[4], bl[4];
                        uint32_t baddr = brow + g16 * 32;
                        ldsm_x4_t(bh[0], bh[1], bh[2], bh[3], baddr);
                        ldsm_x4_t(bl[0], bl[1], bl[2], bl[3], baddr + BPLANE);
                        int n0j = g16 * 2, n1j = g16 * 2 + 1;
                        mma_bf16(d[0][n0j], ah0, bh[0], bh[1]);
                        mma_bf16(d[0][n1j], ah0, bh[2], bh[3]);
                        mma_bf16(d[1][n0j], ah1, bh[0], bh[1]);
                        mma_bf16(d[1][n1j], ah1, bh[2], bh[3]);
                        mma_bf16(d[0][n0j], ah0, bl[0], bl[1]);
                        mma_bf16(d[0][n1j], ah0, bl[2], bl[3]);
                        mma_bf16(d[1][n0j], ah1, bl[0], bl[1]);
                        mma_bf16(d[1][n1j], ah1, bl[2], bl[3]);
                        mma_bf16(d[0][n0j], al0, bh[0], bh[1]);
                        mma_bf16(d[0][n1j], al0, bh[2], bh[3]);
                        mma_bf16(d[1][n0j], al1, bh[0], bh[1]);
                        mma_bf16(d[1][n1j], al1, bh[2], bh[3]);
                    }
                    cid++;
                    slot = (slot == 2) ? 0 : slot + 1;
                    pslot = (pslot == 2) ? 0 : pslot + 1;
                }
            }
        }
    }

    // ---- cross-kg reduction into fp32 tile [64 pos][pitch 68] at smem+0 ----
    float* tile = (float*)smem;   // A planes dead
    int tig = lane & 3, gid = lane >> 2;
    #pragma unroll 1
    for (int g = 0; g < 4; g++) {
        __syncthreads();
        if (kg == g) {
            #pragma unroll
            for (int mi = 0; mi < 2; mi++) {
                int r0 = mq * 32 + mi * 16 + gid;
                #pragma unroll
                for (int nj = 0; nj < 4; nj++) {
                    int col = nq * 32 + nj * 8 + 2 * tig;
                    if (g == 0) {
                        tile[r0 * 68 + col]           = d[mi][nj][0];
                        tile[r0 * 68 + col + 1]       = d[mi][nj][1];
                        tile[(r0 + 8) * 68 + col]     = d[mi][nj][2];
                        tile[(r0 + 8) * 68 + col + 1] = d[mi][nj][3];
                    } else {
                        tile[r0 * 68 + col]           += d[mi][nj][0];
                        tile[r0 * 68 + col + 1]       += d[mi][nj][1];
                        tile[(r0 + 8) * 68 + col]     += d[mi][nj][2];
                        tile[(r0 + 8) * 68 + col + 1] += d[mi][nj][3];
                    }
                }
            }
        }
    }
    __syncthreads();

    // ---- epilogue: thread = (oc, y); bias + squash over x; vector store ----
    {
        int oc = tid & 63, y = tid >> 6;
        float bias = pb[oc];
        float xv[8];
        float qn = 0.0f;
        #pragma unroll
        for (int x = 0; x < 8; x++) {
            float v = tile[(y * 8 + x) * 68 + oc] + bias;
            xv[x] = v;
            qn += v * v;
        }
        float sc = qn / ((1.0f + qn) * sqrtf(qn + 1e-9f));
        uint32_t hp[4], lp[4];
        #pragma unroll
        for (int p = 0; p < 4; p++) {
            __nv_bfloat16 h0, l0, h1, l1;
            split_bf(xv[2*p] * sc, h0, l0);
            split_bf(xv[2*p+1] * sc, h1, l1);
            hp[p] = pk2bf(h0, h1);
            lp[p] = pk2bf(l0, l1);
        }
        size_t idx = (size_t)b * RI + (size_t)(oc * 8 + y) * 8;
        *(uint4*)&g_u_hi[idx] = make_uint4(hp[0], hp[1], hp[2], hp[3]);
        *(uint4*)&g_u_lo[idx] = make_uint4(lp[0], lp[1], lp[2], lp[3]);
    }
}

// ---------------- routing small kernels ----------------
// build_wct with inline softmax over routes (axis 0)
__global__ void build_wct_kernel(const float* __restrict__ W) {
    __shared__ float red[256];
    __shared__ float c_s[NR * 2];
    int tid = threadIdx.x;
    #pragma unroll
    for (int o = 0; o < 2; o++) {
        float mx = -1e30f;
        for (int r = tid; r < NR; r += 256) mx = fmaxf(mx, g_bij[r * 2 + o]);
        red[tid] = mx; __syncthreads();
        for (int s = 128; s > 0; s >>= 1) {
            if (tid < s) red[tid] = fmaxf(red[tid], red[tid + s]);
            __syncthreads();
        }
        mx = red[0]; __syncthreads();
        float sum = 0.0f;
        for (int r = tid; r < NR; r += 256) sum += expf(g_bij[r * 2 + o] - mx);
        red[tid] = sum; __syncthreads();
        for (int s = 128; s > 0; s >>= 1) {
            if (tid < s) red[tid] += red[tid + s];
            __syncthreads();
        }
        sum = red[0]; __syncthreads();
        for (int r = tid; r < NR; r += 256)
            c_s[r * 2 + o] = expf(g_bij[r * 2 + o] - mx) / sum;
    }
    __syncthreads();

    int idx = blockIdx.x * 256 + tid;
    if (idx >= RI * 64) return;
    int od = idx & 63, ri = idx >> 6;
    int r = ri >> 3, i = ri & 7, o = od >> 5, dd = od & 31;
    float v = c_s[r * 2 + o] * W[((r * 2 + o) * 32 + dd) * 8 + i];
    __nv_bfloat16 h, l;
    split_bf(v, h, l);
    g_wct_hi[idx] = h;
    g_wct_lo[idx] = l;
}

__global__ void squash_v_kernel() {
    int gid = blockIdx.x * blockDim.x + threadIdx.x;
    int warp = gid >> 5, lane = gid & 31;
    if (warp >= BATCH * 2) return;
    int b = warp >> 1, o = warp & 1;
    float x = g_s[b * 64 + o * 32 + lane];
    float sq = warp_sum(x * x);
    float sc = sq / ((1.0f + sq) * sqrtf(sq + 1e-9f));
    g_v[b * 64 + o * 32 + lane] = x * sc;
}

__global__ void b_update_kernel(const float* __restrict__ W) {
    int gid = blockIdx.x * blockDim.x + threadIdx.x;
    int warp = gid >> 5, lane = gid & 31;
    if (warp >= NR * 2) return;
    int r = warp >> 1, o = warp & 1;
    float sum = 0.0f;
    for (int t = lane; t < 256; t += 32) {
        int dd = t >> 3, i = t & 7;
        sum += W[(r * 2 + o) * 256 + t] * g_GT[(o * 32 + dd) * RI + r * 8 + i];
    }
    sum = warp_sum(sum);
    if (lane == 0) g_bij[r * 2 + o] += sum;
}

__global__ void mask_kernel(float* __restrict__ out) {
    int gid = blockIdx.x * blockDim.x + threadIdx.x;
    int b = gid >> 5, lane = gid & 31;
    if (b >= BATCH) return;
    float v0 = g_v[b * 64 + lane];
    float v1 = g_v[b * 64 + 32 + lane];
    float n0 = warp_sum(v0 * v0);
    float n1 = warp_sum(v1 * v1);
    float m0 = (n1 > n0) ? 0.0f : 1.0f;
    float m1 = 1.0f - m0;
    out[b * 64 + lane] = v0;
    out[b * 64 + 32 + lane] = v1;
    if (lane == 0) {
        out[OUT_MASK_OFF + b * 2 + 0] = m0;
        out[OUT_MASK_OFF + b * 2 + 1] = m1;
    }
    __nv_bfloat16 h, l;
    split_bf(v0 * m0, h, l);
    g_h0_hi[b * 64 + lane] = h; g_h0_lo[b * 64 + lane] = l;
    split_bf(v1 * m1, h, l);
    g_h0_hi[b * 64 + 32 + lane] = h; g_h0_lo[b * 64 + 32 + lane] = l;
}

__global__ void sigmoid_bias_kernel(const float* __restrict__ bias, float* __restrict__ out) {
    int i = blockIdx.x * blockDim.x + threadIdx.x;
    if (i >= BATCH * 64) return;
    float v = g_r[i] + bias[i & 63];
    out[OUT_REC_OFF + i] = 1.0f / (1.0f + expf(-v));
}

// ---------------- pipelined plane-GEMM pieces ----------------
__device__ __forceinline__ void cp_stage_A(const __nv_bfloat16* hi, const __nv_bfloat16* lo,
                                           int ldA, int m0, int k0, uint32_t bufb, int tid) {
    #pragma unroll
    for (int q = 0; q < 2; q++) {
        int idx = q * 256 + tid;
        int plane = idx >> 8, rem = idx & 255;
        int row = rem >> 2, seg = rem & 3;
        const __nv_bfloat16* src = (plane ? lo : hi) + (size_t)(m0 + row) * ldA + k0 + seg * 8;
        cp_async16(bufb + (plane ? GAL : GAH) + row * 80 + seg * 16, src);
    }
}
__device__ __forceinline__ void cp_stage_B(const __nv_bfloat16* hi, const __nv_bfloat16* lo,
                                           int ldB, int k0, int n0, uint32_t bufb, int tid) {
    #pragma unroll
    for (int q = 0; q < 2; q++) {
        int idx = q * 256 + tid;
        int plane = idx >> 8, rem = idx & 255;
        int row = rem >> 3, seg = rem & 7;
        const __nv_bfloat16* src = (plane ? lo : hi) + (size_t)(k0 + row) * ldB + n0 + seg * 8;
        cp_async16(bufb + (plane ? GBL : GBH) + row * 144 + seg * 16, src);
    }
}
__device__ __forceinline__ void mma_tile(uint32_t bufb, int w, int lane, float (&d)[2][2][4]) {
    int mf = w & 3, ng = w >> 2;
    int mloc = lane & 15, chalf = lane >> 4;
    #pragma unroll
    for (int ks = 0; ks < 2; ks++) {
        uint32_t ah[4], al[4];
        uint32_t aaddr = bufb + GAH + (uint32_t)((mf * 16 + mloc) * 80 + (ks * 16 + chalf * 8) * 2);
        ldsm_x4(ah[0], ah[1], ah[2], ah[3], aaddr);
        ldsm_x4(al[0], al[1], al[2], al[3], aaddr + (GAL - GAH));
        #pragma unroll
        for (int h = 0; h < 2; h++) {
            uint32_t bh[4], bl[4];
            uint32_t baddr = bufb + GBH
                + (uint32_t)((ks * 16 + mloc) * 144 + (ng * 32 + h * 16 + chalf * 8) * 2);
            ldsm_x4_t(bh[0], bh[1], bh[2], bh[3], baddr);
            ldsm_x4_t(bl[0], bl[1], bl[2], bl[3], baddr + (GBL - GBH));
            mma_bf16(d[h][0], ah, bh[0], bh[1]);
            mma_bf16(d[h][1], ah, bh[2], bh[3]);
            mma_bf16(d[h][0], ah, bl[0], bl[1]);
            mma_bf16(d[h][1], ah, bl[2], bl[3]);
            mma_bf16(d[h][0], al, bh[0], bh[1]);
            mma_bf16(d[h][1], al, bh[2], bh[3]);
        }
    }
}

// C += alpha * A@B  (A,B prestaged planes), split-K atomic
__global__ void __launch_bounds__(256) tgemm_pp_splitk(
    const __nv_bfloat16* __restrict__ Ahi, const __nv_bfloat16* __restrict__ Alo, int ldA,
    const __nv_bfloat16* __restrict__ Bhi, const __nv_bfloat16* __restrict__ Blo, int ldB,
    float* __restrict__ C, int ldC, int Kchunk, float alpha)
{
    __shared__ __align__(16) char sm[2 * GBUF];
    int tid = threadIdx.x, w = tid >> 5, lane = tid & 31;
    int n0 = blockIdx.x * 64, m0 = blockIdx.y * 64, kbase = blockIdx.z * Kchunk;
    uint32_t smb = smem_u32(sm);
    int nc = Kchunk / 32;

    cp_stage_A(Ahi, Alo, ldA, m0, kbase, smb, tid);
    cp_stage_B(Bhi, Blo, ldB, kbase, n0, smb, tid);
    asm volatile("cp.async.commit_group;");

    float d[2][2][4] = {};
    for (int c = 0; c < nc; c++) {
        asm volatile("cp.async.wait_group 0;");
        __syncthreads();
        if (c + 1 < nc) {
            uint32_t nb = smb + ((c + 1) & 1) * GBUF;
            cp_stage_A(Ahi, Alo, ldA, m0, kbase + (c + 1) * 32, nb, tid);
            cp_stage_B(Bhi, Blo, ldB, kbase + (c + 1) * 32, n0, nb, tid);
            asm volatile("cp.async.commit_group;");
        }
        mma_tile(smb + (c & 1) * GBUF, w, lane, d);
    }
    int mf = w & 3, ng = w >> 2;
    int tig = lane & 3, gid = lane >> 2;
    #pragma unroll
    for (int h = 0; h < 2; h++)
        #pragma unroll
        for (int f = 0; f < 2; f++) {
            int col = n0 + ng * 32 + h * 16 + f * 8 + 2 * tig;
            int row = m0 + mf * 16 + gid;
            atomicAdd(&C[(size_t)row * ldC + col],           alpha * d[h][f][0]);
            atomicAdd(&C[(size_t)row * ldC + col + 1],       alpha * d[h][f][1]);
            atomicAdd(&C[(size_t)(row + 8) * ldC + col],     alpha * d[h][f][2]);
            atomicAdd(&C[(size_t)(row + 8) * ldC + col + 1], alpha * d[h][f][3]);
        }
}

// GT += alpha * V^T @ B  (V fp32 [K][64] scalar-staged; B planes), split-K atomic
__global__ void __launch_bounds__(256) tgemm_trv_splitk(
    const float* __restrict__ V,
    const __nv_bfloat16* __restrict__ Bhi, const __nv_bfloat16* __restrict__ Blo, int ldB,
    float* __restrict__ C, int ldC, int Kchunk, float alpha)
{
    __shared__ __align__(16) char sm[2 * GBUF];
    int tid = threadIdx.x, w = tid >> 5, lane = tid & 31;
    int n0 = blockIdx.x * 64, kbase = blockIdx.z * Kchunk;
    uint32_t smb = smem_u32(sm);
    int nc = Kchunk / 32;

    auto stageA = [&](int k0, char* buf) {
        int k = tid >> 3, mq = (tid & 7) * 8;
        const float* p = V + (size_t)(k0 + k) * 64 + mq;
        float4 f0 = *(const float4*)p, f1 = *(const float4*)(p + 4);
        float fa[8] = {f0.x, f0.y, f0.z, f0.w, f1.x, f1.y, f1.z, f1.w};
        #pragma unroll
        for (int i = 0; i < 8; i++) {
            __nv_bfloat16 h, l;
            split_bf(fa[i], h, l);
            *(__nv_bfloat16*)(buf + GAH + (mq + i) * 80 + k * 2) = h;
            *(__nv_bfloat16*)(buf + GAL + (mq + i) * 80 + k * 2) = l;
        }
    };

    stageA(kbase, sm);
    cp_stage_B(Bhi, Blo, ldB, kbase, n0, smb, tid);
    asm volatile("cp.async.commit_group;");
    __syncthreads();

    float d[2][2][4] = {};
    for (int c = 0; c < nc; c++) {
        asm volatile("cp.async.wait_group 0;");
        __syncthreads();
        if (c + 1 < nc) {
            char* nbuf = sm + ((c + 1) & 1) * GBUF;
            stageA(kbase + (c + 1) * 32, nbuf);
            cp_stage_B(Bhi, Blo, ldB, kbase + (c + 1) * 32, n0, smb + ((c + 1) & 1) * GBUF, tid);
            asm volatile("cp.async.commit_group;");
        }
        mma_tile(smb + (c & 1) * GBUF, w, lane, d);
    }
    int mf = w & 3, ng = w >> 2;
    int tig = lane & 3, gid = lane >> 2;
    #pragma unroll
    for (int h = 0; h < 2; h++)
        #pragma unroll
        for (int f = 0; f < 2; f++) {
            int col = n0 + ng * 32 + h * 16 + f * 8 + 2 * tig;
            int row = mf * 16 + gid;
            atomicAdd(&C[(size_t)row * ldC + col],           alpha * d[h][f][0]);
            atomicAdd(&C[(size_t)row * ldC + col + 1],       alpha * d[h][f][1]);
            atomicAdd(&C[(size_t)(row + 8) * ldC + col],     alpha * d[h][f][2]);
            atomicAdd(&C[(size_t)(row + 8) * ldC + col + 1], alpha * d[h][f][3]);
        }
}

// Chi/Clo = split(relu(A@B + bias)), full K (A,B planes)
__global__ void __launch_bounds__(256) tgemm_pp_bias(
    const __nv_bfloat16* __restrict__ Ahi, const __nv_bfloat16* __restrict__ Alo, int ldA,
    const __nv_bfloat16* __restrict__ Bhi, const __nv_bfloat16* __restrict__ Blo, int ldB,
    const float* __restrict__ bias,
    __nv_bfloat16* __restrict__ Chi, __nv_bfloat16* __restrict__ Clo, int N, int K)
{
    __shared__ __align__(16) char sm[2 * GBUF];
    int tid = threadIdx.x, w = tid >> 5, lane = tid & 31;
    int n0 = blockIdx.x * 64, m0 = blockIdx.y * 64;
    uint32_t smb = smem_u32(sm);
    int nc = K / 32;

    cp_stage_A(Ahi, Alo, ldA, m0, 0, smb, tid);
    cp_stage_B(Bhi, Blo, ldB, 0, n0, smb, tid);
    asm volatile("cp.async.commit_group;");

    float d[2][2][4] = {};
    for (int c = 0; c < nc; c++) {
        asm volatile("cp.async.wait_group 0;");
        __syncthreads();
        if (c + 1 < nc) {
            uint32_t nb = smb + ((c + 1) & 1) * GBUF;
            cp_stage_A(Ahi, Alo, ldA, m0, (c + 1) * 32, nb, tid);
            cp_stage_B(Bhi, Blo, ldB, (c + 1) * 32, n0, nb, tid);
            asm volatile("cp.async.commit_group;");
        }
        mma_tile(smb + (c & 1) * GBUF, w, lane, d);
    }
    int mf = w & 3, ng = w >> 2;
    int tig = lane & 3, gid = lane >> 2;
    #pragma unroll
    for (int h = 0; h < 2; h++)
        #pragma unroll
        for (int f = 0; f < 2; f++) {
            int col = n0 + ng * 32 + h * 16 + f * 8 + 2 * tig;
            int row = m0 + mf * 16 + gid;
            #pragma unroll
            for (int e = 0; e < 4; e++) {
                int rr = row + (e >> 1) * 8;
                int cc = col + (e & 1);
                float v = fmaxf(d[h][f][e] + bias[cc], 0.0f);
                __nv_bfloat16 hh, ll;
                split_bf(v, hh, ll);
                Chi[(size_t)rr * N + cc] = hh;
                Clo[(size_t)rr * N + cc] = ll;
            }
        }
}

// ---------------- launch ----------------
extern "C" void kernel_launch(void* const* d_in, const int* in_sizes, int n_in,
                              void* d_out, int out_size)
{
    const float* data    = (const float*)d_in[0];
    const float* conv1_w = (const float*)d_in[1];
    const float* conv1_b = (const float*)d_in[2];
    const float* prim_w  = (const float*)d_in[3];
    const float* prim_b  = (const float*)d_in[4];
    const float* W_digit = (const float*)d_in[5];
    const float* dec1_w  = (const float*)d_in[6];
    const float* dec1_b  = (const float*)d_in[7];
    const float* dec2_w  = (const float*)d_in[8];
    const float* dec2_b  = (const float*)d_in[9];
    const float* dec3_w  = (const float*)d_in[10];
    const float* dec3_b  = (const float*)d_in[11];
    float* out = (float*)d_out;

    float *p_bij, *p_s, *p_GT, *p_v, *p_r;
    cudaGetSymbolAddress((void**)&p_bij, g_bij);
    cudaGetSymbolAddress((void**)&p_s,   g_s);
    cudaGetSymbolAddress((void**)&p_GT,  g_GT);
    cudaGetSymbolAddress((void**)&p_v,   g_v);
    cudaGetSymbolAddress((void**)&p_r,   g_r);

    __nv_bfloat16 *u_hi, *u_lo, *wct_hi, *wct_lo, *h0_hi, *h0_lo;
    __nv_bfloat16 *h1_hi, *h1_lo, *h2_hi, *h2_lo;
    __nv_bfloat16 *w1_hi, *w1_lo, *w2_hi, *w2_lo, *w3_hi, *w3_lo;
    cudaGetSymbolAddress((void**)&u_hi, g_u_hi);
    cudaGetSymbolAddress((void**)&u_lo, g_u_lo);
    cudaGetSymbolAddress((void**)&wct_hi, g_wct_hi);
    cudaGetSymbolAddress((void**)&wct_lo, g_wct_lo);
    cudaGetSymbolAddress((void**)&h0_hi, g_h0_hi);
    cudaGetSymbolAddress((void**)&h0_lo, g_h0_lo);
    cudaGetSymbolAddress((void**)&h1_hi, g_h1_hi);
    cudaGetSymbolAddress((void**)&h1_lo, g_h1_lo);
    cudaGetSymbolAddress((void**)&h2_hi, g_h2_hi);
    cudaGetSymbolAddress((void**)&h2_lo, g_h2_lo);
    cudaGetSymbolAddress((void**)&w1_hi, g_w1_hi);
    cudaGetSymbolAddress((void**)&w1_lo, g_w1_lo);
    cudaGetSymbolAddress((void**)&w2_hi, g_w2_hi);
    cudaGetSymbolAddress((void**)&w2_lo, g_w2_lo);
    cudaGetSymbolAddress((void**)&w3_hi, g_w3_hi);
    cudaGetSymbolAddress((void**)&w3_lo, g_w3_lo);

    static int smem_set = 0;
    if (!smem_set) {
        cudaFuncSetAttribute(conv_tc_kernel,
                             cudaFuncAttributeMaxDynamicSharedMemorySize, CONV_SMEM);
        smem_set = 1;
    }

    wb_split_kernel<<<576, 256>>>(prim_w);                             // 0
    split_kernel<<<128, 256>>>(dec1_w, w1_hi, w1_lo, 64 * 512);        // 1
    split_kernel<<<2048, 256>>>(dec2_w, w2_hi, w2_lo, 512 * 1024);     // 2
    conv_tc_kernel<<<BATCH, 512, CONV_SMEM>>>(data, conv1_w, conv1_b, prim_b);  // 3
    split_kernel<<<256, 256>>>(dec3_w, w3_hi, w3_lo, 1024 * 64);       // 4
    zero_kernel<<<4, 256>>>(p_bij, NR * 2);                            // 5

    for (int it = 0; it < 3; it++) {
        build_wct_kernel<<<1024, 256>>>(W_digit);   // inline softmax
        zero_kernel<<<1024, 256>>>(p_s, BATCH * 64);
        tgemm_pp_splitk<<<dim3(1, 64, 8), 256>>>(u_hi, u_lo, RI, wct_hi, wct_lo, 64,
                                                 p_s, 64, 512, 1.0f);
        squash_v_kernel<<<1024, 256>>>();
        if (it < 2) {
            zero_kernel<<<1024, 256>>>(p_GT, 64 * RI);
            tgemm_trv_splitk<<<dim3(64, 1, 8), 256>>>(p_v, u_hi, u_lo, RI,
                                                      p_GT, RI, 512, 1.0f / (float)BATCH);
            b_update_kernel<<<128, 256>>>(W_digit);
        }
    }

    mask_kernel<<<512, 256>>>(out);
    zero_kernel<<<1024, 256>>>(p_r, BATCH * 64);

    tgemm_pp_bias<<<dim3(8, 64), 256>>>(h0_hi, h0_lo, 64, w1_hi, w1_lo, 512,
                                        dec1_b, h1_hi, h1_lo, 512, 64);
    tgemm_pp_bias<<<dim3(16, 64), 256>>>(h1_hi, h1_lo, 512, w2_hi, w2_lo, 1024,
                                         dec2_b, h2_hi, h2_lo, 1024, 512);
    tgemm_pp_splitk<<<dim3(1, 64, 4), 256>>>(h2_hi, h2_lo, 1024, w3_hi, w3_lo, 64,
                                             p_r, 64, 256, 1.0f);
    sigmoid_bias_kernel<<<1024, 256>>>(dec3_b, out);
}